// round 7
// baseline (speedup 1.0000x reference)
#include <cuda_runtime.h>
#include <cuda_bf16.h>
#include <math.h>
#include <stdint.h>

#define NN   50000
#define FH   128

// ===================== scratch (static device globals) =====================
__device__ float g_agg[(size_t)4 * NN * FH];      // 102.4 MB
__device__ float g_deg[4 * NN];
__device__ float g_h1[(size_t)4 * NN * FH];       // 102.4 MB
__device__ float g_hstack[(size_t)4 * NN * FH];   // 102.4 MB
__device__ float g_emb[(size_t)NN * FH];          // 25.6 MB
__device__ __nv_bfloat16 g_whi[18 * 16384], g_wlo[18 * 16384];   // [mat][n][k]

__device__ __forceinline__ void bsplit(float v, __nv_bfloat16& h, __nv_bfloat16& l) {
    h = __float2bfloat16(v);
    l = __float2bfloat16(v - __bfloat162float(h));
}
__device__ __forceinline__ uint32_t pack_bf16(__nv_bfloat16 a, __nv_bfloat16 b) {
    return (uint32_t)__bfloat16_as_ushort(a) | ((uint32_t)__bfloat16_as_ushort(b) << 16);
}
__device__ __forceinline__ void red_add_v4(float* p, float a, float b, float c, float d) {
    asm volatile("red.global.add.v4.f32 [%0], {%1, %2, %3, %4};"
                 :: "l"(p), "f"(a), "f"(b), "f"(c), "f"(d) : "memory");
}
__device__ __forceinline__ void red_add_f32(float* p, float a) {
    asm volatile("red.global.add.f32 [%0], %1;" :: "l"(p), "f"(a) : "memory");
}
__device__ __forceinline__ uint32_t smem_u32(const void* p) {
    uint32_t a;
    asm("{ .reg .u64 t; cvta.to.shared.u64 t, %1; cvt.u32.u64 %0, t; }" : "=r"(a) : "l"(p));
    return a;
}
__device__ __forceinline__ uint32_t swz(uint32_t off) { return off ^ ((off >> 3) & 0x70); }

__device__ __forceinline__ void ldm_x4(uint32_t addr, uint32_t* r) {
    asm volatile("ldmatrix.sync.aligned.m8n8.x4.shared.b16 {%0,%1,%2,%3}, [%4];"
                 : "=r"(r[0]), "=r"(r[1]), "=r"(r[2]), "=r"(r[3]) : "r"(addr));
}
__device__ __forceinline__ void mma16816(float* c, const uint32_t* a, const uint32_t* b) {
    asm volatile("mma.sync.aligned.m16n8k16.row.col.f32.bf16.bf16.f32 "
        "{%0,%1,%2,%3}, {%4,%5,%6,%7}, {%8,%9}, {%0,%1,%2,%3};"
        : "+f"(c[0]), "+f"(c[1]), "+f"(c[2]), "+f"(c[3])
        : "r"(a[0]), "r"(a[1]), "r"(a[2]), "r"(a[3]), "r"(b[0]), "r"(b[1]));
}
__device__ __forceinline__ void cpasync16(uint32_t dst, const void* src) {
    asm volatile("cp.async.ca.shared.global [%0], [%1], 16;"
                 :: "r"(dst), "l"(__cvta_generic_to_global(src)) : "memory");
}
#define CP_COMMIT() asm volatile("cp.async.commit_group;" ::: "memory")
#define CP_WAIT0()  asm volatile("cp.async.wait_group 0;" ::: "memory")

// ===================== small kernels =====================
__global__ void split_weights_kernel(const float* __restrict__ Ws1, const float* __restrict__ Wn1,
                                     const float* __restrict__ Ws2, const float* __restrict__ Wn2,
                                     const float* __restrict__ L1) {
    int g = blockIdx.x * blockDim.x + threadIdx.x;
    if (g >= 18 * 16384) return;
    int m = g >> 14, r = g & 16383, n = r >> 7, k = r & 127;
    const float* s;
    if (m < 4)       s = Ws1 + (size_t)m * 16384;
    else if (m < 8)  s = Wn1 + (size_t)(m - 4) * 16384;
    else if (m < 12) s = Ws2 + (size_t)(m - 8) * 16384;
    else if (m < 16) s = Wn2 + (size_t)(m - 12) * 16384;
    else             s = L1  + (size_t)(m - 16) * 16384;
    float v = s[k * 128 + n];                 // transpose [k][n] -> [n][k]
    __nv_bfloat16 h, l; bsplit(v, h, l);
    g_whi[(size_t)m * 16384 + n * 128 + k] = h;
    g_wlo[(size_t)m * 16384 + n * 128 + k] = l;
}

struct EdgeArgs {
    const int* src[4]; const int* dst[4];
    const float* rows[4];
    int ne[4];
};

// batched scatter: agg[y][dst] += rows[src]; optional degree count; one warp per edge
__global__ void scatter_kernel(EdgeArgs a, int dodeg) {
    int y = blockIdx.y;
    int w = (blockIdx.x * blockDim.x + threadIdx.x) >> 5;
    if (w >= a.ne[y]) return;
    int lane = threadIdx.x & 31;
    int s = __ldg(a.src[y] + w), d = __ldg(a.dst[y] + w);
    float4 v = *(const float4*)(a.rows[y] + (size_t)s * FH + lane * 4);
    float* p = g_agg + ((size_t)y * NN + d) * FH + lane * 4;
    red_add_v4(p, v.x, v.y, v.z, v.w);
    if (dodeg && lane == 0) red_add_f32(&g_deg[y * NN + d], 1.0f);
}

// attention softmax over 4 metapaths -> f32 emb; one warp per node
__global__ void attention_kernel(const float* __restrict__ attW, const float* __restrict__ attB) {
    int n = (blockIdx.x * blockDim.x + threadIdx.x) >> 5;
    if (n >= NN) return;
    int lane = threadIdx.x & 31;
    float4 hv[4]; float logit[4];
#pragma unroll
    for (int k = 0; k < 4; ++k) {
        float4 h4 = *(const float4*)(g_hstack + ((size_t)k * NN + n) * FH + lane * 4);
        float4 w4 = *(const float4*)(attW + k * FH + lane * 4);
        hv[k] = h4;
        float p = h4.x * w4.x + h4.y * w4.y + h4.z * w4.z + h4.w * w4.w;
#pragma unroll
        for (int o = 16; o; o >>= 1) p += __shfl_xor_sync(0xffffffffu, p, o);
        logit[k] = p + attB[k];
    }
    float m = fmaxf(fmaxf(logit[0], logit[1]), fmaxf(logit[2], logit[3]));
    float e[4], s = 0.0f;
#pragma unroll
    for (int k = 0; k < 4; ++k) { e[k] = expf(logit[k] - m); s += e[k]; }
    float is = 1.0f / s;
    float4 o = make_float4(0.f, 0.f, 0.f, 0.f);
#pragma unroll
    for (int k = 0; k < 4; ++k) {
        float w = e[k] * is;
        o.x += w * hv[k].x; o.y += w * hv[k].y; o.z += w * hv[k].z; o.w += w * hv[k].w;
    }
    *(float4*)(g_emb + (size_t)n * FH + lane * 4) = o;
}

// ===================== serial-stage mma.sync GEMM =====================
// D[128 x 128] = sum over 2 halves of bf16-split A_half[rows,128](f32 src) @ W_half[n,k]^T
// 3-term split: Ahi*Whi + Ahi*Wlo + Alo*Whi, fp32 accum.
// Single smem stage (68KB) -> 2+ CTAs/SM; A staged via regs (short live range), W via cp.async.
// MODE 0: relu -> f32.  MODE 1: +bias -> f32.  MODE 2: relu + lin2 dot + sigmoid.
#define SB_BIAS 0
#define SB_L2W  512
#define SB_IDX  1024
#define SB_PART 2048
#define SB_TILES 4096
#define TILE_SZ 16384
#define SMEM_TOTAL (SB_TILES + 4 * TILE_SZ)
// tiles: 0=AHI 1=ALO 2=WHI 3=WLO

// load A chunk (128 rows x 64 f32 cols) into registers; 4 iters x 8 floats per thread
__device__ __forceinline__ void ldg_a(float* v, float* sc, const float* gbase,
                                      const int* sidx, const float* degbase,
                                      int row0, int nrows, int kofs, int tid) {
#pragma unroll
    for (int it = 0; it < 4; ++it) {
        int i = tid + it * 256;
        int r = i >> 3, j = i & 7;
        int grow = row0 + r;
        bool valid = grow < nrows;
        int row = sidx ? sidx[r] : grow;
        const float* p = gbase + (size_t)(valid ? row : 0) * FH + kofs + j * 8;
        float4 a = valid ? *(const float4*)p       : make_float4(0, 0, 0, 0);
        float4 b = valid ? *(const float4*)(p + 4) : make_float4(0, 0, 0, 0);
        v[it * 8 + 0] = a.x; v[it * 8 + 1] = a.y; v[it * 8 + 2] = a.z; v[it * 8 + 3] = a.w;
        v[it * 8 + 4] = b.x; v[it * 8 + 5] = b.y; v[it * 8 + 6] = b.z; v[it * 8 + 7] = b.w;
        sc[it] = degbase ? (1.0f / fmaxf(valid ? __ldg(degbase + grow) : 1.0f, 1.0f)) : 1.0f;
    }
}

// convert + store A regs -> AHI/ALO swizzled tiles
__device__ __forceinline__ void sts_a(const float* v, const float* sc,
                                      uint32_t ahi, uint32_t alo, int tid) {
#pragma unroll
    for (int it = 0; it < 4; ++it) {
        int i = tid + it * 256;
        int r = i >> 3, j = i & 7;
        float s = sc[it];
        uint32_t hp[4], lp[4];
#pragma unroll
        for (int q = 0; q < 4; ++q) {
            float v0 = v[it * 8 + 2 * q] * s, v1 = v[it * 8 + 2 * q + 1] * s;
            __nv_bfloat16 h0, l0, h1, l1;
            bsplit(v0, h0, l0); bsplit(v1, h1, l1);
            hp[q] = pack_bf16(h0, h1); lp[q] = pack_bf16(l0, l1);
        }
        uint32_t off = swz((uint32_t)(r * 128 + j * 16));
        asm volatile("st.shared.v4.b32 [%0], {%1,%2,%3,%4};"
                     :: "r"(ahi + off), "r"(hp[0]), "r"(hp[1]), "r"(hp[2]), "r"(hp[3]));
        asm volatile("st.shared.v4.b32 [%0], {%1,%2,%3,%4};"
                     :: "r"(alo + off), "r"(lp[0]), "r"(lp[1]), "r"(lp[2]), "r"(lp[3]));
    }
}

// async-stage W chunk (bf16 [n][k] source) into swizzled tile
__device__ __forceinline__ void stage_w(uint32_t wdst, const __nv_bfloat16* wsrc,
                                        int kofs, int tid) {
#pragma unroll
    for (int it = 0; it < 4; ++it) {
        int i = tid + it * 256;
        int r = i >> 3, j = i & 7;
        cpasync16(wdst + swz((uint32_t)(r * 128 + j * 16)), wsrc + r * 128 + kofs + j * 8);
    }
}

__device__ __forceinline__ void load_a_frag(uint32_t tb, int wm, int ks, int lane, uint32_t* ra) {
    int q = lane >> 3, r = lane & 7;
    int rofs = ((q & 1) ? 8 : 0) + r;
    int kl = ks * 16 + ((q & 2) ? 8 : 0);
#pragma unroll
    for (int mf = 0; mf < 4; ++mf) {
        uint32_t off = (uint32_t)((wm * 64 + mf * 16 + rofs) * 128 + kl * 2);
        ldm_x4(tb + swz(off), ra + mf * 4);
    }
}
__device__ __forceinline__ void load_w_frag(uint32_t tb, int wn, int ks, int lane, uint32_t* rw) {
    int q = lane >> 3, r = lane & 7;
    int rofs = ((q & 2) ? 8 : 0) + r;
    int kl = ks * 16 + ((q & 1) ? 8 : 0);
#pragma unroll
    for (int pf = 0; pf < 2; ++pf) {
        uint32_t off = (uint32_t)((wn * 32 + pf * 16 + rofs) * 128 + kl * 2);
        ldm_x4(tb + swz(off), rw + pf * 4);
    }
}

template <int MODE>
__global__ void __launch_bounds__(256) mp_gemm_kernel(
    const float* __restrict__ a0base, size_t a0stride,
    const float* __restrict__ a1base, size_t a1stride, int a1deg,
    const int* __restrict__ idx0, const int* __restrict__ idx1,
    int w0mat, int w1mat, int wmatstride,
    const float* __restrict__ bias, int bstride,
    const float* __restrict__ l2w, const float* __restrict__ l2b,
    float* __restrict__ outf, size_t outfstride,
    int nrows)
{
    extern __shared__ char smem[];
    const uint32_t sb = smem_u32(smem);
    const int tid = threadIdx.x, lane = tid & 31, wid = tid >> 5;
    const int wm = wid & 1, wn = wid >> 1;
    const int y = blockIdx.y;
    const int row0 = blockIdx.x * 128;

    float* sbias = (float*)(smem + SB_BIAS);
    float* sl2w  = (float*)(smem + SB_L2W);
    int*   sidx  = (int*)(smem + SB_IDX);       // [2][128]
    float* spart = (float*)(smem + SB_PART);
    if (tid < 128) {
        sbias[tid] = bias[bstride * y + tid];
        if (MODE == 2) {
            sl2w[tid] = l2w[tid];
            int e = row0 + tid;
            sidx[tid]       = (e < nrows) ? __ldg(idx0 + e) : 0;
            sidx[128 + tid] = (e < nrows) ? __ldg(idx1 + e) : 0;
        }
    }
    __syncthreads();

    const float* ab[2] = { a0base + (size_t)y * a0stride, a1base + (size_t)y * a1stride };
    const int* sidxh[2] = { (MODE == 2) ? sidx : nullptr, (MODE == 2) ? sidx + 128 : nullptr };
    const float* degh[2] = { nullptr, a1deg ? (g_deg + y * NN) : nullptr };
    const __nv_bfloat16* whb[2] = { g_whi + (size_t)(w0mat + y * wmatstride) * 16384,
                                    g_whi + (size_t)(w1mat + y * wmatstride) * 16384 };
    const __nv_bfloat16* wlb[2] = { g_wlo + (size_t)(w0mat + y * wmatstride) * 16384,
                                    g_wlo + (size_t)(w1mat + y * wmatstride) * 16384 };

    const uint32_t tAHI = sb + SB_TILES,               tALO = sb + SB_TILES + TILE_SZ;
    const uint32_t tWHI = sb + SB_TILES + 2 * TILE_SZ, tWLO = sb + SB_TILES + 3 * TILE_SZ;

    float acc[4][4][4];
#pragma unroll
    for (int i = 0; i < 4; ++i)
#pragma unroll
        for (int j = 0; j < 4; ++j)
#pragma unroll
            for (int q = 0; q < 4; ++q) acc[i][j][q] = 0.0f;

#pragma unroll 1
    for (int c = 0; c < 4; ++c) {
        const int half = c >> 1, kc = (c & 1) * 64;
        if (c) __syncthreads();   // previous chunk's MMA reads done -> smem reusable
        {
            float av[32], asc[4];
            ldg_a(av, asc, ab[half], sidxh[half], degh[half], row0, nrows, kc, tid);
            stage_w(tWHI, whb[half], kc, tid);
            stage_w(tWLO, wlb[half], kc, tid);
            CP_COMMIT();
            sts_a(av, asc, tAHI, tALO, tid);
        }
        CP_WAIT0();
        __syncthreads();

#pragma unroll
        for (int ks = 0; ks < 4; ++ks) {
            uint32_t ra[16], rwh[8], rwl[8];
            load_a_frag(tAHI, wm, ks, lane, ra);
            load_w_frag(tWHI, wn, ks, lane, rwh);
#pragma unroll
            for (int mf = 0; mf < 4; ++mf)
#pragma unroll
                for (int nf = 0; nf < 4; ++nf)
                    mma16816(acc[mf][nf], ra + mf * 4, rwh + nf * 2);
            load_w_frag(tWLO, wn, ks, lane, rwl);
#pragma unroll
            for (int mf = 0; mf < 4; ++mf)
#pragma unroll
                for (int nf = 0; nf < 4; ++nf)
                    mma16816(acc[mf][nf], ra + mf * 4, rwl + nf * 2);
            load_a_frag(tALO, wm, ks, lane, ra);
#pragma unroll
            for (int mf = 0; mf < 4; ++mf)
#pragma unroll
                for (int nf = 0; nf < 4; ++nf)
                    mma16816(acc[mf][nf], ra + mf * 4, rwh + nf * 2);
        }
    }

    // ---------------- epilogue ----------------
    // rows = row0 + wm*64 + mf*16 + (lane>>2) [+8]; cols = wn*32 + nf*8 + 2*(lane&3) [+1]
    const int rbase = row0 + wm * 64 + (lane >> 2);
    const int cbase = wn * 32 + 2 * (lane & 3);

    if (MODE == 2) {
        float pr[4][2];
#pragma unroll
        for (int mf = 0; mf < 4; ++mf) { pr[mf][0] = 0.f; pr[mf][1] = 0.f; }
#pragma unroll
        for (int mf = 0; mf < 4; ++mf)
#pragma unroll
            for (int nf = 0; nf < 4; ++nf) {
                int gc = cbase + nf * 8;
                float w0 = sl2w[gc], w1 = sl2w[gc + 1];
                float b0v = sbias[gc], b1v = sbias[gc + 1];
                pr[mf][0] += fmaxf(acc[mf][nf][0] + b0v, 0.f) * w0
                           + fmaxf(acc[mf][nf][1] + b1v, 0.f) * w1;
                pr[mf][1] += fmaxf(acc[mf][nf][2] + b0v, 0.f) * w0
                           + fmaxf(acc[mf][nf][3] + b1v, 0.f) * w1;
            }
#pragma unroll
        for (int mf = 0; mf < 4; ++mf)
#pragma unroll
            for (int hh = 0; hh < 2; ++hh) {
                float p = pr[mf][hh];
                p += __shfl_xor_sync(0xffffffffu, p, 1);
                p += __shfl_xor_sync(0xffffffffu, p, 2);
                if ((lane & 3) == 0)
                    spart[(wm * 64 + mf * 16 + (lane >> 2) + hh * 8) * 4 + wn] = p;
            }
        __syncthreads();
        if (tid < 128) {
            int r = row0 + tid;
            if (r < nrows) {
                float s = spart[tid * 4] + spart[tid * 4 + 1] + spart[tid * 4 + 2] + spart[tid * 4 + 3];
                outf[r] = 1.0f / (1.0f + expf(-(s + l2b[0])));
            }
        }
        return;
    }

#pragma unroll
    for (int mf = 0; mf < 4; ++mf) {
        int r0 = rbase + mf * 16, r1 = r0 + 8;
        bool v0 = r0 < nrows, v1 = r1 < nrows;
#pragma unroll
        for (int nf = 0; nf < 4; ++nf) {
            int gc = cbase + nf * 8;
            float b0v = sbias[gc], b1v = sbias[gc + 1];
            float e0 = acc[mf][nf][0] + b0v, e1 = acc[mf][nf][1] + b1v;
            float e2 = acc[mf][nf][2] + b0v, e3 = acc[mf][nf][3] + b1v;
            if (MODE == 0) {
                e0 = fmaxf(e0, 0.f); e1 = fmaxf(e1, 0.f);
                e2 = fmaxf(e2, 0.f); e3 = fmaxf(e3, 0.f);
            }
            if (v0) *(float2*)(outf + (size_t)y * outfstride + (size_t)r0 * FH + gc) = make_float2(e0, e1);
            if (v1) *(float2*)(outf + (size_t)y * outfstride + (size_t)r1 * FH + gc) = make_float2(e2, e3);
        }
    }
}

// ===================== host =====================
extern "C" void kernel_launch(void* const* d_in, const int* in_sizes, int n_in,
                              void* d_out, int out_size) {
    const float* x    = (const float*)d_in[0];
    const float* Ws1  = (const float*)d_in[1];
    const float* b1   = (const float*)d_in[2];
    const float* Wn1  = (const float*)d_in[3];
    const float* Ws2  = (const float*)d_in[4];
    const float* b2   = (const float*)d_in[5];
    const float* Wn2  = (const float*)d_in[6];
    const float* attW = (const float*)d_in[7];
    const float* attB = (const float*)d_in[8];
    const float* l1W  = (const float*)d_in[9];
    const float* l1b  = (const float*)d_in[10];
    const float* l2W  = (const float*)d_in[11];
    const float* l2b  = (const float*)d_in[12];
    const int* srcs[4] = {(const int*)d_in[13], (const int*)d_in[15],
                          (const int*)d_in[17], (const int*)d_in[19]};
    const int* dsts[4] = {(const int*)d_in[14], (const int*)d_in[16],
                          (const int*)d_in[18], (const int*)d_in[20]};
    const int* ssim = (const int*)d_in[21];
    const int* dsim = (const int*)d_in[22];
    const int  esim = in_sizes[21];

    void *aggP, *degP, *h1P, *hsP, *embP;
    cudaGetSymbolAddress(&aggP, g_agg);
    cudaGetSymbolAddress(&degP, g_deg);
    cudaGetSymbolAddress(&h1P, g_h1);
    cudaGetSymbolAddress(&hsP, g_hstack);
    cudaGetSymbolAddress(&embP, g_emb);

    cudaFuncSetAttribute(mp_gemm_kernel<0>, cudaFuncAttributeMaxDynamicSharedMemorySize, SMEM_TOTAL);
    cudaFuncSetAttribute(mp_gemm_kernel<1>, cudaFuncAttributeMaxDynamicSharedMemorySize, SMEM_TOTAL);
    cudaFuncSetAttribute(mp_gemm_kernel<2>, cudaFuncAttributeMaxDynamicSharedMemorySize, SMEM_TOTAL);

    EdgeArgs ea;
    int max_ne = 0;
    for (int k = 0; k < 4; ++k) {
        ea.src[k] = srcs[k]; ea.dst[k] = dsts[k];
        ea.ne[k] = in_sizes[13 + 2 * k];
        if (ea.ne[k] > max_ne) max_ne = ea.ne[k];
    }

    const int NB = (NN + 127) / 128;
    const size_t NF = (size_t)NN * FH;

    // 0. weight split
    split_weights_kernel<<<(18 * 16384 + 255) / 256, 256>>>(Ws1, Wn1, Ws2, Wn2, l1W);

    // 1. layer-1 aggregation + fused degree count
    cudaMemsetAsync(degP, 0, 4 * NN * sizeof(float));
    cudaMemsetAsync(aggP, 0, 4 * NF * sizeof(float));
    for (int k = 0; k < 4; ++k) ea.rows[k] = x;
    scatter_kernel<<<dim3((max_ne + 7) / 8, 4), 256>>>(ea, 1);

    // 2. layer-1 GEMM: h1 = relu(x@Ws1 + (agg*invdeg)@Wn1 + b1) -> f32
    mp_gemm_kernel<0><<<dim3(NB, 4), 256, SMEM_TOTAL>>>(
        x, 0, (const float*)aggP, NF, 1, nullptr, nullptr,
        0, 4, 1, b1, FH, nullptr, nullptr,
        (float*)h1P, NF, NN);

    // 3. layer-2 aggregation
    cudaMemsetAsync(aggP, 0, 4 * NF * sizeof(float));
    for (int k = 0; k < 4; ++k) ea.rows[k] = (const float*)h1P + (size_t)k * NF;
    scatter_kernel<<<dim3((max_ne + 7) / 8, 4), 256>>>(ea, 0);

    // 4. layer-2 GEMM -> f32 hstack
    mp_gemm_kernel<1><<<dim3(NB, 4), 256, SMEM_TOTAL>>>(
        (const float*)h1P, NF, (const float*)aggP, NF, 1, nullptr, nullptr,
        8, 12, 1, b2, FH, nullptr, nullptr,
        (float*)hsP, NF, NN);

    // 5. attention -> f32 emb
    attention_kernel<<<(NN * 32 + 255) / 256, 256>>>(attW, attB);

    // 6. fused edge scorer: gather-GEMM + relu + lin2 dot + sigmoid
    mp_gemm_kernel<2><<<dim3((esim + 127) / 128, 1), 256, SMEM_TOTAL>>>(
        (const float*)embP, 0, (const float*)embP, 0, 0, ssim, dsim,
        16, 17, 0, l1b, 0, l2W, l2b,
        (float*)d_out, 0, esim);
}

// round 8
// speedup vs baseline: 1.0646x; 1.0646x over previous
#include <cuda_runtime.h>
#include <cuda_bf16.h>
#include <math.h>
#include <stdint.h>

#define NN   50000
#define FH   128

// ===================== scratch (static device globals) =====================
__device__ float g_agg[(size_t)4 * NN * FH];      // 102.4 MB
__device__ float g_deg[4 * NN];
__device__ float g_h1[(size_t)4 * NN * FH];       // 102.4 MB
__device__ float g_hstack[(size_t)4 * NN * FH];   // 102.4 MB
__device__ float g_emb[(size_t)NN * FH];          // 25.6 MB
__device__ __nv_bfloat16 g_whi[18 * 16384], g_wlo[18 * 16384];   // [mat][n][k]

__device__ __forceinline__ void bsplit(float v, __nv_bfloat16& h, __nv_bfloat16& l) {
    h = __float2bfloat16(v);
    l = __float2bfloat16(v - __bfloat162float(h));
}
__device__ __forceinline__ uint32_t pack_bf16(__nv_bfloat16 a, __nv_bfloat16 b) {
    return (uint32_t)__bfloat16_as_ushort(a) | ((uint32_t)__bfloat16_as_ushort(b) << 16);
}
__device__ __forceinline__ void red_add_v4(float* p, float a, float b, float c, float d) {
    asm volatile("red.global.add.v4.f32 [%0], {%1, %2, %3, %4};"
                 :: "l"(p), "f"(a), "f"(b), "f"(c), "f"(d) : "memory");
}
__device__ __forceinline__ void red_add_f32(float* p, float a) {
    asm volatile("red.global.add.f32 [%0], %1;" :: "l"(p), "f"(a) : "memory");
}
__device__ __forceinline__ uint32_t smem_u32(const void* p) {
    uint32_t a;
    asm("{ .reg .u64 t; cvta.to.shared.u64 t, %1; cvt.u32.u64 %0, t; }" : "=r"(a) : "l"(p));
    return a;
}
__device__ __forceinline__ uint32_t swz(uint32_t off) { return off ^ ((off >> 3) & 0x70); }

__device__ __forceinline__ void ldm_x4(uint32_t addr, uint32_t* r) {
    asm volatile("ldmatrix.sync.aligned.m8n8.x4.shared.b16 {%0,%1,%2,%3}, [%4];"
                 : "=r"(r[0]), "=r"(r[1]), "=r"(r[2]), "=r"(r[3]) : "r"(addr));
}
__device__ __forceinline__ void mma16816(float* c, const uint32_t* a, const uint32_t* b) {
    asm volatile("mma.sync.aligned.m16n8k16.row.col.f32.bf16.bf16.f32 "
        "{%0,%1,%2,%3}, {%4,%5,%6,%7}, {%8,%9}, {%0,%1,%2,%3};"
        : "+f"(c[0]), "+f"(c[1]), "+f"(c[2]), "+f"(c[3])
        : "r"(a[0]), "r"(a[1]), "r"(a[2]), "r"(a[3]), "r"(b[0]), "r"(b[1]));
}
__device__ __forceinline__ void cpasync16(uint32_t dst, const void* src) {
    asm volatile("cp.async.ca.shared.global [%0], [%1], 16;"
                 :: "r"(dst), "l"(__cvta_generic_to_global(src)) : "memory");
}
#define CP_COMMIT() asm volatile("cp.async.commit_group;" ::: "memory")
#define CP_WAIT0()  asm volatile("cp.async.wait_group 0;" ::: "memory")

// ===================== small kernels =====================
__global__ void split_weights_kernel(const float* __restrict__ Ws1, const float* __restrict__ Wn1,
                                     const float* __restrict__ Ws2, const float* __restrict__ Wn2,
                                     const float* __restrict__ L1) {
    int g = blockIdx.x * blockDim.x + threadIdx.x;
    if (g >= 18 * 16384) return;
    int m = g >> 14, r = g & 16383, n = r >> 7, k = r & 127;
    const float* s;
    if (m < 4)       s = Ws1 + (size_t)m * 16384;
    else if (m < 8)  s = Wn1 + (size_t)(m - 4) * 16384;
    else if (m < 12) s = Ws2 + (size_t)(m - 8) * 16384;
    else if (m < 16) s = Wn2 + (size_t)(m - 12) * 16384;
    else             s = L1  + (size_t)(m - 16) * 16384;
    float v = s[k * 128 + n];                 // transpose [k][n] -> [n][k]
    __nv_bfloat16 h, l; bsplit(v, h, l);
    g_whi[(size_t)m * 16384 + n * 128 + k] = h;
    g_wlo[(size_t)m * 16384 + n * 128 + k] = l;
}

struct EdgeArgs {
    const int* src[4]; const int* dst[4];
    const float* rows[4];
    int ne[4];
};

// batched scatter: agg[y][dst] += rows[src]; optional degree count; one warp per edge
__global__ void scatter_kernel(EdgeArgs a, int dodeg) {
    int y = blockIdx.y;
    int w = (blockIdx.x * blockDim.x + threadIdx.x) >> 5;
    if (w >= a.ne[y]) return;
    int lane = threadIdx.x & 31;
    int s = __ldg(a.src[y] + w), d = __ldg(a.dst[y] + w);
    float4 v = *(const float4*)(a.rows[y] + (size_t)s * FH + lane * 4);
    float* p = g_agg + ((size_t)y * NN + d) * FH + lane * 4;
    red_add_v4(p, v.x, v.y, v.z, v.w);
    if (dodeg && lane == 0) red_add_f32(&g_deg[y * NN + d], 1.0f);
}

// attention softmax over 4 metapaths -> f32 emb; one warp per node
__global__ void attention_kernel(const float* __restrict__ attW, const float* __restrict__ attB) {
    int n = (blockIdx.x * blockDim.x + threadIdx.x) >> 5;
    if (n >= NN) return;
    int lane = threadIdx.x & 31;
    float4 hv[4]; float logit[4];
#pragma unroll
    for (int k = 0; k < 4; ++k) {
        float4 h4 = *(const float4*)(g_hstack + ((size_t)k * NN + n) * FH + lane * 4);
        float4 w4 = *(const float4*)(attW + k * FH + lane * 4);
        hv[k] = h4;
        float p = h4.x * w4.x + h4.y * w4.y + h4.z * w4.z + h4.w * w4.w;
#pragma unroll
        for (int o = 16; o; o >>= 1) p += __shfl_xor_sync(0xffffffffu, p, o);
        logit[k] = p + attB[k];
    }
    float m = fmaxf(fmaxf(logit[0], logit[1]), fmaxf(logit[2], logit[3]));
    float e[4], s = 0.0f;
#pragma unroll
    for (int k = 0; k < 4; ++k) { e[k] = expf(logit[k] - m); s += e[k]; }
    float is = 1.0f / s;
    float4 o = make_float4(0.f, 0.f, 0.f, 0.f);
#pragma unroll
    for (int k = 0; k < 4; ++k) {
        float w = e[k] * is;
        o.x += w * hv[k].x; o.y += w * hv[k].y; o.z += w * hv[k].z; o.w += w * hv[k].w;
    }
    *(float4*)(g_emb + (size_t)n * FH + lane * 4) = o;
}

// ===================== serial-stage mma.sync GEMM (2 CTAs/SM) =====================
// D[128 x 128] = sum over 2 halves of bf16-split A_half[rows,128](f32 src) @ W_half[n,k]^T
// 3-term split: Ahi*Whi + Ahi*Wlo + Alo*Whi, fp32 accum.
// Single smem stage (68KB); A staged per-iteration load->convert->store (short reg live range);
// W via cp.async. __launch_bounds__(256,2) pins 2 CTAs/SM.
// MODE 0: relu -> f32.  MODE 1: +bias -> f32.  MODE 2: relu + lin2 dot + sigmoid.
#define SB_BIAS 0
#define SB_L2W  512
#define SB_IDX  1024
#define SB_PART 2048
#define SB_TILES 4096
#define TILE_SZ 16384
#define SMEM_TOTAL (SB_TILES + 4 * TILE_SZ)

// stage A chunk (128 rows x 64 f32 cols) -> AHI/ALO swizzled bf16 tiles, per-iteration
__device__ __forceinline__ void stage_a(uint32_t ahi, uint32_t alo, const float* gbase,
                                        const int* sidx, const float* degbase,
                                        int row0, int nrows, int kofs, int tid) {
#pragma unroll
    for (int it = 0; it < 4; ++it) {
        int i = tid + it * 256;
        int r = i >> 3, j = i & 7;
        int grow = row0 + r;
        bool valid = grow < nrows;
        int row = sidx ? sidx[r] : grow;
        const float* p = gbase + (size_t)(valid ? row : 0) * FH + kofs + j * 8;
        float4 a = valid ? *(const float4*)p       : make_float4(0, 0, 0, 0);
        float4 b = valid ? *(const float4*)(p + 4) : make_float4(0, 0, 0, 0);
        float s = 1.0f;
        if (degbase) s = valid ? (1.0f / fmaxf(__ldg(degbase + grow), 1.0f)) : 1.0f;
        float vv[8] = { a.x * s, a.y * s, a.z * s, a.w * s,
                        b.x * s, b.y * s, b.z * s, b.w * s };
        uint32_t hp[4], lp[4];
#pragma unroll
        for (int q = 0; q < 4; ++q) {
            __nv_bfloat16 h0, l0, h1, l1;
            bsplit(vv[2 * q], h0, l0); bsplit(vv[2 * q + 1], h1, l1);
            hp[q] = pack_bf16(h0, h1); lp[q] = pack_bf16(l0, l1);
        }
        uint32_t off = swz((uint32_t)(r * 128 + j * 16));
        asm volatile("st.shared.v4.b32 [%0], {%1,%2,%3,%4};"
                     :: "r"(ahi + off), "r"(hp[0]), "r"(hp[1]), "r"(hp[2]), "r"(hp[3]));
        asm volatile("st.shared.v4.b32 [%0], {%1,%2,%3,%4};"
                     :: "r"(alo + off), "r"(lp[0]), "r"(lp[1]), "r"(lp[2]), "r"(lp[3]));
    }
}

// async-stage W chunk (bf16 [n][k] source) into swizzled tile
__device__ __forceinline__ void stage_w(uint32_t wdst, const __nv_bfloat16* wsrc,
                                        int kofs, int tid) {
#pragma unroll
    for (int it = 0; it < 4; ++it) {
        int i = tid + it * 256;
        int r = i >> 3, j = i & 7;
        cpasync16(wdst + swz((uint32_t)(r * 128 + j * 16)), wsrc + r * 128 + kofs + j * 8);
    }
}

__device__ __forceinline__ void load_a_frag(uint32_t tb, int wm, int ks, int lane, uint32_t* ra) {
    int q = lane >> 3, r = lane & 7;
    int rofs = ((q & 1) ? 8 : 0) + r;
    int kl = ks * 16 + ((q & 2) ? 8 : 0);
#pragma unroll
    for (int mf = 0; mf < 4; ++mf) {
        uint32_t off = (uint32_t)((wm * 64 + mf * 16 + rofs) * 128 + kl * 2);
        ldm_x4(tb + swz(off), ra + mf * 4);
    }
}
__device__ __forceinline__ void load_w_frag(uint32_t tb, int wn, int ks, int lane, uint32_t* rw) {
    int q = lane >> 3, r = lane & 7;
    int rofs = ((q & 2) ? 8 : 0) + r;
    int kl = ks * 16 + ((q & 1) ? 8 : 0);
#pragma unroll
    for (int pf = 0; pf < 2; ++pf) {
        uint32_t off = (uint32_t)((wn * 32 + pf * 16 + rofs) * 128 + kl * 2);
        ldm_x4(tb + swz(off), rw + pf * 4);
    }
}

template <int MODE>
__global__ void __launch_bounds__(256, 2) mp_gemm_kernel(
    const float* __restrict__ a0base, size_t a0stride,
    const float* __restrict__ a1base, size_t a1stride, int a1deg,
    const int* __restrict__ idx0, const int* __restrict__ idx1,
    int w0mat, int w1mat, int wmatstride,
    const float* __restrict__ bias, int bstride,
    const float* __restrict__ l2w, const float* __restrict__ l2b,
    float* __restrict__ outf, size_t outfstride,
    int nrows)
{
    extern __shared__ char smem[];
    const uint32_t sb = smem_u32(smem);
    const int tid = threadIdx.x, lane = tid & 31, wid = tid >> 5;
    const int wm = wid & 1, wn = wid >> 1;
    const int y = blockIdx.y;
    const int row0 = blockIdx.x * 128;

    float* sbias = (float*)(smem + SB_BIAS);
    float* sl2w  = (float*)(smem + SB_L2W);
    int*   sidx  = (int*)(smem + SB_IDX);       // [2][128]
    float* spart = (float*)(smem + SB_PART);
    if (tid < 128) {
        sbias[tid] = bias[bstride * y + tid];
        if (MODE == 2) {
            sl2w[tid] = l2w[tid];
            int e = row0 + tid;
            sidx[tid]       = (e < nrows) ? __ldg(idx0 + e) : 0;
            sidx[128 + tid] = (e < nrows) ? __ldg(idx1 + e) : 0;
        }
    }
    __syncthreads();

    const float* ab[2] = { a0base + (size_t)y * a0stride, a1base + (size_t)y * a1stride };
    const int* sidxh[2] = { (MODE == 2) ? sidx : nullptr, (MODE == 2) ? sidx + 128 : nullptr };
    const float* degh[2] = { nullptr, a1deg ? (g_deg + y * NN) : nullptr };
    const __nv_bfloat16* whb[2] = { g_whi + (size_t)(w0mat + y * wmatstride) * 16384,
                                    g_whi + (size_t)(w1mat + y * wmatstride) * 16384 };
    const __nv_bfloat16* wlb[2] = { g_wlo + (size_t)(w0mat + y * wmatstride) * 16384,
                                    g_wlo + (size_t)(w1mat + y * wmatstride) * 16384 };

    const uint32_t tAHI = sb + SB_TILES,               tALO = sb + SB_TILES + TILE_SZ;
    const uint32_t tWHI = sb + SB_TILES + 2 * TILE_SZ, tWLO = sb + SB_TILES + 3 * TILE_SZ;

    float acc[4][4][4];
#pragma unroll
    for (int i = 0; i < 4; ++i)
#pragma unroll
        for (int j = 0; j < 4; ++j)
#pragma unroll
            for (int q = 0; q < 4; ++q) acc[i][j][q] = 0.0f;

#pragma unroll 1
    for (int c = 0; c < 4; ++c) {
        const int half = c >> 1, kc = (c & 1) * 64;
        if (c) __syncthreads();   // previous chunk's MMA reads done -> smem reusable
        stage_w(tWHI, whb[half], kc, tid);
        stage_w(tWLO, wlb[half], kc, tid);
        CP_COMMIT();
        stage_a(tAHI, tALO, ab[half], sidxh[half], degh[half], row0, nrows, kc, tid);
        CP_WAIT0();
        __syncthreads();

#pragma unroll
        for (int ks = 0; ks < 4; ++ks) {
            uint32_t ra[16], rwh[8], rwl[8];
            load_a_frag(tAHI, wm, ks, lane, ra);
            load_w_frag(tWHI, wn, ks, lane, rwh);
#pragma unroll
            for (int mf = 0; mf < 4; ++mf)
#pragma unroll
                for (int nf = 0; nf < 4; ++nf)
                    mma16816(acc[mf][nf], ra + mf * 4, rwh + nf * 2);
            load_w_frag(tWLO, wn, ks, lane, rwl);
#pragma unroll
            for (int mf = 0; mf < 4; ++mf)
#pragma unroll
                for (int nf = 0; nf < 4; ++nf)
                    mma16816(acc[mf][nf], ra + mf * 4, rwl + nf * 2);
            load_a_frag(tALO, wm, ks, lane, ra);
#pragma unroll
            for (int mf = 0; mf < 4; ++mf)
#pragma unroll
                for (int nf = 0; nf < 4; ++nf)
                    mma16816(acc[mf][nf], ra + mf * 4, rwh + nf * 2);
        }
    }

    // ---------------- epilogue ----------------
    // rows = row0 + wm*64 + mf*16 + (lane>>2) [+8]; cols = wn*32 + nf*8 + 2*(lane&3) [+1]
    const int rbase = row0 + wm * 64 + (lane >> 2);
    const int cbase = wn * 32 + 2 * (lane & 3);

    if (MODE == 2) {
        float pr[4][2];
#pragma unroll
        for (int mf = 0; mf < 4; ++mf) { pr[mf][0] = 0.f; pr[mf][1] = 0.f; }
#pragma unroll
        for (int mf = 0; mf < 4; ++mf)
#pragma unroll
            for (int nf = 0; nf < 4; ++nf) {
                int gc = cbase + nf * 8;
                float w0 = sl2w[gc], w1 = sl2w[gc + 1];
                float b0v = sbias[gc], b1v = sbias[gc + 1];
                pr[mf][0] += fmaxf(acc[mf][nf][0] + b0v, 0.f) * w0
                           + fmaxf(acc[mf][nf][1] + b1v, 0.f) * w1;
                pr[mf][1] += fmaxf(acc[mf][nf][2] + b0v, 0.f) * w0
                           + fmaxf(acc[mf][nf][3] + b1v, 0.f) * w1;
            }
#pragma unroll
        for (int mf = 0; mf < 4; ++mf)
#pragma unroll
            for (int hh = 0; hh < 2; ++hh) {
                float p = pr[mf][hh];
                p += __shfl_xor_sync(0xffffffffu, p, 1);
                p += __shfl_xor_sync(0xffffffffu, p, 2);
                if ((lane & 3) == 0)
                    spart[(wm * 64 + mf * 16 + (lane >> 2) + hh * 8) * 4 + wn] = p;
            }
        __syncthreads();
        if (tid < 128) {
            int r = row0 + tid;
            if (r < nrows) {
                float s = spart[tid * 4] + spart[tid * 4 + 1] + spart[tid * 4 + 2] + spart[tid * 4 + 3];
                outf[r] = 1.0f / (1.0f + expf(-(s + l2b[0])));
            }
        }
        return;
    }

#pragma unroll
    for (int mf = 0; mf < 4; ++mf) {
        int r0 = rbase + mf * 16, r1 = r0 + 8;
        bool v0 = r0 < nrows, v1 = r1 < nrows;
#pragma unroll
        for (int nf = 0; nf < 4; ++nf) {
            int gc = cbase + nf * 8;
            float b0v = sbias[gc], b1v = sbias[gc + 1];
            float e0 = acc[mf][nf][0] + b0v, e1 = acc[mf][nf][1] + b1v;
            float e2 = acc[mf][nf][2] + b0v, e3 = acc[mf][nf][3] + b1v;
            if (MODE == 0) {
                e0 = fmaxf(e0, 0.f); e1 = fmaxf(e1, 0.f);
                e2 = fmaxf(e2, 0.f); e3 = fmaxf(e3, 0.f);
            }
            if (v0) *(float2*)(outf + (size_t)y * outfstride + (size_t)r0 * FH + gc) = make_float2(e0, e1);
            if (v1) *(float2*)(outf + (size_t)y * outfstride + (size_t)r1 * FH + gc) = make_float2(e2, e3);
        }
    }
}

// ===================== host =====================
extern "C" void kernel_launch(void* const* d_in, const int* in_sizes, int n_in,
                              void* d_out, int out_size) {
    const float* x    = (const float*)d_in[0];
    const float* Ws1  = (const float*)d_in[1];
    const float* b1   = (const float*)d_in[2];
    const float* Wn1  = (const float*)d_in[3];
    const float* Ws2  = (const float*)d_in[4];
    const float* b2   = (const float*)d_in[5];
    const float* Wn2  = (const float*)d_in[6];
    const float* attW = (const float*)d_in[7];
    const float* attB = (const float*)d_in[8];
    const float* l1W  = (const float*)d_in[9];
    const float* l1b  = (const float*)d_in[10];
    const float* l2W  = (const float*)d_in[11];
    const float* l2b  = (const float*)d_in[12];
    const int* srcs[4] = {(const int*)d_in[13], (const int*)d_in[15],
                          (const int*)d_in[17], (const int*)d_in[19]};
    const int* dsts[4] = {(const int*)d_in[14], (const int*)d_in[16],
                          (const int*)d_in[18], (const int*)d_in[20]};
    const int* ssim = (const int*)d_in[21];
    const int* dsim = (const int*)d_in[22];
    const int  esim = in_sizes[21];

    void *aggP, *degP, *h1P, *hsP, *embP;
    cudaGetSymbolAddress(&aggP, g_agg);
    cudaGetSymbolAddress(&degP, g_deg);
    cudaGetSymbolAddress(&h1P, g_h1);
    cudaGetSymbolAddress(&hsP, g_hstack);
    cudaGetSymbolAddress(&embP, g_emb);

    cudaFuncSetAttribute(mp_gemm_kernel<0>, cudaFuncAttributeMaxDynamicSharedMemorySize, SMEM_TOTAL);
    cudaFuncSetAttribute(mp_gemm_kernel<1>, cudaFuncAttributeMaxDynamicSharedMemorySize, SMEM_TOTAL);
    cudaFuncSetAttribute(mp_gemm_kernel<2>, cudaFuncAttributeMaxDynamicSharedMemorySize, SMEM_TOTAL);

    EdgeArgs ea;
    int max_ne = 0;
    for (int k = 0; k < 4; ++k) {
        ea.src[k] = srcs[k]; ea.dst[k] = dsts[k];
        ea.ne[k] = in_sizes[13 + 2 * k];
        if (ea.ne[k] > max_ne) max_ne = ea.ne[k];
    }

    const int NB = (NN + 127) / 128;
    const size_t NF = (size_t)NN * FH;

    // 0. weight split
    split_weights_kernel<<<(18 * 16384 + 255) / 256, 256>>>(Ws1, Wn1, Ws2, Wn2, l1W);

    // 1. layer-1 aggregation + fused degree count
    cudaMemsetAsync(degP, 0, 4 * NN * sizeof(float));
    cudaMemsetAsync(aggP, 0, 4 * NF * sizeof(float));
    for (int k = 0; k < 4; ++k) ea.rows[k] = x;
    scatter_kernel<<<dim3((max_ne + 7) / 8, 4), 256>>>(ea, 1);

    // 2. layer-1 GEMM: h1 = relu(x@Ws1 + (agg*invdeg)@Wn1 + b1) -> f32
    mp_gemm_kernel<0><<<dim3(NB, 4), 256, SMEM_TOTAL>>>(
        x, 0, (const float*)aggP, NF, 1, nullptr, nullptr,
        0, 4, 1, b1, FH, nullptr, nullptr,
        (float*)h1P, NF, NN);

    // 3. layer-2 aggregation
    cudaMemsetAsync(aggP, 0, 4 * NF * sizeof(float));
    for (int k = 0; k < 4; ++k) ea.rows[k] = (const float*)h1P + (size_t)k * NF;
    scatter_kernel<<<dim3((max_ne + 7) / 8, 4), 256>>>(ea, 0);

    // 4. layer-2 GEMM -> f32 hstack
    mp_gemm_kernel<1><<<dim3(NB, 4), 256, SMEM_TOTAL>>>(
        (const float*)h1P, NF, (const float*)aggP, NF, 1, nullptr, nullptr,
        8, 12, 1, b2, FH, nullptr, nullptr,
        (float*)hsP, NF, NN);

    // 5. attention -> f32 emb
    attention_kernel<<<(NN * 32 + 255) / 256, 256>>>(attW, attB);

    // 6. fused edge scorer: gather-GEMM + relu + lin2 dot + sigmoid
    mp_gemm_kernel<2><<<dim3((esim + 127) / 128, 1), 256, SMEM_TOTAL>>>(
        (const float*)embP, 0, (const float*)embP, 0, 0, ssim, dsim,
        16, 17, 0, l1b, 0, l2W, l2b,
        (float*)d_out, 0, esim);
}

// round 9
// speedup vs baseline: 2.0285x; 1.9054x over previous
#include <cuda_runtime.h>
#include <cuda_bf16.h>
#include <math.h>
#include <stdint.h>

#define NN   50000
#define FH   128

// ===================== scratch (static device globals) =====================
__device__ float         g_agg[(size_t)4 * NN * FH];
__device__ float         g_deg[4 * NN];
__device__ float         g_invdeg[4 * NN];
__device__ float         g_hstack[(size_t)4 * NN * FH];
__device__ float         g_pq[(size_t)2 * NN * FH];          // P = emb@W1a, Q = emb@W1b
__device__ __nv_bfloat16 g_xhi[(size_t)NN * FH],       g_xlo[(size_t)NN * FH];
__device__ __nv_bfloat16 g_agghi[(size_t)4 * NN * FH], g_agglo[(size_t)4 * NN * FH];
__device__ __nv_bfloat16 g_h1hi[(size_t)4 * NN * FH],  g_h1lo[(size_t)4 * NN * FH];
__device__ __nv_bfloat16 g_embhi[(size_t)NN * FH],     g_emblo[(size_t)NN * FH];
__device__ __nv_bfloat16 g_whi[18 * 16384], g_wlo[18 * 16384];   // [mat][n][k]

__device__ __forceinline__ void bsplit(float v, __nv_bfloat16& h, __nv_bfloat16& l) {
    h = __float2bfloat16(v);
    l = __float2bfloat16(v - __bfloat162float(h));
}
__device__ __forceinline__ uint32_t pack_bf16(__nv_bfloat16 a, __nv_bfloat16 b) {
    return (uint32_t)__bfloat16_as_ushort(a) | ((uint32_t)__bfloat16_as_ushort(b) << 16);
}
__device__ __forceinline__ void red_add_v4(float* p, float a, float b, float c, float d) {
    asm volatile("red.global.add.v4.f32 [%0], {%1, %2, %3, %4};"
                 :: "l"(p), "f"(a), "f"(b), "f"(c), "f"(d) : "memory");
}
__device__ __forceinline__ void red_add_f32(float* p, float a) {
    asm volatile("red.global.add.f32 [%0], %1;" :: "l"(p), "f"(a) : "memory");
}
__device__ __forceinline__ uint32_t smem_u32(const void* p) {
    uint32_t a;
    asm("{ .reg .u64 t; cvta.to.shared.u64 t, %1; cvt.u32.u64 %0, t; }" : "=r"(a) : "l"(p));
    return a;
}
__device__ __forceinline__ uint32_t swz(uint32_t off) { return off ^ ((off >> 3) & 0x70); }

__device__ __forceinline__ void ldm_x4(uint32_t addr, uint32_t* r) {
    asm volatile("ldmatrix.sync.aligned.m8n8.x4.shared.b16 {%0,%1,%2,%3}, [%4];"
                 : "=r"(r[0]), "=r"(r[1]), "=r"(r[2]), "=r"(r[3]) : "r"(addr));
}
__device__ __forceinline__ void mma16816(float* c, const uint32_t* a, const uint32_t* b) {
    asm volatile("mma.sync.aligned.m16n8k16.row.col.f32.bf16.bf16.f32 "
        "{%0,%1,%2,%3}, {%4,%5,%6,%7}, {%8,%9}, {%0,%1,%2,%3};"
        : "+f"(c[0]), "+f"(c[1]), "+f"(c[2]), "+f"(c[3])
        : "r"(a[0]), "r"(a[1]), "r"(a[2]), "r"(a[3]), "r"(b[0]), "r"(b[1]));
}

// ===================== small kernels =====================
__global__ void split_weights_kernel(const float* __restrict__ Ws1, const float* __restrict__ Wn1,
                                     const float* __restrict__ Ws2, const float* __restrict__ Wn2,
                                     const float* __restrict__ L1) {
    int g = blockIdx.x * blockDim.x + threadIdx.x;
    if (g >= 18 * 16384) return;
    int m = g >> 14, r = g & 16383, n = r >> 7, k = r & 127;
    const float* s;
    if (m < 4)       s = Ws1 + (size_t)m * 16384;
    else if (m < 8)  s = Wn1 + (size_t)(m - 4) * 16384;
    else if (m < 12) s = Ws2 + (size_t)(m - 8) * 16384;
    else if (m < 16) s = Wn2 + (size_t)(m - 12) * 16384;
    else             s = L1  + (size_t)(m - 16) * 16384;
    float v = s[k * 128 + n];                 // transpose [k][n] -> [n][k]
    __nv_bfloat16 h, l; bsplit(v, h, l);
    g_whi[(size_t)m * 16384 + n * 128 + k] = h;
    g_wlo[(size_t)m * 16384 + n * 128 + k] = l;
}

// split f32 rows -> bf16 hi/lo, optional per-row invdeg scale; grid.y = metapath
__global__ void split_rows_kernel(const float* __restrict__ src, int use_scale,
                                  __nv_bfloat16* __restrict__ hi, __nv_bfloat16* __restrict__ lo) {
    int y = blockIdx.y;
    int i = blockIdx.x * blockDim.x + threadIdx.x;
    if (i >= NN * FH) return;
    size_t o = (size_t)y * NN * FH + i;
    float v = src[o];
    if (use_scale) v *= g_invdeg[y * NN + (i >> 7)];
    __nv_bfloat16 h, l; bsplit(v, h, l);
    hi[o] = h; lo[o] = l;
}

struct EdgeArgs {
    const int* src[4]; const int* dst[4];
    const __nv_bfloat16* rhi[4]; const __nv_bfloat16* rlo[4];
    int ne[4];
};

__global__ void invdeg_kernel() {
    int i = blockIdx.x * blockDim.x + threadIdx.x;
    if (i < 4 * NN) g_invdeg[i] = 1.0f / fmaxf(g_deg[i], 1.0f);
}

// batched scatter: agg[y][dst] += (hi[src]+lo[src]); optional fused degree; one warp per edge
__global__ void scatter_kernel(EdgeArgs a, int dodeg) {
    int y = blockIdx.y;
    int w = (blockIdx.x * blockDim.x + threadIdx.x) >> 5;
    if (w >= a.ne[y]) return;
    int lane = threadIdx.x & 31;
    int s = __ldg(a.src[y] + w), d = __ldg(a.dst[y] + w);
    const __nv_bfloat162* ph = (const __nv_bfloat162*)(a.rhi[y] + (size_t)s * FH + lane * 4);
    const __nv_bfloat162* pl = (const __nv_bfloat162*)(a.rlo[y] + (size_t)s * FH + lane * 4);
    float2 h01 = __bfloat1622float2(ph[0]);
    float2 h23 = __bfloat1622float2(ph[1]);
    float2 l01 = __bfloat1622float2(pl[0]);
    float2 l23 = __bfloat1622float2(pl[1]);
    float* p = g_agg + ((size_t)y * NN + d) * FH + lane * 4;
    red_add_v4(p, h01.x + l01.x, h01.y + l01.y, h23.x + l23.x, h23.y + l23.y);
    if (dodeg && lane == 0) red_add_f32(&g_deg[y * NN + d], 1.0f);
}

// attention softmax over 4 metapaths -> emb bf16 hi/lo; one warp per node
__global__ void attention_kernel(const float* __restrict__ attW, const float* __restrict__ attB) {
    int n = (blockIdx.x * blockDim.x + threadIdx.x) >> 5;
    if (n >= NN) return;
    int lane = threadIdx.x & 31;
    float4 hv[4]; float logit[4];
#pragma unroll
    for (int k = 0; k < 4; ++k) {
        float4 h4 = *(const float4*)(g_hstack + ((size_t)k * NN + n) * FH + lane * 4);
        float4 w4 = *(const float4*)(attW + k * FH + lane * 4);
        hv[k] = h4;
        float p = h4.x * w4.x + h4.y * w4.y + h4.z * w4.z + h4.w * w4.w;
#pragma unroll
        for (int o = 16; o; o >>= 1) p += __shfl_xor_sync(0xffffffffu, p, o);
        logit[k] = p + attB[k];
    }
    float m = fmaxf(fmaxf(logit[0], logit[1]), fmaxf(logit[2], logit[3]));
    float e[4], s = 0.0f;
#pragma unroll
    for (int k = 0; k < 4; ++k) { e[k] = expf(logit[k] - m); s += e[k]; }
    float is = 1.0f / s;
    float4 o = make_float4(0.f, 0.f, 0.f, 0.f);
#pragma unroll
    for (int k = 0; k < 4; ++k) {
        float w = e[k] * is;
        o.x += w * hv[k].x; o.y += w * hv[k].y; o.z += w * hv[k].z; o.w += w * hv[k].w;
    }
    __nv_bfloat16 h0, l0, h1, l1, h2, l2, h3, l3;
    bsplit(o.x, h0, l0); bsplit(o.y, h1, l1); bsplit(o.z, h2, l2); bsplit(o.w, h3, l3);
    *(uint2*)(g_embhi + (size_t)n * FH + lane * 4) = make_uint2(pack_bf16(h0, h1), pack_bf16(h2, h3));
    *(uint2*)(g_emblo + (size_t)n * FH + lane * 4) = make_uint2(pack_bf16(l0, l1), pack_bf16(l2, l3));
}

// edge scorer: score = sigmoid(sum relu(P[s]+Q[d]+b) * w2 + b2); one warp per edge.
// P,Q are 25.6MB each -> L2-resident gathers.
__global__ void edge_score_kernel(const int* __restrict__ src, const int* __restrict__ dst,
                                  const float* __restrict__ l1b, const float* __restrict__ l2w,
                                  const float* __restrict__ l2b,
                                  float* __restrict__ out, int ne) {
    int e = (blockIdx.x * blockDim.x + threadIdx.x) >> 5;
    if (e >= ne) return;
    int lane = threadIdx.x & 31;
    int s = __ldg(src + e), d = __ldg(dst + e);
    float4 p = *(const float4*)(g_pq + (size_t)s * FH + lane * 4);
    float4 q = *(const float4*)(g_pq + (size_t)NN * FH + (size_t)d * FH + lane * 4);
    float4 b = *(const float4*)(l1b + lane * 4);
    float4 w = *(const float4*)(l2w + lane * 4);
    float acc = fmaxf(p.x + q.x + b.x, 0.f) * w.x + fmaxf(p.y + q.y + b.y, 0.f) * w.y
              + fmaxf(p.z + q.z + b.z, 0.f) * w.z + fmaxf(p.w + q.w + b.w, 0.f) * w.w;
#pragma unroll
    for (int o = 16; o; o >>= 1) acc += __shfl_xor_sync(0xffffffffu, acc, o);
    if (lane == 0) out[e] = 1.0f / (1.0f + expf(-(acc + __ldg(l2b))));
}

// ===================== mma.sync GEMM (round-5 schedule) =====================
// MODE 0: 2 halves, relu -> bf16 hi/lo.  MODE 1: 2 halves, +bias -> f32.
// MODE 3: single half (K=128), no bias -> f32 (used for P/Q; grid.y picks mat/out).
#define SB_BIAS 0
#define SB_TILES 4096
#define TILE_SZ 16384
#define SMEM_TOTAL (SB_TILES + 4 * TILE_SZ)

// stage a 128x64 bf16 tile (row-major 128B rows) into SW128-swizzled smem; 256 threads
__device__ __forceinline__ void stage_tile(uint32_t stile, const __nv_bfloat16* gbase,
                                           int row0, int nrows, int kofs, int tid) {
#pragma unroll
    for (int i = tid; i < 1024; i += 256) {
        int r = i >> 3, j = i & 7;
        uint4 v = make_uint4(0, 0, 0, 0);
        int grow = row0 + r;
        if (grow < nrows)
            v = *(const uint4*)(gbase + (size_t)grow * FH + kofs + j * 8);
        uint32_t off = (uint32_t)(r * 128 + j * 16);
        asm volatile("st.shared.v4.b32 [%0], {%1,%2,%3,%4};"
                     :: "r"(stile + swz(off)), "r"(v.x), "r"(v.y), "r"(v.z), "r"(v.w));
    }
}

__device__ __forceinline__ void load_a_frag(uint32_t tb, int wm, int ks, int lane, uint32_t* ra) {
    int q = lane >> 3, r = lane & 7;
    int rofs = ((q & 1) ? 8 : 0) + r;
    int kl = ks * 16 + ((q & 2) ? 8 : 0);
#pragma unroll
    for (int mf = 0; mf < 4; ++mf) {
        uint32_t off = (uint32_t)((wm * 64 + mf * 16 + rofs) * 128 + kl * 2);
        ldm_x4(tb + swz(off), ra + mf * 4);
    }
}
__device__ __forceinline__ void load_w_frag(uint32_t tb, int wn, int ks, int lane, uint32_t* rw) {
    int q = lane >> 3, r = lane & 7;
    int rofs = ((q & 2) ? 8 : 0) + r;
    int kl = ks * 16 + ((q & 1) ? 8 : 0);
#pragma unroll
    for (int pf = 0; pf < 2; ++pf) {
        uint32_t off = (uint32_t)((wn * 32 + pf * 16 + rofs) * 128 + kl * 2);
        ldm_x4(tb + swz(off), rw + pf * 4);
    }
}

template <int MODE>
__global__ void __launch_bounds__(256) mp_gemm_kernel(
    const __nv_bfloat16* __restrict__ a0hi, const __nv_bfloat16* __restrict__ a0lo, size_t a0stride,
    const __nv_bfloat16* __restrict__ a1hi, const __nv_bfloat16* __restrict__ a1lo, size_t a1stride,
    int w0mat, int w1mat, int wmatstride,
    const float* __restrict__ bias, int bstride,
    float* __restrict__ outf, size_t outfstride,
    __nv_bfloat16* __restrict__ outhi, __nv_bfloat16* __restrict__ outlo, size_t outbstride,
    int nrows)
{
    extern __shared__ char smem[];
    const uint32_t sb = smem_u32(smem);
    const int tid = threadIdx.x, lane = tid & 31, wid = tid >> 5;
    const int wm = wid & 1, wn = wid >> 1;
    const int y = blockIdx.y;
    const int row0 = blockIdx.x * 128;

    float* sbias = (float*)(smem + SB_BIAS);
    if (tid < 128) sbias[tid] = bias[bstride * y + tid];

    const __nv_bfloat16* ahis[2] = { a0hi + (size_t)y * a0stride, a1hi + (size_t)y * a1stride };
    const __nv_bfloat16* alos[2] = { a0lo + (size_t)y * a0stride, a1lo + (size_t)y * a1stride };
    const int wm0 = w0mat + y * wmatstride, wm1 = w1mat + y * wmatstride;

    const uint32_t tAHI = sb + SB_TILES,               tALO = sb + SB_TILES + TILE_SZ;
    const uint32_t tWHI = sb + SB_TILES + 2 * TILE_SZ, tWLO = sb + SB_TILES + 3 * TILE_SZ;

    float acc[4][4][4];
#pragma unroll
    for (int i = 0; i < 4; ++i)
#pragma unroll
        for (int j = 0; j < 4; ++j)
#pragma unroll
            for (int q = 0; q < 4; ++q) acc[i][j][q] = 0.0f;

    const int CHUNKS = (MODE == 3) ? 2 : 4;
#pragma unroll 1
    for (int c = 0; c < CHUNKS; ++c) {
        const int half = (MODE == 3) ? 0 : (c >> 1), kc = (c & 1) * 64;
        const __nv_bfloat16* whb = g_whi + (size_t)(half ? wm1 : wm0) * 16384;
        const __nv_bfloat16* wlb = g_wlo + (size_t)(half ? wm1 : wm0) * 16384;
        if (c) __syncthreads();
        stage_tile(tAHI, ahis[half], row0, nrows, kc, tid);
        stage_tile(tALO, alos[half], row0, nrows, kc, tid);
        stage_tile(tWHI, whb, 0, 128, kc, tid);
        stage_tile(tWLO, wlb, 0, 128, kc, tid);
        __syncthreads();

#pragma unroll
        for (int ks = 0; ks < 4; ++ks) {
            uint32_t ra[16], rwh[8], rwl[8];
            load_a_frag(tAHI, wm, ks, lane, ra);
            load_w_frag(tWHI, wn, ks, lane, rwh);
#pragma unroll
            for (int mf = 0; mf < 4; ++mf)
#pragma unroll
                for (int nf = 0; nf < 4; ++nf)
                    mma16816(acc[mf][nf], ra + mf * 4, rwh + nf * 2);
            load_w_frag(tWLO, wn, ks, lane, rwl);
#pragma unroll
            for (int mf = 0; mf < 4; ++mf)
#pragma unroll
                for (int nf = 0; nf < 4; ++nf)
                    mma16816(acc[mf][nf], ra + mf * 4, rwl + nf * 2);
            load_a_frag(tALO, wm, ks, lane, ra);
#pragma unroll
            for (int mf = 0; mf < 4; ++mf)
#pragma unroll
                for (int nf = 0; nf < 4; ++nf)
                    mma16816(acc[mf][nf], ra + mf * 4, rwh + nf * 2);
        }
    }

    // ---------------- epilogue ----------------
    // rows = row0 + wm*64 + mf*16 + (lane>>2) [+8]; cols = wn*32 + nf*8 + 2*(lane&3) [+1]
    const int rbase = row0 + wm * 64 + (lane >> 2);
    const int cbase = wn * 32 + 2 * (lane & 3);

#pragma unroll
    for (int mf = 0; mf < 4; ++mf) {
        int r0 = rbase + mf * 16, r1 = r0 + 8;
        bool v0 = r0 < nrows, v1 = r1 < nrows;
#pragma unroll
        for (int nf = 0; nf < 4; ++nf) {
            int gc = cbase + nf * 8;
            float b0v = (MODE == 3) ? 0.f : sbias[gc];
            float b1v = (MODE == 3) ? 0.f : sbias[gc + 1];
            float e0 = acc[mf][nf][0] + b0v, e1 = acc[mf][nf][1] + b1v;
            float e2 = acc[mf][nf][2] + b0v, e3 = acc[mf][nf][3] + b1v;
            if (MODE == 0) {
                e0 = fmaxf(e0, 0.f); e1 = fmaxf(e1, 0.f);
                e2 = fmaxf(e2, 0.f); e3 = fmaxf(e3, 0.f);
                __nv_bfloat16 h0, l0, h1, l1, h2, l2, h3, l3;
                bsplit(e0, h0, l0); bsplit(e1, h1, l1); bsplit(e2, h2, l2); bsplit(e3, h3, l3);
                if (v0) {
                    *(uint32_t*)(outhi + (size_t)y * outbstride + (size_t)r0 * FH + gc) = pack_bf16(h0, h1);
                    *(uint32_t*)(outlo + (size_t)y * outbstride + (size_t)r0 * FH + gc) = pack_bf16(l0, l1);
                }
                if (v1) {
                    *(uint32_t*)(outhi + (size_t)y * outbstride + (size_t)r1 * FH + gc) = pack_bf16(h2, h3);
                    *(uint32_t*)(outlo + (size_t)y * outbstride + (size_t)r1 * FH + gc) = pack_bf16(l2, l3);
                }
            } else {
                if (v0) *(float2*)(outf + (size_t)y * outfstride + (size_t)r0 * FH + gc) = make_float2(e0, e1);
                if (v1) *(float2*)(outf + (size_t)y * outfstride + (size_t)r1 * FH + gc) = make_float2(e2, e3);
            }
        }
    }
}

// ===================== host =====================
extern "C" void kernel_launch(void* const* d_in, const int* in_sizes, int n_in,
                              void* d_out, int out_size) {
    const float* x    = (const float*)d_in[0];
    const float* Ws1  = (const float*)d_in[1];
    const float* b1   = (const float*)d_in[2];
    const float* Wn1  = (const float*)d_in[3];
    const float* Ws2  = (const float*)d_in[4];
    const float* b2   = (const float*)d_in[5];
    const float* Wn2  = (const float*)d_in[6];
    const float* attW = (const float*)d_in[7];
    const float* attB = (const float*)d_in[8];
    const float* l1W  = (const float*)d_in[9];
    const float* l1b  = (const float*)d_in[10];
    const float* l2W  = (const float*)d_in[11];
    const float* l2b  = (const float*)d_in[12];
    const int* srcs[4] = {(const int*)d_in[13], (const int*)d_in[15],
                          (const int*)d_in[17], (const int*)d_in[19]};
    const int* dsts[4] = {(const int*)d_in[14], (const int*)d_in[16],
                          (const int*)d_in[18], (const int*)d_in[20]};
    const int* ssim = (const int*)d_in[21];
    const int* dsim = (const int*)d_in[22];
    const int  esim = in_sizes[21];

    void *aggP, *degP, *hsP, *pqP, *xhiP, *xloP, *agghiP, *aggloP, *h1hiP, *h1loP, *embhiP, *embloP;
    cudaGetSymbolAddress(&aggP, g_agg);
    cudaGetSymbolAddress(&degP, g_deg);
    cudaGetSymbolAddress(&hsP, g_hstack);
    cudaGetSymbolAddress(&pqP, g_pq);
    cudaGetSymbolAddress(&xhiP, g_xhi);     cudaGetSymbolAddress(&xloP, g_xlo);
    cudaGetSymbolAddress(&agghiP, g_agghi); cudaGetSymbolAddress(&aggloP, g_agglo);
    cudaGetSymbolAddress(&h1hiP, g_h1hi);   cudaGetSymbolAddress(&h1loP, g_h1lo);
    cudaGetSymbolAddress(&embhiP, g_embhi); cudaGetSymbolAddress(&embloP, g_emblo);

    cudaFuncSetAttribute(mp_gemm_kernel<0>, cudaFuncAttributeMaxDynamicSharedMemorySize, SMEM_TOTAL);
    cudaFuncSetAttribute(mp_gemm_kernel<1>, cudaFuncAttributeMaxDynamicSharedMemorySize, SMEM_TOTAL);
    cudaFuncSetAttribute(mp_gemm_kernel<3>, cudaFuncAttributeMaxDynamicSharedMemorySize, SMEM_TOTAL);

    EdgeArgs ea;
    int max_ne = 0;
    for (int k = 0; k < 4; ++k) {
        ea.src[k] = srcs[k]; ea.dst[k] = dsts[k];
        ea.ne[k] = in_sizes[13 + 2 * k];
        if (ea.ne[k] > max_ne) max_ne = ea.ne[k];
    }

    const int NB = (NN + 127) / 128;
    const size_t NF = (size_t)NN * FH;

    // 0. weight + x splits
    split_weights_kernel<<<(18 * 16384 + 255) / 256, 256>>>(Ws1, Wn1, Ws2, Wn2, l1W);
    split_rows_kernel<<<dim3((NN * FH + 255) / 256, 1), 256>>>(x, 0,
        (__nv_bfloat16*)xhiP, (__nv_bfloat16*)xloP);

    // 1. layer-1 aggregation + fused degree count
    cudaMemsetAsync(degP, 0, 4 * NN * sizeof(float));
    cudaMemsetAsync(aggP, 0, 4 * NF * sizeof(float));
    for (int k = 0; k < 4; ++k) { ea.rhi[k] = (const __nv_bfloat16*)xhiP; ea.rlo[k] = (const __nv_bfloat16*)xloP; }
    scatter_kernel<<<dim3((max_ne + 7) / 8, 4), 256>>>(ea, 1);
    invdeg_kernel<<<(4 * NN + 255) / 256, 256>>>();
    split_rows_kernel<<<dim3((NN * FH + 255) / 256, 4), 256>>>((const float*)aggP, 1,
        (__nv_bfloat16*)agghiP, (__nv_bfloat16*)aggloP);

    // 2. layer-1 GEMM: h1 = relu(x@Ws1 + aggn@Wn1 + b1) -> bf16 hi/lo
    mp_gemm_kernel<0><<<dim3(NB, 4), 256, SMEM_TOTAL>>>(
        (const __nv_bfloat16*)xhiP, (const __nv_bfloat16*)xloP, 0,
        (const __nv_bfloat16*)agghiP, (const __nv_bfloat16*)aggloP, NF,
        0, 4, 1, b1, FH,
        nullptr, 0, (__nv_bfloat16*)h1hiP, (__nv_bfloat16*)h1loP, NF, NN);

    // 3. layer-2 aggregation
    cudaMemsetAsync(aggP, 0, 4 * NF * sizeof(float));
    for (int k = 0; k < 4; ++k) {
        ea.rhi[k] = (const __nv_bfloat16*)h1hiP + (size_t)k * NF;
        ea.rlo[k] = (const __nv_bfloat16*)h1loP + (size_t)k * NF;
    }
    scatter_kernel<<<dim3((max_ne + 7) / 8, 4), 256>>>(ea, 0);
    split_rows_kernel<<<dim3((NN * FH + 255) / 256, 4), 256>>>((const float*)aggP, 1,
        (__nv_bfloat16*)agghiP, (__nv_bfloat16*)aggloP);

    // 4. layer-2 GEMM -> f32 hstack
    mp_gemm_kernel<1><<<dim3(NB, 4), 256, SMEM_TOTAL>>>(
        (const __nv_bfloat16*)h1hiP, (const __nv_bfloat16*)h1loP, NF,
        (const __nv_bfloat16*)agghiP, (const __nv_bfloat16*)aggloP, NF,
        8, 12, 1, b2, FH,
        (float*)hsP, NF, nullptr, nullptr, 0, NN);

    // 5. attention -> emb bf16 hi/lo
    attention_kernel<<<(NN * 32 + 255) / 256, 256>>>(attW, attB);

    // 6. P/Q GEMM: P = emb@W1a (y=0), Q = emb@W1b (y=1); no bias
    mp_gemm_kernel<3><<<dim3(NB, 2), 256, SMEM_TOTAL>>>(
        (const __nv_bfloat16*)embhiP, (const __nv_bfloat16*)embloP, 0,
        (const __nv_bfloat16*)embhiP, (const __nv_bfloat16*)embloP, 0,
        16, 16, 1, l1b, 0,
        (float*)pqP, NF, nullptr, nullptr, 0, NN);

    // 7. edge scorer: relu(P[s]+Q[d]+b) . w2 -> sigmoid
    edge_score_kernel<<<((size_t)esim * 32 + 255) / 256, 256>>>(
        ssim, dsim, l1b, l2W, l2b, (float*)d_out, esim);
}

// round 10
// speedup vs baseline: 2.3867x; 1.1766x over previous
#include <cuda_runtime.h>
#include <cuda_bf16.h>
#include <math.h>
#include <stdint.h>

#define NN   50000
#define FH   128

// ===================== scratch (static device globals) =====================
__device__ float         g_agg[(size_t)4 * NN * FH];
__device__ float         g_deg[4 * NN];
__device__ float         g_invdeg[4 * NN];
__device__ float         g_pq[(size_t)2 * NN * FH];          // P = emb@W1a, Q = emb@W1b
__device__ __nv_bfloat16 g_xhi[(size_t)NN * FH],       g_xlo[(size_t)NN * FH];
__device__ __nv_bfloat16 g_agghi[(size_t)4 * NN * FH], g_agglo[(size_t)4 * NN * FH];
__device__ __nv_bfloat16 g_h1hi[(size_t)4 * NN * FH],  g_h1lo[(size_t)4 * NN * FH];
__device__ __nv_bfloat16 g_hshi[(size_t)4 * NN * FH],  g_hslo[(size_t)4 * NN * FH];
__device__ __nv_bfloat16 g_embhi[(size_t)NN * FH],     g_emblo[(size_t)NN * FH];
__device__ __nv_bfloat16 g_whi[18 * 16384], g_wlo[18 * 16384];   // [mat][n][k]

__device__ __forceinline__ void bsplit(float v, __nv_bfloat16& h, __nv_bfloat16& l) {
    h = __float2bfloat16(v);
    l = __float2bfloat16(v - __bfloat162float(h));
}
__device__ __forceinline__ uint32_t pack_bf16(__nv_bfloat16 a, __nv_bfloat16 b) {
    return (uint32_t)__bfloat16_as_ushort(a) | ((uint32_t)__bfloat16_as_ushort(b) << 16);
}
__device__ __forceinline__ void red_add_v4(float* p, float a, float b, float c, float d) {
    asm volatile("red.global.add.v4.f32 [%0], {%1, %2, %3, %4};"
                 :: "l"(p), "f"(a), "f"(b), "f"(c), "f"(d) : "memory");
}
__device__ __forceinline__ void red_add_f32(float* p, float a) {
    asm volatile("red.global.add.f32 [%0], %1;" :: "l"(p), "f"(a) : "memory");
}
__device__ __forceinline__ uint32_t smem_u32(const void* p) {
    uint32_t a;
    asm("{ .reg .u64 t; cvta.to.shared.u64 t, %1; cvt.u32.u64 %0, t; }" : "=r"(a) : "l"(p));
    return a;
}
__device__ __forceinline__ uint32_t swz(uint32_t off) { return off ^ ((off >> 3) & 0x70); }

__device__ __forceinline__ void ldm_x4(uint32_t addr, uint32_t* r) {
    asm volatile("ldmatrix.sync.aligned.m8n8.x4.shared.b16 {%0,%1,%2,%3}, [%4];"
                 : "=r"(r[0]), "=r"(r[1]), "=r"(r[2]), "=r"(r[3]) : "r"(addr));
}
__device__ __forceinline__ void mma16816(float* c, const uint32_t* a, const uint32_t* b) {
    asm volatile("mma.sync.aligned.m16n8k16.row.col.f32.bf16.bf16.f32 "
        "{%0,%1,%2,%3}, {%4,%5,%6,%7}, {%8,%9}, {%0,%1,%2,%3};"
        : "+f"(c[0]), "+f"(c[1]), "+f"(c[2]), "+f"(c[3])
        : "r"(a[0]), "r"(a[1]), "r"(a[2]), "r"(a[3]), "r"(b[0]), "r"(b[1]));
}
// cp.async with zero-fill when src_bytes < 16
__device__ __forceinline__ void cpasync16z(uint32_t dst, const void* src, int src_bytes) {
    asm volatile("cp.async.ca.shared.global [%0], [%1], 16, %2;"
                 :: "r"(dst), "l"(__cvta_generic_to_global(src)), "r"(src_bytes) : "memory");
}
#define CP_COMMIT() asm volatile("cp.async.commit_group;" ::: "memory")
#define CP_WAIT0()  asm volatile("cp.async.wait_group 0;" ::: "memory")

// ===================== small kernels =====================
__global__ void split_weights_kernel(const float* __restrict__ Ws1, const float* __restrict__ Wn1,
                                     const float* __restrict__ Ws2, const float* __restrict__ Wn2,
                                     const float* __restrict__ L1) {
    int g = blockIdx.x * blockDim.x + threadIdx.x;
    if (g >= 18 * 16384) return;
    int m = g >> 14, r = g & 16383, n = r >> 7, k = r & 127;
    const float* s;
    if (m < 4)       s = Ws1 + (size_t)m * 16384;
    else if (m < 8)  s = Wn1 + (size_t)(m - 4) * 16384;
    else if (m < 12) s = Ws2 + (size_t)(m - 8) * 16384;
    else if (m < 16) s = Wn2 + (size_t)(m - 12) * 16384;
    else             s = L1  + (size_t)(m - 16) * 16384;
    float v = s[k * 128 + n];                 // transpose [k][n] -> [n][k]
    __nv_bfloat16 h, l; bsplit(v, h, l);
    g_whi[(size_t)m * 16384 + n * 128 + k] = h;
    g_wlo[(size_t)m * 16384 + n * 128 + k] = l;
}

// split f32 rows -> bf16 hi/lo, optional per-row invdeg scale; grid.y = metapath
__global__ void split_rows_kernel(const float* __restrict__ src, int use_scale,
                                  __nv_bfloat16* __restrict__ hi, __nv_bfloat16* __restrict__ lo) {
    int y = blockIdx.y;
    int i = blockIdx.x * blockDim.x + threadIdx.x;
    if (i >= NN * FH) return;
    size_t o = (size_t)y * NN * FH + i;
    float v = src[o];
    if (use_scale) v *= g_invdeg[y * NN + (i >> 7)];
    __nv_bfloat16 h, l; bsplit(v, h, l);
    hi[o] = h; lo[o] = l;
}

struct EdgeArgs {
    const int* src[4]; const int* dst[4];
    const __nv_bfloat16* rhi[4]; const __nv_bfloat16* rlo[4];
    int off[5];   // exclusive prefix of edge counts (metapath-major scheduling)
};

__global__ void invdeg_kernel() {
    int i = blockIdx.x * blockDim.x + threadIdx.x;
    if (i < 4 * NN) g_invdeg[i] = 1.0f / fmaxf(g_deg[i], 1.0f);
}

// linearized batched scatter, metapath-major block order (sequential phases ->
// per-phase working set = source(25.6MB) + agg slice(25.6MB) stays L2-resident).
// one warp per edge; optional fused degree count.
__global__ void scatter_kernel(EdgeArgs a, int dodeg) {
    int w = (blockIdx.x * blockDim.x + threadIdx.x) >> 5;
    if (w >= a.off[4]) return;
    int y = (w >= a.off[1]) + (w >= a.off[2]) + (w >= a.off[3]);
    int e = w - a.off[y];
    int lane = threadIdx.x & 31;
    int s = __ldg(a.src[y] + e), d = __ldg(a.dst[y] + e);
    const __nv_bfloat162* ph = (const __nv_bfloat162*)(a.rhi[y] + (size_t)s * FH + lane * 4);
    const __nv_bfloat162* pl = (const __nv_bfloat162*)(a.rlo[y] + (size_t)s * FH + lane * 4);
    float2 h01 = __bfloat1622float2(ph[0]);
    float2 h23 = __bfloat1622float2(ph[1]);
    float2 l01 = __bfloat1622float2(pl[0]);
    float2 l23 = __bfloat1622float2(pl[1]);
    float* p = g_agg + ((size_t)y * NN + d) * FH + lane * 4;
    red_add_v4(p, h01.x + l01.x, h01.y + l01.y, h23.x + l23.x, h23.y + l23.y);
    if (dodeg && lane == 0) red_add_f32(&g_deg[y * NN + d], 1.0f);
}

// attention softmax over 4 metapaths (hstack in bf16 hi/lo) -> emb bf16 hi/lo; one warp per node
__global__ void attention_kernel(const float* __restrict__ attW, const float* __restrict__ attB) {
    int n = (blockIdx.x * blockDim.x + threadIdx.x) >> 5;
    if (n >= NN) return;
    int lane = threadIdx.x & 31;
    float4 hv[4]; float logit[4];
#pragma unroll
    for (int k = 0; k < 4; ++k) {
        size_t o = ((size_t)k * NN + n) * FH + lane * 4;
        const __nv_bfloat162* ph = (const __nv_bfloat162*)(g_hshi + o);
        const __nv_bfloat162* pl = (const __nv_bfloat162*)(g_hslo + o);
        float2 h01 = __bfloat1622float2(ph[0]);
        float2 h23 = __bfloat1622float2(ph[1]);
        float2 l01 = __bfloat1622float2(pl[0]);
        float2 l23 = __bfloat1622float2(pl[1]);
        float4 h4 = make_float4(h01.x + l01.x, h01.y + l01.y, h23.x + l23.x, h23.y + l23.y);
        float4 w4 = *(const float4*)(attW + k * FH + lane * 4);
        hv[k] = h4;
        float p = h4.x * w4.x + h4.y * w4.y + h4.z * w4.z + h4.w * w4.w;
#pragma unroll
        for (int o2 = 16; o2; o2 >>= 1) p += __shfl_xor_sync(0xffffffffu, p, o2);
        logit[k] = p + attB[k];
    }
    float m = fmaxf(fmaxf(logit[0], logit[1]), fmaxf(logit[2], logit[3]));
    float e[4], s = 0.0f;
#pragma unroll
    for (int k = 0; k < 4; ++k) { e[k] = expf(logit[k] - m); s += e[k]; }
    float is = 1.0f / s;
    float4 o = make_float4(0.f, 0.f, 0.f, 0.f);
#pragma unroll
    for (int k = 0; k < 4; ++k) {
        float w = e[k] * is;
        o.x += w * hv[k].x; o.y += w * hv[k].y; o.z += w * hv[k].z; o.w += w * hv[k].w;
    }
    __nv_bfloat16 h0, l0, h1, l1, h2, l2, h3, l3;
    bsplit(o.x, h0, l0); bsplit(o.y, h1, l1); bsplit(o.z, h2, l2); bsplit(o.w, h3, l3);
    *(uint2*)(g_embhi + (size_t)n * FH + lane * 4) = make_uint2(pack_bf16(h0, h1), pack_bf16(h2, h3));
    *(uint2*)(g_emblo + (size_t)n * FH + lane * 4) = make_uint2(pack_bf16(l0, l1), pack_bf16(l2, l3));
}

// edge scorer: score = sigmoid(sum relu(P[s]+Q[d]+b) * w2 + b2); one warp per edge.
__global__ void edge_score_kernel(const int* __restrict__ src, const int* __restrict__ dst,
                                  const float* __restrict__ l1b, const float* __restrict__ l2w,
                                  const float* __restrict__ l2b,
                                  float* __restrict__ out, int ne) {
    int e = (blockIdx.x * blockDim.x + threadIdx.x) >> 5;
    if (e >= ne) return;
    int lane = threadIdx.x & 31;
    int s = __ldg(src + e), d = __ldg(dst + e);
    float4 p = *(const float4*)(g_pq + (size_t)s * FH + lane * 4);
    float4 q = *(const float4*)(g_pq + (size_t)NN * FH + (size_t)d * FH + lane * 4);
    float4 b = *(const float4*)(l1b + lane * 4);
    float4 w = *(const float4*)(l2w + lane * 4);
    float acc = fmaxf(p.x + q.x + b.x, 0.f) * w.x + fmaxf(p.y + q.y + b.y, 0.f) * w.y
              + fmaxf(p.z + q.z + b.z, 0.f) * w.z + fmaxf(p.w + q.w + b.w, 0.f) * w.w;
#pragma unroll
    for (int o = 16; o; o >>= 1) acc += __shfl_xor_sync(0xffffffffu, acc, o);
    if (lane == 0) out[e] = 1.0f / (1.0f + expf(-(acc + __ldg(l2b))));
}

// ===================== mma.sync GEMM (cp.async staging) =====================
// MODE 0: 2 halves, bias+relu -> bf16 hi/lo.  MODE 1: 2 halves, +bias -> bf16 hi/lo.
// MODE 3: single half (K=128), no bias -> f32.
#define SB_BIAS 0
#define SB_TILES 4096
#define TILE_SZ 16384
#define SMEM_TOTAL (SB_TILES + 4 * TILE_SZ)

// stage a 128x64 bf16 tile (row-major 128B rows) into SW128-swizzled smem via cp.async
__device__ __forceinline__ void stage_tile(uint32_t stile, const __nv_bfloat16* gbase,
                                           int row0, int nrows, int kofs, int tid) {
#pragma unroll
    for (int i = tid; i < 1024; i += 256) {
        int r = i >> 3, j = i & 7;
        int grow = row0 + r;
        bool valid = grow < nrows;
        const __nv_bfloat16* src = gbase + (size_t)(valid ? grow : 0) * FH + kofs + j * 8;
        uint32_t off = (uint32_t)(r * 128 + j * 16);
        cpasync16z(stile + swz(off), src, valid ? 16 : 0);
    }
}

__device__ __forceinline__ void load_a_frag(uint32_t tb, int wm, int ks, int lane, uint32_t* ra) {
    int q = lane >> 3, r = lane & 7;
    int rofs = ((q & 1) ? 8 : 0) + r;
    int kl = ks * 16 + ((q & 2) ? 8 : 0);
#pragma unroll
    for (int mf = 0; mf < 4; ++mf) {
        uint32_t off = (uint32_t)((wm * 64 + mf * 16 + rofs) * 128 + kl * 2);
        ldm_x4(tb + swz(off), ra + mf * 4);
    }
}
__device__ __forceinline__ void load_w_frag(uint32_t tb, int wn, int ks, int lane, uint32_t* rw) {
    int q = lane >> 3, r = lane & 7;
    int rofs = ((q & 2) ? 8 : 0) + r;
    int kl = ks * 16 + ((q & 1) ? 8 : 0);
#pragma unroll
    for (int pf = 0; pf < 2; ++pf) {
        uint32_t off = (uint32_t)((wn * 32 + pf * 16 + rofs) * 128 + kl * 2);
        ldm_x4(tb + swz(off), rw + pf * 4);
    }
}

template <int MODE>
__global__ void __launch_bounds__(256) mp_gemm_kernel(
    const __nv_bfloat16* __restrict__ a0hi, const __nv_bfloat16* __restrict__ a0lo, size_t a0stride,
    const __nv_bfloat16* __restrict__ a1hi, const __nv_bfloat16* __restrict__ a1lo, size_t a1stride,
    int w0mat, int w1mat, int wmatstride,
    const float* __restrict__ bias, int bstride,
    float* __restrict__ outf, size_t outfstride,
    __nv_bfloat16* __restrict__ outhi, __nv_bfloat16* __restrict__ outlo, size_t outbstride,
    int nrows)
{
    extern __shared__ char smem[];
    const uint32_t sb = smem_u32(smem);
    const int tid = threadIdx.x, lane = tid & 31, wid = tid >> 5;
    const int wm = wid & 1, wn = wid >> 1;
    const int y = blockIdx.y;
    const int row0 = blockIdx.x * 128;

    float* sbias = (float*)(smem + SB_BIAS);
    if (tid < 128) sbias[tid] = bias[bstride * y + tid];

    const __nv_bfloat16* ahis[2] = { a0hi + (size_t)y * a0stride, a1hi + (size_t)y * a1stride };
    const __nv_bfloat16* alos[2] = { a0lo + (size_t)y * a0stride, a1lo + (size_t)y * a1stride };
    const int wm0 = w0mat + y * wmatstride, wm1 = w1mat + y * wmatstride;

    const uint32_t tAHI = sb + SB_TILES,               tALO = sb + SB_TILES + TILE_SZ;
    const uint32_t tWHI = sb + SB_TILES + 2 * TILE_SZ, tWLO = sb + SB_TILES + 3 * TILE_SZ;

    float acc[4][4][4];
#pragma unroll
    for (int i = 0; i < 4; ++i)
#pragma unroll
        for (int j = 0; j < 4; ++j)
#pragma unroll
            for (int q = 0; q < 4; ++q) acc[i][j][q] = 0.0f;

    const int CHUNKS = (MODE == 3) ? 2 : 4;
#pragma unroll 1
    for (int c = 0; c < CHUNKS; ++c) {
        const int half = (MODE == 3) ? 0 : (c >> 1), kc = (c & 1) * 64;
        const __nv_bfloat16* whb = g_whi + (size_t)(half ? wm1 : wm0) * 16384;
        const __nv_bfloat16* wlb = g_wlo + (size_t)(half ? wm1 : wm0) * 16384;
        if (c) __syncthreads();
        stage_tile(tAHI, ahis[half], row0, nrows, kc, tid);
        stage_tile(tALO, alos[half], row0, nrows, kc, tid);
        stage_tile(tWHI, whb, 0, 128, kc, tid);
        stage_tile(tWLO, wlb, 0, 128, kc, tid);
        CP_COMMIT();
        CP_WAIT0();
        __syncthreads();

#pragma unroll
        for (int ks = 0; ks < 4; ++ks) {
            uint32_t ra[16], rwh[8], rwl[8];
            load_a_frag(tAHI, wm, ks, lane, ra);
            load_w_frag(tWHI, wn, ks, lane, rwh);
#pragma unroll
            for (int mf = 0; mf < 4; ++mf)
#pragma unroll
                for (int nf = 0; nf < 4; ++nf)
                    mma16816(acc[mf][nf], ra + mf * 4, rwh + nf * 2);
            load_w_frag(tWLO, wn, ks, lane, rwl);
#pragma unroll
            for (int mf = 0; mf < 4; ++mf)
#pragma unroll
                for (int nf = 0; nf < 4; ++nf)
                    mma16816(acc[mf][nf], ra + mf * 4, rwl + nf * 2);
            load_a_frag(tALO, wm, ks, lane, ra);
#pragma unroll
            for (int mf = 0; mf < 4; ++mf)
#pragma unroll
                for (int nf = 0; nf < 4; ++nf)
                    mma16816(acc[mf][nf], ra + mf * 4, rwh + nf * 2);
        }
    }

    // ---------------- epilogue ----------------
    // rows = row0 + wm*64 + mf*16 + (lane>>2) [+8]; cols = wn*32 + nf*8 + 2*(lane&3) [+1]
    const int rbase = row0 + wm * 64 + (lane >> 2);
    const int cbase = wn * 32 + 2 * (lane & 3);

#pragma unroll
    for (int mf = 0; mf < 4; ++mf) {
        int r0 = rbase + mf * 16, r1 = r0 + 8;
        bool v0 = r0 < nrows, v1 = r1 < nrows;
#pragma unroll
        for (int nf = 0; nf < 4; ++nf) {
            int gc = cbase + nf * 8;
            float b0v = (MODE == 3) ? 0.f : sbias[gc];
            float b1v = (MODE == 3) ? 0.f : sbias[gc + 1];
            float e0 = acc[mf][nf][0] + b0v, e1 = acc[mf][nf][1] + b1v;
            float e2 = acc[mf][nf][2] + b0v, e3 = acc[mf][nf][3] + b1v;
            if (MODE == 3) {
                if (v0) *(float2*)(outf + (size_t)y * outfstride + (size_t)r0 * FH + gc) = make_float2(e0, e1);
                if (v1) *(float2*)(outf + (size_t)y * outfstride + (size_t)r1 * FH + gc) = make_float2(e2, e3);
            } else {
                if (MODE == 0) {
                    e0 = fmaxf(e0, 0.f); e1 = fmaxf(e1, 0.f);
                    e2 = fmaxf(e2, 0.f); e3 = fmaxf(e3, 0.f);
                }
                __nv_bfloat16 h0, l0, h1, l1, h2, l2, h3, l3;
                bsplit(e0, h0, l0); bsplit(e1, h1, l1); bsplit(e2, h2, l2); bsplit(e3, h3, l3);
                if (v0) {
                    *(uint32_t*)(outhi + (size_t)y * outbstride + (size_t)r0 * FH + gc) = pack_bf16(h0, h1);
                    *(uint32_t*)(outlo + (size_t)y * outbstride + (size_t)r0 * FH + gc) = pack_bf16(l0, l1);
                }
                if (v1) {
                    *(uint32_t*)(outhi + (size_t)y * outbstride + (size_t)r1 * FH + gc) = pack_bf16(h2, h3);
                    *(uint32_t*)(outlo + (size_t)y * outbstride + (size_t)r1 * FH + gc) = pack_bf16(l2, l3);
                }
            }
        }
    }
}

// ===================== host =====================
extern "C" void kernel_launch(void* const* d_in, const int* in_sizes, int n_in,
                              void* d_out, int out_size) {
    const float* x    = (const float*)d_in[0];
    const float* Ws1  = (const float*)d_in[1];
    const float* b1   = (const float*)d_in[2];
    const float* Wn1  = (const float*)d_in[3];
    const float* Ws2  = (const float*)d_in[4];
    const float* b2   = (const float*)d_in[5];
    const float* Wn2  = (const float*)d_in[6];
    const float* attW = (const float*)d_in[7];
    const float* attB = (const float*)d_in[8];
    const float* l1W  = (const float*)d_in[9];
    const float* l1b  = (const float*)d_in[10];
    const float* l2W  = (const float*)d_in[11];
    const float* l2b  = (const float*)d_in[12];
    const int* srcs[4] = {(const int*)d_in[13], (const int*)d_in[15],
                          (const int*)d_in[17], (const int*)d_in[19]};
    const int* dsts[4] = {(const int*)d_in[14], (const int*)d_in[16],
                          (const int*)d_in[18], (const int*)d_in[20]};
    const int* ssim = (const int*)d_in[21];
    const int* dsim = (const int*)d_in[22];
    const int  esim = in_sizes[21];

    void *aggP, *degP, *pqP, *xhiP, *xloP, *agghiP, *aggloP, *h1hiP, *h1loP,
         *hshiP, *hsloP, *embhiP, *embloP;
    cudaGetSymbolAddress(&aggP, g_agg);
    cudaGetSymbolAddress(&degP, g_deg);
    cudaGetSymbolAddress(&pqP, g_pq);
    cudaGetSymbolAddress(&xhiP, g_xhi);     cudaGetSymbolAddress(&xloP, g_xlo);
    cudaGetSymbolAddress(&agghiP, g_agghi); cudaGetSymbolAddress(&aggloP, g_agglo);
    cudaGetSymbolAddress(&h1hiP, g_h1hi);   cudaGetSymbolAddress(&h1loP, g_h1lo);
    cudaGetSymbolAddress(&hshiP, g_hshi);   cudaGetSymbolAddress(&hsloP, g_hslo);
    cudaGetSymbolAddress(&embhiP, g_embhi); cudaGetSymbolAddress(&embloP, g_emblo);

    cudaFuncSetAttribute(mp_gemm_kernel<0>, cudaFuncAttributeMaxDynamicSharedMemorySize, SMEM_TOTAL);
    cudaFuncSetAttribute(mp_gemm_kernel<1>, cudaFuncAttributeMaxDynamicSharedMemorySize, SMEM_TOTAL);
    cudaFuncSetAttribute(mp_gemm_kernel<3>, cudaFuncAttributeMaxDynamicSharedMemorySize, SMEM_TOTAL);

    EdgeArgs ea;
    ea.off[0] = 0;
    for (int k = 0; k < 4; ++k) {
        ea.src[k] = srcs[k]; ea.dst[k] = dsts[k];
        ea.off[k + 1] = ea.off[k] + in_sizes[13 + 2 * k];
    }
    const int total_e = ea.off[4];
    const int NBS = (int)(((size_t)total_e * 32 + 255) / 256);

    const int NB = (NN + 127) / 128;
    const size_t NF = (size_t)NN * FH;

    // 0. weight + x splits
    split_weights_kernel<<<(18 * 16384 + 255) / 256, 256>>>(Ws1, Wn1, Ws2, Wn2, l1W);
    split_rows_kernel<<<dim3((NN * FH + 255) / 256, 1), 256>>>(x, 0,
        (__nv_bfloat16*)xhiP, (__nv_bfloat16*)xloP);

    // 1. layer-1 aggregation (metapath-major) + fused degree count
    cudaMemsetAsync(degP, 0, 4 * NN * sizeof(float));
    cudaMemsetAsync(aggP, 0, 4 * NF * sizeof(float));
    for (int k = 0; k < 4; ++k) { ea.rhi[k] = (const __nv_bfloat16*)xhiP; ea.rlo[k] = (const __nv_bfloat16*)xloP; }
    scatter_kernel<<<NBS, 256>>>(ea, 1);
    invdeg_kernel<<<(4 * NN + 255) / 256, 256>>>();
    split_rows_kernel<<<dim3((NN * FH + 255) / 256, 4), 256>>>((const float*)aggP, 1,
        (__nv_bfloat16*)agghiP, (__nv_bfloat16*)aggloP);

    // 2. layer-1 GEMM: h1 = relu(x@Ws1 + aggn@Wn1 + b1) -> bf16 hi/lo
    mp_gemm_kernel<0><<<dim3(NB, 4), 256, SMEM_TOTAL>>>(
        (const __nv_bfloat16*)xhiP, (const __nv_bfloat16*)xloP, 0,
        (const __nv_bfloat16*)agghiP, (const __nv_bfloat16*)aggloP, NF,
        0, 4, 1, b1, FH,
        nullptr, 0, (__nv_bfloat16*)h1hiP, (__nv_bfloat16*)h1loP, NF, NN);

    // 3. layer-2 aggregation (metapath-major)
    cudaMemsetAsync(aggP, 0, 4 * NF * sizeof(float));
    for (int k = 0; k < 4; ++k) {
        ea.rhi[k] = (const __nv_bfloat16*)h1hiP + (size_t)k * NF;
        ea.rlo[k] = (const __nv_bfloat16*)h1loP + (size_t)k * NF;
    }
    scatter_kernel<<<NBS, 256>>>(ea, 0);
    split_rows_kernel<<<dim3((NN * FH + 255) / 256, 4), 256>>>((const float*)aggP, 1,
        (__nv_bfloat16*)agghiP, (__nv_bfloat16*)aggloP);

    // 4. layer-2 GEMM -> hstack bf16 hi/lo
    mp_gemm_kernel<1><<<dim3(NB, 4), 256, SMEM_TOTAL>>>(
        (const __nv_bfloat16*)h1hiP, (const __nv_bfloat16*)h1loP, NF,
        (const __nv_bfloat16*)agghiP, (const __nv_bfloat16*)aggloP, NF,
        8, 12, 1, b2, FH,
        nullptr, 0, (__nv_bfloat16*)hshiP, (__nv_bfloat16*)hsloP, NF, NN);

    // 5. attention -> emb bf16 hi/lo
    attention_kernel<<<(NN * 32 + 255) / 256, 256>>>(attW, attB);

    // 6. P/Q GEMM: P = emb@W1a (y=0), Q = emb@W1b (y=1); no bias
    mp_gemm_kernel<3><<<dim3(NB, 2), 256, SMEM_TOTAL>>>(
        (const __nv_bfloat16*)embhiP, (const __nv_bfloat16*)embloP, 0,
        (const __nv_bfloat16*)embhiP, (const __nv_bfloat16*)embloP, 0,
        16, 16, 1, l1b, 0,
        (float*)pqP, NF, nullptr, nullptr, 0, NN);

    // 7. edge scorer: relu(P[s]+Q[d]+b) . w2 -> sigmoid
    edge_score_kernel<<<(int)(((size_t)esim * 32 + 255) / 256), 256>>>(
        ssim, dsim, l1b, l2W, l2b, (float*)d_out, esim);
}

// round 11
// speedup vs baseline: 2.9898x; 1.2527x over previous
#include <cuda_runtime.h>
#include <cuda_bf16.h>
#include <math.h>
#include <stdint.h>

#define NN   50000
#define FH   128
#define NTOT (4 * NN)
#define CSRMAX 2200000

// ===================== scratch (static device globals) =====================
__device__ int           g_degi[NTOT];
__device__ int           g_offs[NTOT + 1];
__device__ int           g_cur[NTOT];
__device__ int           g_csr[CSRMAX];
__device__ float         g_pq[(size_t)2 * NN * FH];          // P = emb@W1a, Q = emb@W1b
__device__ __nv_bfloat16 g_xhi[(size_t)NN * FH],       g_xlo[(size_t)NN * FH];
__device__ __nv_bfloat16 g_agghi[(size_t)4 * NN * FH], g_agglo[(size_t)4 * NN * FH];
__device__ __nv_bfloat16 g_h1hi[(size_t)4 * NN * FH],  g_h1lo[(size_t)4 * NN * FH];
__device__ __nv_bfloat16 g_hshi[(size_t)4 * NN * FH],  g_hslo[(size_t)4 * NN * FH];
__device__ __nv_bfloat16 g_embhi[(size_t)NN * FH],     g_emblo[(size_t)NN * FH];
__device__ __nv_bfloat16 g_whi[18 * 16384], g_wlo[18 * 16384];   // [mat][n][k]

__device__ __forceinline__ void bsplit(float v, __nv_bfloat16& h, __nv_bfloat16& l) {
    h = __float2bfloat16(v);
    l = __float2bfloat16(v - __bfloat162float(h));
}
__device__ __forceinline__ uint32_t pack_bf16(__nv_bfloat16 a, __nv_bfloat16 b) {
    return (uint32_t)__bfloat16_as_ushort(a) | ((uint32_t)__bfloat16_as_ushort(b) << 16);
}
__device__ __forceinline__ uint32_t smem_u32(const void* p) {
    uint32_t a;
    asm("{ .reg .u64 t; cvta.to.shared.u64 t, %1; cvt.u32.u64 %0, t; }" : "=r"(a) : "l"(p));
    return a;
}
__device__ __forceinline__ uint32_t swz(uint32_t off) { return off ^ ((off >> 3) & 0x70); }

__device__ __forceinline__ void ldm_x4(uint32_t addr, uint32_t* r) {
    asm volatile("ldmatrix.sync.aligned.m8n8.x4.shared.b16 {%0,%1,%2,%3}, [%4];"
                 : "=r"(r[0]), "=r"(r[1]), "=r"(r[2]), "=r"(r[3]) : "r"(addr));
}
__device__ __forceinline__ void mma16816(float* c, const uint32_t* a, const uint32_t* b) {
    asm volatile("mma.sync.aligned.m16n8k16.row.col.f32.bf16.bf16.f32 "
        "{%0,%1,%2,%3}, {%4,%5,%6,%7}, {%8,%9}, {%0,%1,%2,%3};"
        : "+f"(c[0]), "+f"(c[1]), "+f"(c[2]), "+f"(c[3])
        : "r"(a[0]), "r"(a[1]), "r"(a[2]), "r"(a[3]), "r"(b[0]), "r"(b[1]));
}
__device__ __forceinline__ void cpasync16z(uint32_t dst, const void* src, int src_bytes) {
    asm volatile("cp.async.ca.shared.global [%0], [%1], 16, %2;"
                 :: "r"(dst), "l"(__cvta_generic_to_global(src)), "r"(src_bytes) : "memory");
}
#define CP_COMMIT() asm volatile("cp.async.commit_group;" ::: "memory")
#define CP_WAIT0()  asm volatile("cp.async.wait_group 0;" ::: "memory")

// ===================== small kernels =====================
__global__ void split_weights_kernel(const float* __restrict__ Ws1, const float* __restrict__ Wn1,
                                     const float* __restrict__ Ws2, const float* __restrict__ Wn2,
                                     const float* __restrict__ L1) {
    int g = blockIdx.x * blockDim.x + threadIdx.x;
    if (g >= 18 * 16384) return;
    int m = g >> 14, r = g & 16383, n = r >> 7, k = r & 127;
    const float* s;
    if (m < 4)       s = Ws1 + (size_t)m * 16384;
    else if (m < 8)  s = Wn1 + (size_t)(m - 4) * 16384;
    else if (m < 12) s = Ws2 + (size_t)(m - 8) * 16384;
    else if (m < 16) s = Wn2 + (size_t)(m - 12) * 16384;
    else             s = L1  + (size_t)(m - 16) * 16384;
    float v = s[k * 128 + n];                 // transpose [k][n] -> [n][k]
    __nv_bfloat16 h, l; bsplit(v, h, l);
    g_whi[(size_t)m * 16384 + n * 128 + k] = h;
    g_wlo[(size_t)m * 16384 + n * 128 + k] = l;
}

// split f32 rows -> bf16 hi/lo (x only)
__global__ void split_x_kernel(const float* __restrict__ src) {
    int i = blockIdx.x * blockDim.x + threadIdx.x;
    if (i >= NN * FH) return;
    __nv_bfloat16 h, l; bsplit(src[i], h, l);
    g_xhi[i] = h; g_xlo[i] = l;
}

struct EdgeArgs {
    const int* src[4]; const int* dst[4];
    int off[5];
};

// ---------- CSR build (once per launch; shared by both layers) ----------
__global__ void degcount_kernel(EdgeArgs a) {
    int w = blockIdx.x * blockDim.x + threadIdx.x;
    if (w >= a.off[4]) return;
    int y = (w >= a.off[1]) + (w >= a.off[2]) + (w >= a.off[3]);
    atomicAdd(&g_degi[y * NN + __ldg(a.dst[y] + (w - a.off[y]))], 1);
}

__global__ void scan_kernel() {   // single block, 1024 threads
    __shared__ int part[1024];
    const int per = (NTOT + 1023) / 1024;
    int t = threadIdx.x;
    int beg = t * per, end = min(beg + per, NTOT);
    int s = 0;
    for (int i = beg; i < end; ++i) s += g_degi[i];
    part[t] = s;
    __syncthreads();
    if (t == 0) {
        int run = 0;
        for (int i = 0; i < 1024; ++i) { int v = part[i]; part[i] = run; run += v; }
    }
    __syncthreads();
    int run = part[t];
    for (int i = beg; i < end; ++i) { g_offs[i] = run; run += g_degi[i]; }
    if (t == 1023) g_offs[NTOT] = run;
}

__global__ void fill_kernel(EdgeArgs a) {
    int w = blockIdx.x * blockDim.x + threadIdx.x;
    if (w >= a.off[4]) return;
    int y = (w >= a.off[1]) + (w >= a.off[2]) + (w >= a.off[3]);
    int e = w - a.off[y];
    int s = __ldg(a.src[y] + e), d = __ldg(a.dst[y] + e);
    int node = y * NN + d;
    int pos = g_offs[node] + atomicAdd(&g_cur[node], 1);
    g_csr[pos] = s;
}

// ---------- CSR gather aggregation: one warp per (metapath,node) ----------
// mean over in-neighbors, written as bf16 hi/lo with 1/deg scaling folded in.
// f32src != null -> gather f32 rows (layer 1, x); else bf16 hi/lo (layer 2, h1).
__global__ void gather_kernel(const float* __restrict__ f32src,
                              const __nv_bfloat16* __restrict__ shi,
                              const __nv_bfloat16* __restrict__ slo, size_t ystride) {
    int g = (blockIdx.x * blockDim.x + threadIdx.x) >> 5;
    if (g >= NTOT) return;
    int lane = threadIdx.x & 31;
    int y = g / NN;
    int o0 = __ldg(g_offs + g), o1 = __ldg(g_offs + g + 1);
    float4 acc = make_float4(0.f, 0.f, 0.f, 0.f);
    int s = (o0 < o1) ? __ldg(g_csr + o0) : 0;
    if (f32src) {
        for (int j = o0; j < o1; ++j) {
            int sn = (j + 1 < o1) ? __ldg(g_csr + j + 1) : 0;
            float4 v = __ldg((const float4*)(f32src + (size_t)s * FH) + lane);
            acc.x += v.x; acc.y += v.y; acc.z += v.z; acc.w += v.w;
            s = sn;
        }
    } else {
        const __nv_bfloat16* hb = shi + (size_t)y * ystride;
        const __nv_bfloat16* lb = slo + (size_t)y * ystride;
        for (int j = o0; j < o1; ++j) {
            int sn = (j + 1 < o1) ? __ldg(g_csr + j + 1) : 0;
            const __nv_bfloat162* ph = (const __nv_bfloat162*)(hb + (size_t)s * FH + lane * 4);
            const __nv_bfloat162* pl = (const __nv_bfloat162*)(lb + (size_t)s * FH + lane * 4);
            float2 a = __bfloat1622float2(ph[0]);
            float2 b = __bfloat1622float2(ph[1]);
            float2 c = __bfloat1622float2(pl[0]);
            float2 d = __bfloat1622float2(pl[1]);
            acc.x += a.x + c.x; acc.y += a.y + c.y; acc.z += b.x + d.x; acc.w += b.y + d.y;
            s = sn;
        }
    }
    float sc = 1.0f / fmaxf((float)(o1 - o0), 1.0f);
    __nv_bfloat16 h0, l0, h1, l1, h2, l2, h3, l3;
    bsplit(acc.x * sc, h0, l0); bsplit(acc.y * sc, h1, l1);
    bsplit(acc.z * sc, h2, l2); bsplit(acc.w * sc, h3, l3);
    size_t o = (size_t)g * FH + lane * 4;
    *(uint2*)(g_agghi + o) = make_uint2(pack_bf16(h0, h1), pack_bf16(h2, h3));
    *(uint2*)(g_agglo + o) = make_uint2(pack_bf16(l0, l1), pack_bf16(l2, l3));
}

// attention softmax over 4 metapaths (hstack in bf16 hi/lo) -> emb bf16 hi/lo; one warp per node
__global__ void attention_kernel(const float* __restrict__ attW, const float* __restrict__ attB) {
    int n = (blockIdx.x * blockDim.x + threadIdx.x) >> 5;
    if (n >= NN) return;
    int lane = threadIdx.x & 31;
    float4 hv[4]; float logit[4];
#pragma unroll
    for (int k = 0; k < 4; ++k) {
        size_t o = ((size_t)k * NN + n) * FH + lane * 4;
        const __nv_bfloat162* ph = (const __nv_bfloat162*)(g_hshi + o);
        const __nv_bfloat162* pl = (const __nv_bfloat162*)(g_hslo + o);
        float2 h01 = __bfloat1622float2(ph[0]);
        float2 h23 = __bfloat1622float2(ph[1]);
        float2 l01 = __bfloat1622float2(pl[0]);
        float2 l23 = __bfloat1622float2(pl[1]);
        float4 h4 = make_float4(h01.x + l01.x, h01.y + l01.y, h23.x + l23.x, h23.y + l23.y);
        float4 w4 = *(const float4*)(attW + k * FH + lane * 4);
        hv[k] = h4;
        float p = h4.x * w4.x + h4.y * w4.y + h4.z * w4.z + h4.w * w4.w;
#pragma unroll
        for (int o2 = 16; o2; o2 >>= 1) p += __shfl_xor_sync(0xffffffffu, p, o2);
        logit[k] = p + attB[k];
    }
    float m = fmaxf(fmaxf(logit[0], logit[1]), fmaxf(logit[2], logit[3]));
    float e[4], s = 0.0f;
#pragma unroll
    for (int k = 0; k < 4; ++k) { e[k] = expf(logit[k] - m); s += e[k]; }
    float is = 1.0f / s;
    float4 o = make_float4(0.f, 0.f, 0.f, 0.f);
#pragma unroll
    for (int k = 0; k < 4; ++k) {
        float w = e[k] * is;
        o.x += w * hv[k].x; o.y += w * hv[k].y; o.z += w * hv[k].z; o.w += w * hv[k].w;
    }
    __nv_bfloat16 h0, l0, h1, l1, h2, l2, h3, l3;
    bsplit(o.x, h0, l0); bsplit(o.y, h1, l1); bsplit(o.z, h2, l2); bsplit(o.w, h3, l3);
    *(uint2*)(g_embhi + (size_t)n * FH + lane * 4) = make_uint2(pack_bf16(h0, h1), pack_bf16(h2, h3));
    *(uint2*)(g_emblo + (size_t)n * FH + lane * 4) = make_uint2(pack_bf16(l0, l1), pack_bf16(l2, l3));
}

// edge scorer: score = sigmoid(sum relu(P[s]+Q[d]+b) * w2 + b2); one warp per edge.
__global__ void edge_score_kernel(const int* __restrict__ src, const int* __restrict__ dst,
                                  const float* __restrict__ l1b, const float* __restrict__ l2w,
                                  const float* __restrict__ l2b,
                                  float* __restrict__ out, int ne) {
    int e = (blockIdx.x * blockDim.x + threadIdx.x) >> 5;
    if (e >= ne) return;
    int lane = threadIdx.x & 31;
    int s = __ldg(src + e), d = __ldg(dst + e);
    float4 p = *(const float4*)(g_pq + (size_t)s * FH + lane * 4);
    float4 q = *(const float4*)(g_pq + (size_t)NN * FH + (size_t)d * FH + lane * 4);
    float4 b = *(const float4*)(l1b + lane * 4);
    float4 w = *(const float4*)(l2w + lane * 4);
    float acc = fmaxf(p.x + q.x + b.x, 0.f) * w.x + fmaxf(p.y + q.y + b.y, 0.f) * w.y
              + fmaxf(p.z + q.z + b.z, 0.f) * w.z + fmaxf(p.w + q.w + b.w, 0.f) * w.w;
#pragma unroll
    for (int o = 16; o; o >>= 1) acc += __shfl_xor_sync(0xffffffffu, acc, o);
    if (lane == 0) out[e] = 1.0f / (1.0f + expf(-(acc + __ldg(l2b))));
}

// ===================== mma.sync GEMM (cp.async staging) =====================
// MODE 0: 2 halves, bias+relu -> bf16 hi/lo.  MODE 1: 2 halves, +bias -> bf16 hi/lo.
// MODE 3: single half (K=128), no bias -> f32.
#define SB_BIAS 0
#define SB_TILES 4096
#define TILE_SZ 16384
#define SMEM_TOTAL (SB_TILES + 4 * TILE_SZ)

__device__ __forceinline__ void stage_tile(uint32_t stile, const __nv_bfloat16* gbase,
                                           int row0, int nrows, int kofs, int tid) {
#pragma unroll
    for (int i = tid; i < 1024; i += 256) {
        int r = i >> 3, j = i & 7;
        int grow = row0 + r;
        bool valid = grow < nrows;
        const __nv_bfloat16* src = gbase + (size_t)(valid ? grow : 0) * FH + kofs + j * 8;
        uint32_t off = (uint32_t)(r * 128 + j * 16);
        cpasync16z(stile + swz(off), src, valid ? 16 : 0);
    }
}

__device__ __forceinline__ void load_a_frag(uint32_t tb, int wm, int ks, int lane, uint32_t* ra) {
    int q = lane >> 3, r = lane & 7;
    int rofs = ((q & 1) ? 8 : 0) + r;
    int kl = ks * 16 + ((q & 2) ? 8 : 0);
#pragma unroll
    for (int mf = 0; mf < 4; ++mf) {
        uint32_t off = (uint32_t)((wm * 64 + mf * 16 + rofs) * 128 + kl * 2);
        ldm_x4(tb + swz(off), ra + mf * 4);
    }
}
__device__ __forceinline__ void load_w_frag(uint32_t tb, int wn, int ks, int lane, uint32_t* rw) {
    int q = lane >> 3, r = lane & 7;
    int rofs = ((q & 2) ? 8 : 0) + r;
    int kl = ks * 16 + ((q & 1) ? 8 : 0);
#pragma unroll
    for (int pf = 0; pf < 2; ++pf) {
        uint32_t off = (uint32_t)((wn * 32 + pf * 16 + rofs) * 128 + kl * 2);
        ldm_x4(tb + swz(off), rw + pf * 4);
    }
}

template <int MODE>
__global__ void __launch_bounds__(256) mp_gemm_kernel(
    const __nv_bfloat16* __restrict__ a0hi, const __nv_bfloat16* __restrict__ a0lo, size_t a0stride,
    const __nv_bfloat16* __restrict__ a1hi, const __nv_bfloat16* __restrict__ a1lo, size_t a1stride,
    int w0mat, int w1mat, int wmatstride,
    const float* __restrict__ bias, int bstride,
    float* __restrict__ outf, size_t outfstride,
    __nv_bfloat16* __restrict__ outhi, __nv_bfloat16* __restrict__ outlo, size_t outbstride,
    int nrows)
{
    extern __shared__ char smem[];
    const uint32_t sb = smem_u32(smem);
    const int tid = threadIdx.x, lane = tid & 31, wid = tid >> 5;
    const int wm = wid & 1, wn = wid >> 1;
    const int y = blockIdx.y;
    const int row0 = blockIdx.x * 128;

    float* sbias = (float*)(smem + SB_BIAS);
    if (tid < 128) sbias[tid] = bias[bstride * y + tid];

    const __nv_bfloat16* ahis[2] = { a0hi + (size_t)y * a0stride, a1hi + (size_t)y * a1stride };
    const __nv_bfloat16* alos[2] = { a0lo + (size_t)y * a0stride, a1lo + (size_t)y * a1stride };
    const int wm0 = w0mat + y * wmatstride, wm1 = w1mat + y * wmatstride;

    const uint32_t tAHI = sb + SB_TILES,               tALO = sb + SB_TILES + TILE_SZ;
    const uint32_t tWHI = sb + SB_TILES + 2 * TILE_SZ, tWLO = sb + SB_TILES + 3 * TILE_SZ;

    float acc[4][4][4];
#pragma unroll
    for (int i = 0; i < 4; ++i)
#pragma unroll
        for (int j = 0; j < 4; ++j)
#pragma unroll
            for (int q = 0; q < 4; ++q) acc[i][j][q] = 0.0f;

    const int CHUNKS = (MODE == 3) ? 2 : 4;
#pragma unroll 1
    for (int c = 0; c < CHUNKS; ++c) {
        const int half = (MODE == 3) ? 0 : (c >> 1), kc = (c & 1) * 64;
        const __nv_bfloat16* whb = g_whi + (size_t)(half ? wm1 : wm0) * 16384;
        const __nv_bfloat16* wlb = g_wlo + (size_t)(half ? wm1 : wm0) * 16384;
        if (c) __syncthreads();
        stage_tile(tAHI, ahis[half], row0, nrows, kc, tid);
        stage_tile(tALO, alos[half], row0, nrows, kc, tid);
        stage_tile(tWHI, whb, 0, 128, kc, tid);
        stage_tile(tWLO, wlb, 0, 128, kc, tid);
        CP_COMMIT();
        CP_WAIT0();
        __syncthreads();

#pragma unroll
        for (int ks = 0; ks < 4; ++ks) {
            uint32_t ra[16], rwh[8], rwl[8];
            load_a_frag(tAHI, wm, ks, lane, ra);
            load_w_frag(tWHI, wn, ks, lane, rwh);
#pragma unroll
            for (int mf = 0; mf < 4; ++mf)
#pragma unroll
                for (int nf = 0; nf < 4; ++nf)
                    mma16816(acc[mf][nf], ra + mf * 4, rwh + nf * 2);
            load_w_frag(tWLO, wn, ks, lane, rwl);
#pragma unroll
            for (int mf = 0; mf < 4; ++mf)
#pragma unroll
                for (int nf = 0; nf < 4; ++nf)
                    mma16816(acc[mf][nf], ra + mf * 4, rwl + nf * 2);
            load_a_frag(tALO, wm, ks, lane, ra);
#pragma unroll
            for (int mf = 0; mf < 4; ++mf)
#pragma unroll
                for (int nf = 0; nf < 4; ++nf)
                    mma16816(acc[mf][nf], ra + mf * 4, rwh + nf * 2);
        }
    }

    // ---------------- epilogue ----------------
    const int rbase = row0 + wm * 64 + (lane >> 2);
    const int cbase = wn * 32 + 2 * (lane & 3);

#pragma unroll
    for (int mf = 0; mf < 4; ++mf) {
        int r0 = rbase + mf * 16, r1 = r0 + 8;
        bool v0 = r0 < nrows, v1 = r1 < nrows;
#pragma unroll
        for (int nf = 0; nf < 4; ++nf) {
            int gc = cbase + nf * 8;
            float b0v = (MODE == 3) ? 0.f : sbias[gc];
            float b1v = (MODE == 3) ? 0.f : sbias[gc + 1];
            float e0 = acc[mf][nf][0] + b0v, e1 = acc[mf][nf][1] + b1v;
            float e2 = acc[mf][nf][2] + b0v, e3 = acc[mf][nf][3] + b1v;
            if (MODE == 3) {
                if (v0) *(float2*)(outf + (size_t)y * outfstride + (size_t)r0 * FH + gc) = make_float2(e0, e1);
                if (v1) *(float2*)(outf + (size_t)y * outfstride + (size_t)r1 * FH + gc) = make_float2(e2, e3);
            } else {
                if (MODE == 0) {
                    e0 = fmaxf(e0, 0.f); e1 = fmaxf(e1, 0.f);
                    e2 = fmaxf(e2, 0.f); e3 = fmaxf(e3, 0.f);
                }
                __nv_bfloat16 h0, l0, h1, l1, h2, l2, h3, l3;
                bsplit(e0, h0, l0); bsplit(e1, h1, l1); bsplit(e2, h2, l2); bsplit(e3, h3, l3);
                if (v0) {
                    *(uint32_t*)(outhi + (size_t)y * outbstride + (size_t)r0 * FH + gc) = pack_bf16(h0, h1);
                    *(uint32_t*)(outlo + (size_t)y * outbstride + (size_t)r0 * FH + gc) = pack_bf16(l0, l1);
                }
                if (v1) {
                    *(uint32_t*)(outhi + (size_t)y * outbstride + (size_t)r1 * FH + gc) = pack_bf16(h2, h3);
                    *(uint32_t*)(outlo + (size_t)y * outbstride + (size_t)r1 * FH + gc) = pack_bf16(l2, l3);
                }
            }
        }
    }
}

// ===================== host =====================
extern "C" void kernel_launch(void* const* d_in, const int* in_sizes, int n_in,
                              void* d_out, int out_size) {
    const float* x    = (const float*)d_in[0];
    const float* Ws1  = (const float*)d_in[1];
    const float* b1   = (const float*)d_in[2];
    const float* Wn1  = (const float*)d_in[3];
    const float* Ws2  = (const float*)d_in[4];
    const float* b2   = (const float*)d_in[5];
    const float* Wn2  = (const float*)d_in[6];
    const float* attW = (const float*)d_in[7];
    const float* attB = (const float*)d_in[8];
    const float* l1W  = (const float*)d_in[9];
    const float* l1b  = (const float*)d_in[10];
    const float* l2W  = (const float*)d_in[11];
    const float* l2b  = (const float*)d_in[12];
    const int* srcs[4] = {(const int*)d_in[13], (const int*)d_in[15],
                          (const int*)d_in[17], (const int*)d_in[19]};
    const int* dsts[4] = {(const int*)d_in[14], (const int*)d_in[16],
                          (const int*)d_in[18], (const int*)d_in[20]};
    const int* ssim = (const int*)d_in[21];
    const int* dsim = (const int*)d_in[22];
    const int  esim = in_sizes[21];

    void *degiP, *curP, *pqP, *xhiP, *xloP, *agghiP, *aggloP, *h1hiP, *h1loP,
         *hshiP, *hsloP, *embhiP, *embloP;
    cudaGetSymbolAddress(&degiP, g_degi);
    cudaGetSymbolAddress(&curP, g_cur);
    cudaGetSymbolAddress(&pqP, g_pq);
    cudaGetSymbolAddress(&xhiP, g_xhi);     cudaGetSymbolAddress(&xloP, g_xlo);
    cudaGetSymbolAddress(&agghiP, g_agghi); cudaGetSymbolAddress(&aggloP, g_agglo);
    cudaGetSymbolAddress(&h1hiP, g_h1hi);   cudaGetSymbolAddress(&h1loP, g_h1lo);
    cudaGetSymbolAddress(&hshiP, g_hshi);   cudaGetSymbolAddress(&hsloP, g_hslo);
    cudaGetSymbolAddress(&embhiP, g_embhi); cudaGetSymbolAddress(&embloP, g_emblo);

    cudaFuncSetAttribute(mp_gemm_kernel<0>, cudaFuncAttributeMaxDynamicSharedMemorySize, SMEM_TOTAL);
    cudaFuncSetAttribute(mp_gemm_kernel<1>, cudaFuncAttributeMaxDynamicSharedMemorySize, SMEM_TOTAL);
    cudaFuncSetAttribute(mp_gemm_kernel<3>, cudaFuncAttributeMaxDynamicSharedMemorySize, SMEM_TOTAL);

    EdgeArgs ea;
    ea.off[0] = 0;
    for (int k = 0; k < 4; ++k) {
        ea.src[k] = srcs[k]; ea.dst[k] = dsts[k];
        ea.off[k + 1] = ea.off[k] + in_sizes[13 + 2 * k];
    }
    const int total_e = ea.off[4];

    const int NB = (NN + 127) / 128;
    const size_t NF = (size_t)NN * FH;
    const int NG = (int)(((size_t)NTOT * 32 + 255) / 256);

    // 0. weight + x splits
    split_weights_kernel<<<(18 * 16384 + 255) / 256, 256>>>(Ws1, Wn1, Ws2, Wn2, l1W);
    split_x_kernel<<<(NN * FH + 255) / 256, 256>>>(x);

    // 1. CSR build (shared by both layers)
    cudaMemsetAsync(degiP, 0, NTOT * sizeof(int));
    cudaMemsetAsync(curP, 0, NTOT * sizeof(int));
    degcount_kernel<<<(total_e + 255) / 256, 256>>>(ea);
    scan_kernel<<<1, 1024>>>();
    fill_kernel<<<(total_e + 255) / 256, 256>>>(ea);

    // 2. layer-1 aggregation: gather mean of x over in-neighbors -> agg bf16 hi/lo
    gather_kernel<<<NG, 256>>>(x, nullptr, nullptr, 0);

    // 3. layer-1 GEMM: h1 = relu(x@Ws1 + aggn@Wn1 + b1) -> bf16 hi/lo
    mp_gemm_kernel<0><<<dim3(NB, 4), 256, SMEM_TOTAL>>>(
        (const __nv_bfloat16*)xhiP, (const __nv_bfloat16*)xloP, 0,
        (const __nv_bfloat16*)agghiP, (const __nv_bfloat16*)aggloP, NF,
        0, 4, 1, b1, FH,
        nullptr, 0, (__nv_bfloat16*)h1hiP, (__nv_bfloat16*)h1loP, NF, NN);

    // 4. layer-2 aggregation: gather mean of h1 over in-neighbors
    gather_kernel<<<NG, 256>>>(nullptr, (const __nv_bfloat16*)h1hiP,
                               (const __nv_bfloat16*)h1loP, NF);

    // 5. layer-2 GEMM -> hstack bf16 hi/lo
    mp_gemm_kernel<1><<<dim3(NB, 4), 256, SMEM_TOTAL>>>(
        (const __nv_bfloat16*)h1hiP, (const __nv_bfloat16*)h1loP, NF,
        (const __nv_bfloat16*)agghiP, (const __nv_bfloat16*)aggloP, NF,
        8, 12, 1, b2, FH,
        nullptr, 0, (__nv_bfloat16*)hshiP, (__nv_bfloat16*)hsloP, NF, NN);

    // 6. attention -> emb bf16 hi/lo
    attention_kernel<<<(NN * 32 + 255) / 256, 256>>>(attW, attB);

    // 7. P/Q GEMM: P = emb@W1a (y=0), Q = emb@W1b (y=1); no bias
    mp_gemm_kernel<3><<<dim3(NB, 2), 256, SMEM_TOTAL>>>(
        (const __nv_bfloat16*)embhiP, (const __nv_bfloat16*)embloP, 0,
        (const __nv_bfloat16*)embhiP, (const __nv_bfloat16*)embloP, 0,
        16, 16, 1, l1b, 0,
        (float*)pqP, NF, nullptr, nullptr, 0, NN);

    // 8. edge scorer: relu(P[s]+Q[d]+b) . w2 -> sigmoid
    edge_score_kernel<<<(int)(((size_t)esim * 32 + 255) / 256), 256>>>(
        ssim, dsim, l1b, l2W, l2b, (float*)d_out, esim);
}

// round 12
// speedup vs baseline: 3.8474x; 1.2868x over previous
#include <cuda_runtime.h>
#include <cuda_bf16.h>
#include <math.h>
#include <stdint.h>

#define NN   50000
#define FH   128
#define NTOT (4 * NN)
#define CSRMAX 2200000
#define SCAN_B ((NTOT + 1023) / 1024)

// ===================== scratch (static device globals) =====================
__device__ int           g_degi[NTOT];
__device__ int           g_offs[NTOT + 1];
__device__ int           g_cur[NTOT];
__device__ int           g_part[SCAN_B];
__device__ int           g_csr[CSRMAX];
__device__ float         g_pq[(size_t)2 * NN * FH];          // P = emb@W1a, Q = emb@W1b
__device__ __nv_bfloat16 g_xhi[(size_t)NN * FH],       g_xlo[(size_t)NN * FH];
__device__ __nv_bfloat16 g_agghi[(size_t)4 * NN * FH], g_agglo[(size_t)4 * NN * FH];
__device__ __nv_bfloat16 g_h1hi[(size_t)4 * NN * FH],  g_h1lo[(size_t)4 * NN * FH];
__device__ __nv_bfloat16 g_hshi[(size_t)4 * NN * FH],  g_hslo[(size_t)4 * NN * FH];
__device__ __nv_bfloat16 g_embhi[(size_t)NN * FH],     g_emblo[(size_t)NN * FH];
__device__ __nv_bfloat16 g_whi[18 * 16384], g_wlo[18 * 16384];   // [mat][n][k]

__device__ __forceinline__ void bsplit(float v, __nv_bfloat16& h, __nv_bfloat16& l) {
    h = __float2bfloat16(v);
    l = __float2bfloat16(v - __bfloat162float(h));
}
__device__ __forceinline__ uint32_t pack_bf16(__nv_bfloat16 a, __nv_bfloat16 b) {
    return (uint32_t)__bfloat16_as_ushort(a) | ((uint32_t)__bfloat16_as_ushort(b) << 16);
}
__device__ __forceinline__ uint32_t smem_u32(const void* p) {
    uint32_t a;
    asm("{ .reg .u64 t; cvta.to.shared.u64 t, %1; cvt.u32.u64 %0, t; }" : "=r"(a) : "l"(p));
    return a;
}
__device__ __forceinline__ uint32_t swz(uint32_t off) { return off ^ ((off >> 3) & 0x70); }

__device__ __forceinline__ void ldm_x4(uint32_t addr, uint32_t* r) {
    asm volatile("ldmatrix.sync.aligned.m8n8.x4.shared.b16 {%0,%1,%2,%3}, [%4];"
                 : "=r"(r[0]), "=r"(r[1]), "=r"(r[2]), "=r"(r[3]) : "r"(addr));
}
__device__ __forceinline__ void mma16816(float* c, const uint32_t* a, const uint32_t* b) {
    asm volatile("mma.sync.aligned.m16n8k16.row.col.f32.bf16.bf16.f32 "
        "{%0,%1,%2,%3}, {%4,%5,%6,%7}, {%8,%9}, {%0,%1,%2,%3};"
        : "+f"(c[0]), "+f"(c[1]), "+f"(c[2]), "+f"(c[3])
        : "r"(a[0]), "r"(a[1]), "r"(a[2]), "r"(a[3]), "r"(b[0]), "r"(b[1]));
}
__device__ __forceinline__ void cpasync16z(uint32_t dst, const void* src, int src_bytes) {
    asm volatile("cp.async.ca.shared.global [%0], [%1], 16, %2;"
                 :: "r"(dst), "l"(__cvta_generic_to_global(src)), "r"(src_bytes) : "memory");
}
#define CP_COMMIT() asm volatile("cp.async.commit_group;" ::: "memory")
#define CP_WAIT0()  asm volatile("cp.async.wait_group 0;" ::: "memory")

// ===================== small kernels =====================
__global__ void split_weights_kernel(const float* __restrict__ Ws1, const float* __restrict__ Wn1,
                                     const float* __restrict__ Ws2, const float* __restrict__ Wn2,
                                     const float* __restrict__ L1) {
    int g = blockIdx.x * blockDim.x + threadIdx.x;
    if (g >= 18 * 16384) return;
    int m = g >> 14, r = g & 16383, n = r >> 7, k = r & 127;
    const float* s;
    if (m < 4)       s = Ws1 + (size_t)m * 16384;
    else if (m < 8)  s = Wn1 + (size_t)(m - 4) * 16384;
    else if (m < 12) s = Ws2 + (size_t)(m - 8) * 16384;
    else if (m < 16) s = Wn2 + (size_t)(m - 12) * 16384;
    else             s = L1  + (size_t)(m - 16) * 16384;
    float v = s[k * 128 + n];                 // transpose [k][n] -> [n][k]
    __nv_bfloat16 h, l; bsplit(v, h, l);
    g_whi[(size_t)m * 16384 + n * 128 + k] = h;
    g_wlo[(size_t)m * 16384 + n * 128 + k] = l;
}

// split f32 rows -> bf16 hi/lo (x only)
__global__ void split_x_kernel(const float* __restrict__ src) {
    int i = blockIdx.x * blockDim.x + threadIdx.x;
    if (i >= NN * FH) return;
    __nv_bfloat16 h, l; bsplit(src[i], h, l);
    g_xhi[i] = h; g_xlo[i] = l;
}

struct EdgeArgs {
    const int* src[4]; const int* dst[4];
    int off[5];
};

// ---------- CSR build (once per launch; shared by both layers) ----------
__global__ void degcount_kernel(EdgeArgs a) {
    int w = blockIdx.x * blockDim.x + threadIdx.x;
    if (w >= a.off[4]) return;
    int y = (w >= a.off[1]) + (w >= a.off[2]) + (w >= a.off[3]);
    atomicAdd(&g_degi[y * NN + __ldg(a.dst[y] + (w - a.off[y]))], 1);
}

// 3-phase device-wide exclusive scan of g_degi -> g_offs
__global__ void scan1_kernel() {   // per-block 1024-chunk scan
    __shared__ int sh[1024];
    int t = threadIdx.x;
    int i = blockIdx.x * 1024 + t;
    int v = (i < NTOT) ? g_degi[i] : 0;
    sh[t] = v;
    __syncthreads();
#pragma unroll
    for (int o = 1; o < 1024; o <<= 1) {
        int add = (t >= o) ? sh[t - o] : 0;
        __syncthreads();
        sh[t] += add;
        __syncthreads();
    }
    if (i < NTOT) g_offs[i] = sh[t] - v;      // block-local exclusive
    if (t == 1023) g_part[blockIdx.x] = sh[1023];
}

__global__ void scan2_kernel() {   // single block scans block totals
    __shared__ int sh[256];
    int t = threadIdx.x;
    int v = (t < SCAN_B) ? g_part[t] : 0;
    sh[t] = v;
    __syncthreads();
#pragma unroll
    for (int o = 1; o < 256; o <<= 1) {
        int add = (t >= o) ? sh[t - o] : 0;
        __syncthreads();
        sh[t] += add;
        __syncthreads();
    }
    if (t < SCAN_B) g_part[t] = sh[t] - v;    // exclusive base per block
    if (t == 255) g_offs[NTOT] = sh[255];     // grand total
}

__global__ void scan3_kernel() {   // add block bases
    int i = blockIdx.x * 1024 + threadIdx.x;
    if (i < NTOT) g_offs[i] += g_part[blockIdx.x];
}

__global__ void fill_kernel(EdgeArgs a) {
    int w = blockIdx.x * blockDim.x + threadIdx.x;
    if (w >= a.off[4]) return;
    int y = (w >= a.off[1]) + (w >= a.off[2]) + (w >= a.off[3]);
    int e = w - a.off[y];
    int s = __ldg(a.src[y] + e), d = __ldg(a.dst[y] + e);
    int node = y * NN + d;
    int pos = g_offs[node] + atomicAdd(&g_cur[node], 1);
    g_csr[pos] = s;
}

// ---------- CSR gather aggregation: one warp per (metapath,node) ----------
__global__ void gather_kernel(const float* __restrict__ f32src,
                              const __nv_bfloat16* __restrict__ shi,
                              const __nv_bfloat16* __restrict__ slo, size_t ystride) {
    int g = (blockIdx.x * blockDim.x + threadIdx.x) >> 5;
    if (g >= NTOT) return;
    int lane = threadIdx.x & 31;
    int y = g / NN;
    int o0 = __ldg(g_offs + g), o1 = __ldg(g_offs + g + 1);
    float4 acc = make_float4(0.f, 0.f, 0.f, 0.f);
    int s = (o0 < o1) ? __ldg(g_csr + o0) : 0;
    if (f32src) {
        for (int j = o0; j < o1; ++j) {
            int sn = (j + 1 < o1) ? __ldg(g_csr + j + 1) : 0;
            float4 v = __ldg((const float4*)(f32src + (size_t)s * FH) + lane);
            acc.x += v.x; acc.y += v.y; acc.z += v.z; acc.w += v.w;
            s = sn;
        }
    } else {
        const __nv_bfloat16* hb = shi + (size_t)y * ystride;
        const __nv_bfloat16* lb = slo + (size_t)y * ystride;
        for (int j = o0; j < o1; ++j) {
            int sn = (j + 1 < o1) ? __ldg(g_csr + j + 1) : 0;
            const __nv_bfloat162* ph = (const __nv_bfloat162*)(hb + (size_t)s * FH + lane * 4);
            const __nv_bfloat162* pl = (const __nv_bfloat162*)(lb + (size_t)s * FH + lane * 4);
            float2 a = __bfloat1622float2(ph[0]);
            float2 b = __bfloat1622float2(ph[1]);
            float2 c = __bfloat1622float2(pl[0]);
            float2 d = __bfloat1622float2(pl[1]);
            acc.x += a.x + c.x; acc.y += a.y + c.y; acc.z += b.x + d.x; acc.w += b.y + d.y;
            s = sn;
        }
    }
    float sc = 1.0f / fmaxf((float)(o1 - o0), 1.0f);
    __nv_bfloat16 h0, l0, h1, l1, h2, l2, h3, l3;
    bsplit(acc.x * sc, h0, l0); bsplit(acc.y * sc, h1, l1);
    bsplit(acc.z * sc, h2, l2); bsplit(acc.w * sc, h3, l3);
    size_t o = (size_t)g * FH + lane * 4;
    *(uint2*)(g_agghi + o) = make_uint2(pack_bf16(h0, h1), pack_bf16(h2, h3));
    *(uint2*)(g_agglo + o) = make_uint2(pack_bf16(l0, l1), pack_bf16(l2, l3));
}

// attention softmax over 4 metapaths (hstack in bf16 hi/lo) -> emb bf16 hi/lo; one warp per node
__global__ void attention_kernel(const float* __restrict__ attW, const float* __restrict__ attB) {
    int n = (blockIdx.x * blockDim.x + threadIdx.x) >> 5;
    if (n >= NN) return;
    int lane = threadIdx.x & 31;
    float4 hv[4]; float logit[4];
#pragma unroll
    for (int k = 0; k < 4; ++k) {
        size_t o = ((size_t)k * NN + n) * FH + lane * 4;
        const __nv_bfloat162* ph = (const __nv_bfloat162*)(g_hshi + o);
        const __nv_bfloat162* pl = (const __nv_bfloat162*)(g_hslo + o);
        float2 h01 = __bfloat1622float2(ph[0]);
        float2 h23 = __bfloat1622float2(ph[1]);
        float2 l01 = __bfloat1622float2(pl[0]);
        float2 l23 = __bfloat1622float2(pl[1]);
        float4 h4 = make_float4(h01.x + l01.x, h01.y + l01.y, h23.x + l23.x, h23.y + l23.y);
        float4 w4 = *(const float4*)(attW + k * FH + lane * 4);
        hv[k] = h4;
        float p = h4.x * w4.x + h4.y * w4.y + h4.z * w4.z + h4.w * w4.w;
#pragma unroll
        for (int o2 = 16; o2; o2 >>= 1) p += __shfl_xor_sync(0xffffffffu, p, o2);
        logit[k] = p + attB[k];
    }
    float m = fmaxf(fmaxf(logit[0], logit[1]), fmaxf(logit[2], logit[3]));
    float e[4], s = 0.0f;
#pragma unroll
    for (int k = 0; k < 4; ++k) { e[k] = expf(logit[k] - m); s += e[k]; }
    float is = 1.0f / s;
    float4 o = make_float4(0.f, 0.f, 0.f, 0.f);
#pragma unroll
    for (int k = 0; k < 4; ++k) {
        float w = e[k] * is;
        o.x += w * hv[k].x; o.y += w * hv[k].y; o.z += w * hv[k].z; o.w += w * hv[k].w;
    }
    __nv_bfloat16 h0, l0, h1, l1, h2, l2, h3, l3;
    bsplit(o.x, h0, l0); bsplit(o.y, h1, l1); bsplit(o.z, h2, l2); bsplit(o.w, h3, l3);
    *(uint2*)(g_embhi + (size_t)n * FH + lane * 4) = make_uint2(pack_bf16(h0, h1), pack_bf16(h2, h3));
    *(uint2*)(g_emblo + (size_t)n * FH + lane * 4) = make_uint2(pack_bf16(l0, l1), pack_bf16(l2, l3));
}

// edge scorer: score = sigmoid(sum relu(P[s]+Q[d]+b) * w2 + b2); one warp per edge.
__global__ void edge_score_kernel(const int* __restrict__ src, const int* __restrict__ dst,
                                  const float* __restrict__ l1b, const float* __restrict__ l2w,
                                  const float* __restrict__ l2b,
                                  float* __restrict__ out, int ne) {
    int e = (blockIdx.x * blockDim.x + threadIdx.x) >> 5;
    if (e >= ne) return;
    int lane = threadIdx.x & 31;
    int s = __ldg(src + e), d = __ldg(dst + e);
    float4 p = *(const float4*)(g_pq + (size_t)s * FH + lane * 4);
    float4 q = *(const float4*)(g_pq + (size_t)NN * FH + (size_t)d * FH + lane * 4);
    float4 b = *(const float4*)(l1b + lane * 4);
    float4 w = *(const float4*)(l2w + lane * 4);
    float acc = fmaxf(p.x + q.x + b.x, 0.f) * w.x + fmaxf(p.y + q.y + b.y, 0.f) * w.y
              + fmaxf(p.z + q.z + b.z, 0.f) * w.z + fmaxf(p.w + q.w + b.w, 0.f) * w.w;
#pragma unroll
    for (int o = 16; o; o >>= 1) acc += __shfl_xor_sync(0xffffffffu, acc, o);
    if (lane == 0) out[e] = 1.0f / (1.0f + expf(-(acc + __ldg(l2b))));
}

// ===================== mma.sync GEMM (cp.async staging) =====================
// MODE 0: 2 halves, bias+relu -> bf16 hi/lo.  MODE 1: 2 halves, +bias -> bf16 hi/lo.
// MODE 3: single half (K=128), no bias -> f32.
#define SB_BIAS 0
#define SB_TILES 4096
#define TILE_SZ 16384
#define SMEM_TOTAL (SB_TILES + 4 * TILE_SZ)

__device__ __forceinline__ void stage_tile(uint32_t stile, const __nv_bfloat16* gbase,
                                           int row0, int nrows, int kofs, int tid) {
#pragma unroll
    for (int i = tid; i < 1024; i += 256) {
        int r = i >> 3, j = i & 7;
        int grow = row0 + r;
        bool valid = grow < nrows;
        const __nv_bfloat16* src = gbase + (size_t)(valid ? grow : 0) * FH + kofs + j * 8;
        uint32_t off = (uint32_t)(r * 128 + j * 16);
        cpasync16z(stile + swz(off), src, valid ? 16 : 0);
    }
}

__device__ __forceinline__ void load_a_frag(uint32_t tb, int wm, int ks, int lane, uint32_t* ra) {
    int q = lane >> 3, r = lane & 7;
    int rofs = ((q & 1) ? 8 : 0) + r;
    int kl = ks * 16 + ((q & 2) ? 8 : 0);
#pragma unroll
    for (int mf = 0; mf < 4; ++mf) {
        uint32_t off = (uint32_t)((wm * 64 + mf * 16 + rofs) * 128 + kl * 2);
        ldm_x4(tb + swz(off), ra + mf * 4);
    }
}
__device__ __forceinline__ void load_w_frag(uint32_t tb, int wn, int ks, int lane, uint32_t* rw) {
    int q = lane >> 3, r = lane & 7;
    int rofs = ((q & 2) ? 8 : 0) + r;
    int kl = ks * 16 + ((q & 1) ? 8 : 0);
#pragma unroll
    for (int pf = 0; pf < 2; ++pf) {
        uint32_t off = (uint32_t)((wn * 32 + pf * 16 + rofs) * 128 + kl * 2);
        ldm_x4(tb + swz(off), rw + pf * 4);
    }
}

template <int MODE>
__global__ void __launch_bounds__(256) mp_gemm_kernel(
    const __nv_bfloat16* __restrict__ a0hi, const __nv_bfloat16* __restrict__ a0lo, size_t a0stride,
    const __nv_bfloat16* __restrict__ a1hi, const __nv_bfloat16* __restrict__ a1lo, size_t a1stride,
    int w0mat, int w1mat, int wmatstride,
    const float* __restrict__ bias, int bstride,
    float* __restrict__ outf, size_t outfstride,
    __nv_bfloat16* __restrict__ outhi, __nv_bfloat16* __restrict__ outlo, size_t outbstride,
    int nrows)
{
    extern __shared__ char smem[];
    const uint32_t sb = smem_u32(smem);
    const int tid = threadIdx.x, lane = tid & 31, wid = tid >> 5;
    const int wm = wid & 1, wn = wid >> 1;
    const int y = blockIdx.y;
    const int row0 = blockIdx.x * 128;

    float* sbias = (float*)(smem + SB_BIAS);
    if (tid < 128) sbias[tid] = bias[bstride * y + tid];

    const __nv_bfloat16* ahis[2] = { a0hi + (size_t)y * a0stride, a1hi + (size_t)y * a1stride };
    const __nv_bfloat16* alos[2] = { a0lo + (size_t)y * a0stride, a1lo + (size_t)y * a1stride };
    const int wm0 = w0mat + y * wmatstride, wm1 = w1mat + y * wmatstride;

    const uint32_t tAHI = sb + SB_TILES,               tALO = sb + SB_TILES + TILE_SZ;
    const uint32_t tWHI = sb + SB_TILES + 2 * TILE_SZ, tWLO = sb + SB_TILES + 3 * TILE_SZ;

    float acc[4][4][4];
#pragma unroll
    for (int i = 0; i < 4; ++i)
#pragma unroll
        for (int j = 0; j < 4; ++j)
#pragma unroll
            for (int q = 0; q < 4; ++q) acc[i][j][q] = 0.0f;

    const int CHUNKS = (MODE == 3) ? 2 : 4;
#pragma unroll 1
    for (int c = 0; c < CHUNKS; ++c) {
        const int half = (MODE == 3) ? 0 : (c >> 1), kc = (c & 1) * 64;
        const __nv_bfloat16* whb = g_whi + (size_t)(half ? wm1 : wm0) * 16384;
        const __nv_bfloat16* wlb = g_wlo + (size_t)(half ? wm1 : wm0) * 16384;
        if (c) __syncthreads();
        stage_tile(tAHI, ahis[half], row0, nrows, kc, tid);
        stage_tile(tALO, alos[half], row0, nrows, kc, tid);
        stage_tile(tWHI, whb, 0, 128, kc, tid);
        stage_tile(tWLO, wlb, 0, 128, kc, tid);
        CP_COMMIT();
        CP_WAIT0();
        __syncthreads();

#pragma unroll
        for (int ks = 0; ks < 4; ++ks) {
            uint32_t ra[16], rwh[8], rwl[8];
            load_a_frag(tAHI, wm, ks, lane, ra);
            load_w_frag(tWHI, wn, ks, lane, rwh);
#pragma unroll
            for (int mf = 0; mf < 4; ++mf)
#pragma unroll
                for (int nf = 0; nf < 4; ++nf)
                    mma16816(acc[mf][nf], ra + mf * 4, rwh + nf * 2);
            load_w_frag(tWLO, wn, ks, lane, rwl);
#pragma unroll
            for (int mf = 0; mf < 4; ++mf)
#pragma unroll
                for (int nf = 0; nf < 4; ++nf)
                    mma16816(acc[mf][nf], ra + mf * 4, rwl + nf * 2);
            load_a_frag(tALO, wm, ks, lane, ra);
#pragma unroll
            for (int mf = 0; mf < 4; ++mf)
#pragma unroll
                for (int nf = 0; nf < 4; ++nf)
                    mma16816(acc[mf][nf], ra + mf * 4, rwh + nf * 2);
        }
    }

    // ---------------- epilogue ----------------
    const int rbase = row0 + wm * 64 + (lane >> 2);
    const int cbase = wn * 32 + 2 * (lane & 3);

#pragma unroll
    for (int mf = 0; mf < 4; ++mf) {
        int r0 = rbase + mf * 16, r1 = r0 + 8;
        bool v0 = r0 < nrows, v1 = r1 < nrows;
#pragma unroll
        for (int nf = 0; nf < 4; ++nf) {
            int gc = cbase + nf * 8;
            float b0v = (MODE == 3) ? 0.f : sbias[gc];
            float b1v = (MODE == 3) ? 0.f : sbias[gc + 1];
            float e0 = acc[mf][nf][0] + b0v, e1 = acc[mf][nf][1] + b1v;
            float e2 = acc[mf][nf][2] + b0v, e3 = acc[mf][nf][3] + b1v;
            if (MODE == 3) {
                if (v0) *(float2*)(outf + (size_t)y * outfstride + (size_t)r0 * FH + gc) = make_float2(e0, e1);
                if (v1) *(float2*)(outf + (size_t)y * outfstride + (size_t)r1 * FH + gc) = make_float2(e2, e3);
            } else {
                if (MODE == 0) {
                    e0 = fmaxf(e0, 0.f); e1 = fmaxf(e1, 0.f);
                    e2 = fmaxf(e2, 0.f); e3 = fmaxf(e3, 0.f);
                }
                __nv_bfloat16 h0, l0, h1, l1, h2, l2, h3, l3;
                bsplit(e0, h0, l0); bsplit(e1, h1, l1); bsplit(e2, h2, l2); bsplit(e3, h3, l3);
                if (v0) {
                    *(uint32_t*)(outhi + (size_t)y * outbstride + (size_t)r0 * FH + gc) = pack_bf16(h0, h1);
                    *(uint32_t*)(outlo + (size_t)y * outbstride + (size_t)r0 * FH + gc) = pack_bf16(l0, l1);
                }
                if (v1) {
                    *(uint32_t*)(outhi + (size_t)y * outbstride + (size_t)r1 * FH + gc) = pack_bf16(h2, h3);
                    *(uint32_t*)(outlo + (size_t)y * outbstride + (size_t)r1 * FH + gc) = pack_bf16(l2, l3);
                }
            }
        }
    }
}

// ===================== host =====================
extern "C" void kernel_launch(void* const* d_in, const int* in_sizes, int n_in,
                              void* d_out, int out_size) {
    const float* x    = (const float*)d_in[0];
    const float* Ws1  = (const float*)d_in[1];
    const float* b1   = (const float*)d_in[2];
    const float* Wn1  = (const float*)d_in[3];
    const float* Ws2  = (const float*)d_in[4];
    const float* b2   = (const float*)d_in[5];
    const float* Wn2  = (const float*)d_in[6];
    const float* attW = (const float*)d_in[7];
    const float* attB = (const float*)d_in[8];
    const float* l1W  = (const float*)d_in[9];
    const float* l1b  = (const float*)d_in[10];
    const float* l2W  = (const float*)d_in[11];
    const float* l2b  = (const float*)d_in[12];
    const int* srcs[4] = {(const int*)d_in[13], (const int*)d_in[15],
                          (const int*)d_in[17], (const int*)d_in[19]};
    const int* dsts[4] = {(const int*)d_in[14], (const int*)d_in[16],
                          (const int*)d_in[18], (const int*)d_in[20]};
    const int* ssim = (const int*)d_in[21];
    const int* dsim = (const int*)d_in[22];
    const int  esim = in_sizes[21];

    void *degiP, *curP, *pqP, *xhiP, *xloP, *agghiP, *aggloP, *h1hiP, *h1loP,
         *hshiP, *hsloP, *embhiP, *embloP;
    cudaGetSymbolAddress(&degiP, g_degi);
    cudaGetSymbolAddress(&curP, g_cur);
    cudaGetSymbolAddress(&pqP, g_pq);
    cudaGetSymbolAddress(&xhiP, g_xhi);     cudaGetSymbolAddress(&xloP, g_xlo);
    cudaGetSymbolAddress(&agghiP, g_agghi); cudaGetSymbolAddress(&aggloP, g_agglo);
    cudaGetSymbolAddress(&h1hiP, g_h1hi);   cudaGetSymbolAddress(&h1loP, g_h1lo);
    cudaGetSymbolAddress(&hshiP, g_hshi);   cudaGetSymbolAddress(&hsloP, g_hslo);
    cudaGetSymbolAddress(&embhiP, g_embhi); cudaGetSymbolAddress(&embloP, g_emblo);

    cudaFuncSetAttribute(mp_gemm_kernel<0>, cudaFuncAttributeMaxDynamicSharedMemorySize, SMEM_TOTAL);
    cudaFuncSetAttribute(mp_gemm_kernel<1>, cudaFuncAttributeMaxDynamicSharedMemorySize, SMEM_TOTAL);
    cudaFuncSetAttribute(mp_gemm_kernel<3>, cudaFuncAttributeMaxDynamicSharedMemorySize, SMEM_TOTAL);

    EdgeArgs ea;
    ea.off[0] = 0;
    for (int k = 0; k < 4; ++k) {
        ea.src[k] = srcs[k]; ea.dst[k] = dsts[k];
        ea.off[k + 1] = ea.off[k] + in_sizes[13 + 2 * k];
    }
    const int total_e = ea.off[4];

    const int NB = (NN + 127) / 128;
    const size_t NF = (size_t)NN * FH;
    const int NG = (int)(((size_t)NTOT * 32 + 255) / 256);

    // 0. weight + x splits
    split_weights_kernel<<<(18 * 16384 + 255) / 256, 256>>>(Ws1, Wn1, Ws2, Wn2, l1W);
    split_x_kernel<<<(NN * FH + 255) / 256, 256>>>(x);

    // 1. CSR build (shared by both layers); parallel 3-phase scan
    cudaMemsetAsync(degiP, 0, NTOT * sizeof(int));
    cudaMemsetAsync(curP, 0, NTOT * sizeof(int));
    degcount_kernel<<<(total_e + 255) / 256, 256>>>(ea);
    scan1_kernel<<<SCAN_B, 1024>>>();
    scan2_kernel<<<1, 256>>>();
    scan3_kernel<<<SCAN_B, 1024>>>();
    fill_kernel<<<(total_e + 255) / 256, 256>>>(ea);

    // 2. layer-1 aggregation: gather mean of x over in-neighbors -> agg bf16 hi/lo
    gather_kernel<<<NG, 256>>>(x, nullptr, nullptr, 0);

    // 3. layer-1 GEMM: h1 = relu(x@Ws1 + aggn@Wn1 + b1) -> bf16 hi/lo
    mp_gemm_kernel<0><<<dim3(NB, 4), 256, SMEM_TOTAL>>>(
        (const __nv_bfloat16*)xhiP, (const __nv_bfloat16*)xloP, 0,
        (const __nv_bfloat16*)agghiP, (const __nv_bfloat16*)aggloP, NF,
        0, 4, 1, b1, FH,
        nullptr, 0, (__nv_bfloat16*)h1hiP, (__nv_bfloat16*)h1loP, NF, NN);

    // 4. layer-2 aggregation: gather mean of h1 over in-neighbors
    gather_kernel<<<NG, 256>>>(nullptr, (const __nv_bfloat16*)h1hiP,
                               (const __nv_bfloat16*)h1loP, NF);

    // 5. layer-2 GEMM -> hstack bf16 hi/lo
    mp_gemm_kernel<1><<<dim3(NB, 4), 256, SMEM_TOTAL>>>(
        (const __nv_bfloat16*)h1hiP, (const __nv_bfloat16*)h1loP, NF,
        (const __nv_bfloat16*)agghiP, (const __nv_bfloat16*)aggloP, NF,
        8, 12, 1, b2, FH,
        nullptr, 0, (__nv_bfloat16*)hshiP, (__nv_bfloat16*)hsloP, NF, NN);

    // 6. attention -> emb bf16 hi/lo
    attention_kernel<<<(NN * 32 + 255) / 256, 256>>>(attW, attB);

    // 7. P/Q GEMM: P = emb@W1a (y=0), Q = emb@W1b (y=1); no bias
    mp_gemm_kernel<3><<<dim3(NB, 2), 256, SMEM_TOTAL>>>(
        (const __nv_bfloat16*)embhiP, (const __nv_bfloat16*)embloP, 0,
        (const __nv_bfloat16*)embhiP, (const __nv_bfloat16*)embloP, 0,
        16, 16, 1, l1b, 0,
        (float*)pqP, NF, nullptr, nullptr, 0, NN);

    // 8. edge scorer: relu(P[s]+Q[d]+b) . w2 -> sigmoid
    edge_score_kernel<<<(int)(((size_t)esim * 32 + 255) / 256), 256>>>(
        ssim, dsim, l1b, l2W, l2b, (float*)d_out, esim);
}

// round 13
// speedup vs baseline: 4.6783x; 1.2159x over previous
#include <cuda_runtime.h>
#include <cuda_bf16.h>
#include <math.h>
#include <stdint.h>

#define NN   50000
#define FH   128
#define NTOT (4 * NN)
#define CSRMAX 2200000
#define SCAN_B ((NTOT + 1023) / 1024)

// ===================== scratch (static device globals) =====================
__device__ int           g_degi[NTOT];
__device__ int           g_offs[NTOT + 1];
__device__ int           g_cur[NTOT];
__device__ int           g_part[SCAN_B];
__device__ int           g_csr[CSRMAX];
__device__ float         g_pq[(size_t)2 * NN * FH];          // P = emb@W1a, Q = emb@W1b
__device__ __nv_bfloat16 g_xhi[(size_t)NN * FH],       g_xlo[(size_t)NN * FH];
__device__ __nv_bfloat16 g_agghi[(size_t)4 * NN * FH], g_agglo[(size_t)4 * NN * FH];
__device__ __nv_bfloat16 g_h1hi[(size_t)4 * NN * FH],  g_h1lo[(size_t)4 * NN * FH];
__device__ __nv_bfloat16 g_hshi[(size_t)4 * NN * FH],  g_hslo[(size_t)4 * NN * FH];
__device__ __nv_bfloat16 g_embhi[(size_t)NN * FH],     g_emblo[(size_t)NN * FH];
__device__ __nv_bfloat16 g_whi[18 * 16384];   // [mat][n][k] (hi only; 2-term GEMM)

__device__ __forceinline__ void bsplit(float v, __nv_bfloat16& h, __nv_bfloat16& l) {
    h = __float2bfloat16(v);
    l = __float2bfloat16(v - __bfloat162float(h));
}
__device__ __forceinline__ uint32_t pack_bf16(__nv_bfloat16 a, __nv_bfloat16 b) {
    return (uint32_t)__bfloat16_as_ushort(a) | ((uint32_t)__bfloat16_as_ushort(b) << 16);
}
__device__ __forceinline__ uint32_t smem_u32(const void* p) {
    uint32_t a;
    asm("{ .reg .u64 t; cvta.to.shared.u64 t, %1; cvt.u32.u64 %0, t; }" : "=r"(a) : "l"(p));
    return a;
}
__device__ __forceinline__ uint32_t swz(uint32_t off) { return off ^ ((off >> 3) & 0x70); }

__device__ __forceinline__ void ldm_x4(uint32_t addr, uint32_t* r) {
    asm volatile("ldmatrix.sync.aligned.m8n8.x4.shared.b16 {%0,%1,%2,%3}, [%4];"
                 : "=r"(r[0]), "=r"(r[1]), "=r"(r[2]), "=r"(r[3]) : "r"(addr));
}
__device__ __forceinline__ void mma16816(float* c, const uint32_t* a, const uint32_t* b) {
    asm volatile("mma.sync.aligned.m16n8k16.row.col.f32.bf16.bf16.f32 "
        "{%0,%1,%2,%3}, {%4,%5,%6,%7}, {%8,%9}, {%0,%1,%2,%3};"
        : "+f"(c[0]), "+f"(c[1]), "+f"(c[2]), "+f"(c[3])
        : "r"(a[0]), "r"(a[1]), "r"(a[2]), "r"(a[3]), "r"(b[0]), "r"(b[1]));
}
__device__ __forceinline__ void cpasync16z(uint32_t dst, const void* src, int src_bytes) {
    asm volatile("cp.async.ca.shared.global [%0], [%1], 16, %2;"
                 :: "r"(dst), "l"(__cvta_generic_to_global(src)), "r"(src_bytes) : "memory");
}
#define CP_COMMIT() asm volatile("cp.async.commit_group;" ::: "memory")
#define CP_WAIT0()  asm volatile("cp.async.wait_group 0;" ::: "memory")

// ===================== small kernels =====================
__global__ void split_weights_kernel(const float* __restrict__ Ws1, const float* __restrict__ Wn1,
                                     const float* __restrict__ Ws2, const float* __restrict__ Wn2,
                                     const float* __restrict__ L1) {
    int g = blockIdx.x * blockDim.x + threadIdx.x;
    if (g >= 18 * 16384) return;
    int m = g >> 14, r = g & 16383, n = r >> 7, k = r & 127;
    const float* s;
    if (m < 4)       s = Ws1 + (size_t)m * 16384;
    else if (m < 8)  s = Wn1 + (size_t)(m - 4) * 16384;
    else if (m < 12) s = Ws2 + (size_t)(m - 8) * 16384;
    else if (m < 16) s = Wn2 + (size_t)(m - 12) * 16384;
    else             s = L1  + (size_t)(m - 16) * 16384;
    // transpose [k][n] -> [n][k]; hi only (2-term GEMM uses exact A, truncated W)
    g_whi[(size_t)m * 16384 + n * 128 + k] = __float2bfloat16(s[k * 128 + n]);
}

// split f32 rows -> bf16 hi/lo (x only)
__global__ void split_x_kernel(const float* __restrict__ src) {
    int i = blockIdx.x * blockDim.x + threadIdx.x;
    if (i >= NN * FH) return;
    __nv_bfloat16 h, l; bsplit(src[i], h, l);
    g_xhi[i] = h; g_xlo[i] = l;
}

struct EdgeArgs {
    const int* src[4]; const int* dst[4];
    int off[5];
};

// ---------- CSR build (once per launch; shared by both layers) ----------
__global__ void degcount_kernel(EdgeArgs a) {
    int w = blockIdx.x * blockDim.x + threadIdx.x;
    if (w >= a.off[4]) return;
    int y = (w >= a.off[1]) + (w >= a.off[2]) + (w >= a.off[3]);
    atomicAdd(&g_degi[y * NN + __ldg(a.dst[y] + (w - a.off[y]))], 1);
}

__global__ void scan1_kernel() {
    __shared__ int sh[1024];
    int t = threadIdx.x;
    int i = blockIdx.x * 1024 + t;
    int v = (i < NTOT) ? g_degi[i] : 0;
    sh[t] = v;
    __syncthreads();
#pragma unroll
    for (int o = 1; o < 1024; o <<= 1) {
        int add = (t >= o) ? sh[t - o] : 0;
        __syncthreads();
        sh[t] += add;
        __syncthreads();
    }
    if (i < NTOT) g_offs[i] = sh[t] - v;
    if (t == 1023) g_part[blockIdx.x] = sh[1023];
}

__global__ void scan2_kernel() {
    __shared__ int sh[256];
    int t = threadIdx.x;
    int v = (t < SCAN_B) ? g_part[t] : 0;
    sh[t] = v;
    __syncthreads();
#pragma unroll
    for (int o = 1; o < 256; o <<= 1) {
        int add = (t >= o) ? sh[t - o] : 0;
        __syncthreads();
        sh[t] += add;
        __syncthreads();
    }
    if (t < SCAN_B) g_part[t] = sh[t] - v;
    if (t == 255) g_offs[NTOT] = sh[255];
}

__global__ void scan3_kernel() {
    int i = blockIdx.x * 1024 + threadIdx.x;
    if (i < NTOT) g_offs[i] += g_part[blockIdx.x];
}

__global__ void fill_kernel(EdgeArgs a) {
    int w = blockIdx.x * blockDim.x + threadIdx.x;
    if (w >= a.off[4]) return;
    int y = (w >= a.off[1]) + (w >= a.off[2]) + (w >= a.off[3]);
    int e = w - a.off[y];
    int s = __ldg(a.src[y] + e), d = __ldg(a.dst[y] + e);
    int node = y * NN + d;
    int pos = g_offs[node] + atomicAdd(&g_cur[node], 1);
    g_csr[pos] = s;
}

// ---------- CSR gather aggregation: one warp per (metapath,node), 2-edge ILP ----------
__global__ void gather_kernel(const float* __restrict__ f32src,
                              const __nv_bfloat16* __restrict__ shi,
                              const __nv_bfloat16* __restrict__ slo, size_t ystride) {
    int g = (blockIdx.x * blockDim.x + threadIdx.x) >> 5;
    if (g >= NTOT) return;
    int lane = threadIdx.x & 31;
    int y = g / NN;
    int o0 = __ldg(g_offs + g), o1 = __ldg(g_offs + g + 1);
    float4 acc0 = make_float4(0.f, 0.f, 0.f, 0.f);
    float4 acc1 = make_float4(0.f, 0.f, 0.f, 0.f);
    int j = o0;
    if (f32src) {
        for (; j + 1 < o1; j += 2) {
            int s0 = __ldg(g_csr + j), s1 = __ldg(g_csr + j + 1);
            float4 v0 = __ldg((const float4*)(f32src + (size_t)s0 * FH) + lane);
            float4 v1 = __ldg((const float4*)(f32src + (size_t)s1 * FH) + lane);
            acc0.x += v0.x; acc0.y += v0.y; acc0.z += v0.z; acc0.w += v0.w;
            acc1.x += v1.x; acc1.y += v1.y; acc1.z += v1.z; acc1.w += v1.w;
        }
        if (j < o1) {
            int s0 = __ldg(g_csr + j);
            float4 v0 = __ldg((const float4*)(f32src + (size_t)s0 * FH) + lane);
            acc0.x += v0.x; acc0.y += v0.y; acc0.z += v0.z; acc0.w += v0.w;
        }
    } else {
        const __nv_bfloat16* hb = shi + (size_t)y * ystride;
        const __nv_bfloat16* lb = slo + (size_t)y * ystride;
        for (; j + 1 < o1; j += 2) {
            int s0 = __ldg(g_csr + j), s1 = __ldg(g_csr + j + 1);
            uint2 h0 = __ldg((const uint2*)(hb + (size_t)s0 * FH) + lane);
            uint2 l0 = __ldg((const uint2*)(lb + (size_t)s0 * FH) + lane);
            uint2 h1 = __ldg((const uint2*)(hb + (size_t)s1 * FH) + lane);
            uint2 l1 = __ldg((const uint2*)(lb + (size_t)s1 * FH) + lane);
            float2 a0 = __bfloat1622float2(*(__nv_bfloat162*)&h0.x);
            float2 b0 = __bfloat1622float2(*(__nv_bfloat162*)&h0.y);
            float2 c0 = __bfloat1622float2(*(__nv_bfloat162*)&l0.x);
            float2 d0 = __bfloat1622float2(*(__nv_bfloat162*)&l0.y);
            float2 a1 = __bfloat1622float2(*(__nv_bfloat162*)&h1.x);
            float2 b1 = __bfloat1622float2(*(__nv_bfloat162*)&h1.y);
            float2 c1 = __bfloat1622float2(*(__nv_bfloat162*)&l1.x);
            float2 d1 = __bfloat1622float2(*(__nv_bfloat162*)&l1.y);
            acc0.x += a0.x + c0.x; acc0.y += a0.y + c0.y; acc0.z += b0.x + d0.x; acc0.w += b0.y + d0.y;
            acc1.x += a1.x + c1.x; acc1.y += a1.y + c1.y; acc1.z += b1.x + d1.x; acc1.w += b1.y + d1.y;
        }
        if (j < o1) {
            int s0 = __ldg(g_csr + j);
            uint2 h0 = __ldg((const uint2*)(hb + (size_t)s0 * FH) + lane);
            uint2 l0 = __ldg((const uint2*)(lb + (size_t)s0 * FH) + lane);
            float2 a0 = __bfloat1622float2(*(__nv_bfloat162*)&h0.x);
            float2 b0 = __bfloat1622float2(*(__nv_bfloat162*)&h0.y);
            float2 c0 = __bfloat1622float2(*(__nv_bfloat162*)&l0.x);
            float2 d0 = __bfloat1622float2(*(__nv_bfloat162*)&l0.y);
            acc0.x += a0.x + c0.x; acc0.y += a0.y + c0.y; acc0.z += b0.x + d0.x; acc0.w += b0.y + d0.y;
        }
    }
    float4 acc = make_float4(acc0.x + acc1.x, acc0.y + acc1.y, acc0.z + acc1.z, acc0.w + acc1.w);
    float sc = 1.0f / fmaxf((float)(o1 - o0), 1.0f);
    __nv_bfloat16 h0, l0, h1, l1, h2, l2, h3, l3;
    bsplit(acc.x * sc, h0, l0); bsplit(acc.y * sc, h1, l1);
    bsplit(acc.z * sc, h2, l2); bsplit(acc.w * sc, h3, l3);
    size_t o = (size_t)g * FH + lane * 4;
    *(uint2*)(g_agghi + o) = make_uint2(pack_bf16(h0, h1), pack_bf16(h2, h3));
    *(uint2*)(g_agglo + o) = make_uint2(pack_bf16(l0, l1), pack_bf16(l2, l3));
}

// attention softmax over 4 metapaths (hstack bf16 hi/lo) -> emb bf16 hi/lo; one warp per node
__global__ void attention_kernel(const float* __restrict__ attW, const float* __restrict__ attB) {
    int n = (blockIdx.x * blockDim.x + threadIdx.x) >> 5;
    if (n >= NN) return;
    int lane = threadIdx.x & 31;
    float4 hv[4]; float logit[4];
#pragma unroll
    for (int k = 0; k < 4; ++k) {
        size_t o = ((size_t)k * NN + n) * FH + lane * 4;
        const __nv_bfloat162* ph = (const __nv_bfloat162*)(g_hshi + o);
        const __nv_bfloat162* pl = (const __nv_bfloat162*)(g_hslo + o);
        float2 h01 = __bfloat1622float2(ph[0]);
        float2 h23 = __bfloat1622float2(ph[1]);
        float2 l01 = __bfloat1622float2(pl[0]);
        float2 l23 = __bfloat1622float2(pl[1]);
        float4 h4 = make_float4(h01.x + l01.x, h01.y + l01.y, h23.x + l23.x, h23.y + l23.y);
        float4 w4 = *(const float4*)(attW + k * FH + lane * 4);
        hv[k] = h4;
        float p = h4.x * w4.x + h4.y * w4.y + h4.z * w4.z + h4.w * w4.w;
#pragma unroll
        for (int o2 = 16; o2; o2 >>= 1) p += __shfl_xor_sync(0xffffffffu, p, o2);
        logit[k] = p + attB[k];
    }
    float m = fmaxf(fmaxf(logit[0], logit[1]), fmaxf(logit[2], logit[3]));
    float e[4], s = 0.0f;
#pragma unroll
    for (int k = 0; k < 4; ++k) { e[k] = expf(logit[k] - m); s += e[k]; }
    float is = 1.0f / s;
    float4 o = make_float4(0.f, 0.f, 0.f, 0.f);
#pragma unroll
    for (int k = 0; k < 4; ++k) {
        float w = e[k] * is;
        o.x += w * hv[k].x; o.y += w * hv[k].y; o.z += w * hv[k].z; o.w += w * hv[k].w;
    }
    __nv_bfloat16 h0, l0, h1, l1, h2, l2, h3, l3;
    bsplit(o.x, h0, l0); bsplit(o.y, h1, l1); bsplit(o.z, h2, l2); bsplit(o.w, h3, l3);
    *(uint2*)(g_embhi + (size_t)n * FH + lane * 4) = make_uint2(pack_bf16(h0, h1), pack_bf16(h2, h3));
    *(uint2*)(g_emblo + (size_t)n * FH + lane * 4) = make_uint2(pack_bf16(l0, l1), pack_bf16(l2, l3));
}

// edge scorer: score = sigmoid(sum relu(P[s]+Q[d]+b) * w2 + b2); one warp per edge.
__global__ void edge_score_kernel(const int* __restrict__ src, const int* __restrict__ dst,
                                  const float* __restrict__ l1b, const float* __restrict__ l2w,
                                  const float* __restrict__ l2b,
                                  float* __restrict__ out, int ne) {
    int e = (blockIdx.x * blockDim.x + threadIdx.x) >> 5;
    if (e >= ne) return;
    int lane = threadIdx.x & 31;
    int s = __ldg(src + e), d = __ldg(dst + e);
    float4 p = *(const float4*)(g_pq + (size_t)s * FH + lane * 4);
    float4 q = *(const float4*)(g_pq + (size_t)NN * FH + (size_t)d * FH + lane * 4);
    float4 b = *(const float4*)(l1b + lane * 4);
    float4 w = *(const float4*)(l2w + lane * 4);
    float acc = fmaxf(p.x + q.x + b.x, 0.f) * w.x + fmaxf(p.y + q.y + b.y, 0.f) * w.y
              + fmaxf(p.z + q.z + b.z, 0.f) * w.z + fmaxf(p.w + q.w + b.w, 0.f) * w.w;
#pragma unroll
    for (int o = 16; o; o >>= 1) acc += __shfl_xor_sync(0xffffffffu, acc, o);
    if (lane == 0) out[e] = 1.0f / (1.0f + expf(-(acc + __ldg(l2b))));
}

// ===================== mma.sync GEMM: 2-term (A exact, W hi-only) =====================
// D = (Ahi + Alo) @ Whi; error = A @ Wlo ~ 2^-9 relative, sigmoid-compressed downstream.
// MODE 0: 2 halves, bias+relu -> bf16 hi/lo.  MODE 1: 2 halves, +bias -> bf16 hi/lo.
// MODE 3: single half (K=128), no bias -> f32.
#define SB_BIAS 0
#define SB_TILES 4096
#define TILE_SZ 16384
#define SMEM_TOTAL (SB_TILES + 3 * TILE_SZ)

__device__ __forceinline__ void stage_tile(uint32_t stile, const __nv_bfloat16* gbase,
                                           int row0, int nrows, int kofs, int tid) {
#pragma unroll
    for (int i = tid; i < 1024; i += 256) {
        int r = i >> 3, j = i & 7;
        int grow = row0 + r;
        bool valid = grow < nrows;
        const __nv_bfloat16* src = gbase + (size_t)(valid ? grow : 0) * FH + kofs + j * 8;
        uint32_t off = (uint32_t)(r * 128 + j * 16);
        cpasync16z(stile + swz(off), src, valid ? 16 : 0);
    }
}

__device__ __forceinline__ void load_a_frag(uint32_t tb, int wm, int ks, int lane, uint32_t* ra) {
    int q = lane >> 3, r = lane & 7;
    int rofs = ((q & 1) ? 8 : 0) + r;
    int kl = ks * 16 + ((q & 2) ? 8 : 0);
#pragma unroll
    for (int mf = 0; mf < 4; ++mf) {
        uint32_t off = (uint32_t)((wm * 64 + mf * 16 + rofs) * 128 + kl * 2);
        ldm_x4(tb + swz(off), ra + mf * 4);
    }
}
__device__ __forceinline__ void load_w_frag(uint32_t tb, int wn, int ks, int lane, uint32_t* rw) {
    int q = lane >> 3, r = lane & 7;
    int rofs = ((q & 2) ? 8 : 0) + r;
    int kl = ks * 16 + ((q & 1) ? 8 : 0);
#pragma unroll
    for (int pf = 0; pf < 2; ++pf) {
        uint32_t off = (uint32_t)((wn * 32 + pf * 16 + rofs) * 128 + kl * 2);
        ldm_x4(tb + swz(off), rw + pf * 4);
    }
}

template <int MODE>
__global__ void __launch_bounds__(256) mp_gemm_kernel(
    const __nv_bfloat16* __restrict__ a0hi, const __nv_bfloat16* __restrict__ a0lo, size_t a0stride,
    const __nv_bfloat16* __restrict__ a1hi, const __nv_bfloat16* __restrict__ a1lo, size_t a1stride,
    int w0mat, int w1mat, int wmatstride,
    const float* __restrict__ bias, int bstride,
    float* __restrict__ outf, size_t outfstride,
    __nv_bfloat16* __restrict__ outhi, __nv_bfloat16* __restrict__ outlo, size_t outbstride,
    int nrows)
{
    extern __shared__ char smem[];
    const uint32_t sb = smem_u32(smem);
    const int tid = threadIdx.x, lane = tid & 31, wid = tid >> 5;
    const int wm = wid & 1, wn = wid >> 1;
    const int y = blockIdx.y;
    const int row0 = blockIdx.x * 128;

    float* sbias = (float*)(smem + SB_BIAS);
    if (tid < 128) sbias[tid] = bias[bstride * y + tid];

    const __nv_bfloat16* ahis[2] = { a0hi + (size_t)y * a0stride, a1hi + (size_t)y * a1stride };
    const __nv_bfloat16* alos[2] = { a0lo + (size_t)y * a0stride, a1lo + (size_t)y * a1stride };
    const int wm0 = w0mat + y * wmatstride, wm1 = w1mat + y * wmatstride;

    const uint32_t tAHI = sb + SB_TILES;
    const uint32_t tALO = sb + SB_TILES + TILE_SZ;
    const uint32_t tWHI = sb + SB_TILES + 2 * TILE_SZ;

    float acc[4][4][4];
#pragma unroll
    for (int i = 0; i < 4; ++i)
#pragma unroll
        for (int j = 0; j < 4; ++j)
#pragma unroll
            for (int q = 0; q < 4; ++q) acc[i][j][q] = 0.0f;

    const int CHUNKS = (MODE == 3) ? 2 : 4;
#pragma unroll 1
    for (int c = 0; c < CHUNKS; ++c) {
        const int half = (MODE == 3) ? 0 : (c >> 1), kc = (c & 1) * 64;
        const __nv_bfloat16* whb = g_whi + (size_t)(half ? wm1 : wm0) * 16384;
        if (c) __syncthreads();
        stage_tile(tAHI, ahis[half], row0, nrows, kc, tid);
        stage_tile(tALO, alos[half], row0, nrows, kc, tid);
        stage_tile(tWHI, whb, 0, 128, kc, tid);
        CP_COMMIT();
        CP_WAIT0();
        __syncthreads();

#pragma unroll
        for (int ks = 0; ks < 4; ++ks) {
            uint32_t ra[16], rwh[8];
            load_a_frag(tAHI, wm, ks, lane, ra);
            load_w_frag(tWHI, wn, ks, lane, rwh);
#pragma unroll
            for (int mf = 0; mf < 4; ++mf)
#pragma unroll
                for (int nf = 0; nf < 4; ++nf)
                    mma16816(acc[mf][nf], ra + mf * 4, rwh + nf * 2);
            load_a_frag(tALO, wm, ks, lane, ra);
#pragma unroll
            for (int mf = 0; mf < 4; ++mf)
#pragma unroll
                for (int nf = 0; nf < 4; ++nf)
                    mma16816(acc[mf][nf], ra + mf * 4, rwh + nf * 2);
        }
    }

    // ---------------- epilogue ----------------
    const int rbase = row0 + wm * 64 + (lane >> 2);
    const int cbase = wn * 32 + 2 * (lane & 3);

#pragma unroll
    for (int mf = 0; mf < 4; ++mf) {
        int r0 = rbase + mf * 16, r1 = r0 + 8;
        bool v0 = r0 < nrows, v1 = r1 < nrows;
#pragma unroll
        for (int nf = 0; nf < 4; ++nf) {
            int gc = cbase + nf * 8;
            float b0v = (MODE == 3) ? 0.f : sbias[gc];
            float b1v = (MODE == 3) ? 0.f : sbias[gc + 1];
            float e0 = acc[mf][nf][0] + b0v, e1 = acc[mf][nf][1] + b1v;
            float e2 = acc[mf][nf][2] + b0v, e3 = acc[mf][nf][3] + b1v;
            if (MODE == 3) {
                if (v0) *(float2*)(outf + (size_t)y * outfstride + (size_t)r0 * FH + gc) = make_float2(e0, e1);
                if (v1) *(float2*)(outf + (size_t)y * outfstride + (size_t)r1 * FH + gc) = make_float2(e2, e3);
            } else {
                if (MODE == 0) {
                    e0 = fmaxf(e0, 0.f); e1 = fmaxf(e1, 0.f);
                    e2 = fmaxf(e2, 0.f); e3 = fmaxf(e3, 0.f);
                }
                __nv_bfloat16 h0, l0, h1, l1, h2, l2, h3, l3;
                bsplit(e0, h0, l0); bsplit(e1, h1, l1); bsplit(e2, h2, l2); bsplit(e3, h3, l3);
                if (v0) {
                    *(uint32_t*)(outhi + (size_t)y * outbstride + (size_t)r0 * FH + gc) = pack_bf16(h0, h1);
                    *(uint32_t*)(outlo + (size_t)y * outbstride + (size_t)r0 * FH + gc) = pack_bf16(l0, l1);
                }
                if (v1) {
                    *(uint32_t*)(outhi + (size_t)y * outbstride + (size_t)r1 * FH + gc) = pack_bf16(h2, h3);
                    *(uint32_t*)(outlo + (size_t)y * outbstride + (size_t)r1 * FH + gc) = pack_bf16(l2, l3);
                }
            }
        }
    }
}

// ===================== host =====================
extern "C" void kernel_launch(void* const* d_in, const int* in_sizes, int n_in,
                              void* d_out, int out_size) {
    const float* x    = (const float*)d_in[0];
    const float* Ws1  = (const float*)d_in[1];
    const float* b1   = (const float*)d_in[2];
    const float* Wn1  = (const float*)d_in[3];
    const float* Ws2  = (const float*)d_in[4];
    const float* b2   = (const float*)d_in[5];
    const float* Wn2  = (const float*)d_in[6];
    const float* attW = (const float*)d_in[7];
    const float* attB = (const float*)d_in[8];
    const float* l1W  = (const float*)d_in[9];
    const float* l1b  = (const float*)d_in[10];
    const float* l2W  = (const float*)d_in[11];
    const float* l2b  = (const float*)d_in[12];
    const int* srcs[4] = {(const int*)d_in[13], (const int*)d_in[15],
                          (const int*)d_in[17], (const int*)d_in[19]};
    const int* dsts[4] = {(const int*)d_in[14], (const int*)d_in[16],
                          (const int*)d_in[18], (const int*)d_in[20]};
    const int* ssim = (const int*)d_in[21];
    const int* dsim = (const int*)d_in[22];
    const int  esim = in_sizes[21];

    void *degiP, *curP, *pqP, *xhiP, *xloP, *agghiP, *aggloP, *h1hiP, *h1loP,
         *hshiP, *hsloP, *embhiP, *embloP;
    cudaGetSymbolAddress(&degiP, g_degi);
    cudaGetSymbolAddress(&curP, g_cur);
    cudaGetSymbolAddress(&pqP, g_pq);
    cudaGetSymbolAddress(&xhiP, g_xhi);     cudaGetSymbolAddress(&xloP, g_xlo);
    cudaGetSymbolAddress(&agghiP, g_agghi); cudaGetSymbolAddress(&aggloP, g_agglo);
    cudaGetSymbolAddress(&h1hiP, g_h1hi);   cudaGetSymbolAddress(&h1loP, g_h1lo);
    cudaGetSymbolAddress(&hshiP, g_hshi);   cudaGetSymbolAddress(&hsloP, g_hslo);
    cudaGetSymbolAddress(&embhiP, g_embhi); cudaGetSymbolAddress(&embloP, g_emblo);

    cudaFuncSetAttribute(mp_gemm_kernel<0>, cudaFuncAttributeMaxDynamicSharedMemorySize, SMEM_TOTAL);
    cudaFuncSetAttribute(mp_gemm_kernel<1>, cudaFuncAttributeMaxDynamicSharedMemorySize, SMEM_TOTAL);
    cudaFuncSetAttribute(mp_gemm_kernel<3>, cudaFuncAttributeMaxDynamicSharedMemorySize, SMEM_TOTAL);

    EdgeArgs ea;
    ea.off[0] = 0;
    for (int k = 0; k < 4; ++k) {
        ea.src[k] = srcs[k]; ea.dst[k] = dsts[k];
        ea.off[k + 1] = ea.off[k] + in_sizes[13 + 2 * k];
    }
    const int total_e = ea.off[4];

    const int NB = (NN + 127) / 128;
    const size_t NF = (size_t)NN * FH;
    const int NG = (int)(((size_t)NTOT * 32 + 255) / 256);

    // 0. weight + x splits
    split_weights_kernel<<<(18 * 16384 + 255) / 256, 256>>>(Ws1, Wn1, Ws2, Wn2, l1W);
    split_x_kernel<<<(NN * FH + 255) / 256, 256>>>(x);

    // 1. CSR build (shared by both layers)
    cudaMemsetAsync(degiP, 0, NTOT * sizeof(int));
    cudaMemsetAsync(curP, 0, NTOT * sizeof(int));
    degcount_kernel<<<(total_e + 255) / 256, 256>>>(ea);
    scan1_kernel<<<SCAN_B, 1024>>>();
    scan2_kernel<<<1, 256>>>();
    scan3_kernel<<<SCAN_B, 1024>>>();
    fill_kernel<<<(total_e + 255) / 256, 256>>>(ea);

    // 2. layer-1 aggregation: gather mean of x over in-neighbors -> agg bf16 hi/lo
    gather_kernel<<<NG, 256>>>(x, nullptr, nullptr, 0);

    // 3. layer-1 GEMM: h1 = relu(x@Ws1 + aggn@Wn1 + b1) -> bf16 hi/lo
    mp_gemm_kernel<0><<<dim3(NB, 4), 256, SMEM_TOTAL>>>(
        (const __nv_bfloat16*)xhiP, (const __nv_bfloat16*)xloP, 0,
        (const __nv_bfloat16*)agghiP, (const __nv_bfloat16*)aggloP, NF,
        0, 4, 1, b1, FH,
        nullptr, 0, (__nv_bfloat16*)h1hiP, (__nv_bfloat16*)h1loP, NF, NN);

    // 4. layer-2 aggregation: gather mean of h1 over in-neighbors
    gather_kernel<<<NG, 256>>>(nullptr, (const __nv_bfloat16*)h1hiP,
                               (const __nv_bfloat16*)h1loP, NF);

    // 5. layer-2 GEMM -> hstack bf16 hi/lo
    mp_gemm_kernel<1><<<dim3(NB, 4), 256, SMEM_TOTAL>>>(
        (const __nv_bfloat16*)h1hiP, (const __nv_bfloat16*)h1loP, NF,
        (const __nv_bfloat16*)agghiP, (const __nv_bfloat16*)aggloP, NF,
        8, 12, 1, b2, FH,
        nullptr, 0, (__nv_bfloat16*)hshiP, (__nv_bfloat16*)hsloP, NF, NN);

    // 6. attention -> emb bf16 hi/lo
    attention_kernel<<<(NN * 32 + 255) / 256, 256>>>(attW, attB);

    // 7. P/Q GEMM: P = emb@W1a (y=0), Q = emb@W1b (y=1); no bias
    mp_gemm_kernel<3><<<dim3(NB, 2), 256, SMEM_TOTAL>>>(
        (const __nv_bfloat16*)embhiP, (const __nv_bfloat16*)embloP, 0,
        (const __nv_bfloat16*)embhiP, (const __nv_bfloat16*)embloP, 0,
        16, 16, 1, l1b, 0,
        (float*)pqP, NF, nullptr, nullptr, 0, NN);

    // 8. edge scorer: relu(P[s]+Q[d]+b) . w2 -> sigmoid
    edge_score_kernel<<<(int)(((size_t)esim * 32 + 255) / 256), 256>>>(
        ssim, dsim, l1b, l2W, l2b, (float*)d_out, esim);
}

// round 14
// speedup vs baseline: 6.3430x; 1.3559x over previous
#include <cuda_runtime.h>
#include <cuda_bf16.h>
#include <math.h>
#include <stdint.h>

#define NN   50000
#define FH   128
#define NTOT (4 * NN)
#define CSRMAX 2200000
#define SCAN_B ((NTOT + 1023) / 1024)

// ===================== scratch (static device globals) =====================
__device__ int           g_degi[NTOT];
__device__ int           g_offs[NTOT + 1];
__device__ int           g_cur[NTOT];
__device__ int           g_part[SCAN_B];
__device__ int           g_csr[CSRMAX];
__device__ float         g_pq[(size_t)2 * NN * FH];          // P = emb@W1a, Q = emb@W1b
__device__ __nv_bfloat16 g_x[(size_t)NN * FH];
__device__ __nv_bfloat16 g_agg[(size_t)4 * NN * FH];
__device__ __nv_bfloat16 g_h1[(size_t)4 * NN * FH];
__device__ __nv_bfloat16 g_hs[(size_t)4 * NN * FH];
__device__ __nv_bfloat16 g_emb[(size_t)NN * FH];
__device__ __nv_bfloat16 g_whi[18 * 16384];   // [mat][n][k]

__device__ __forceinline__ uint32_t pack_bf16(__nv_bfloat16 a, __nv_bfloat16 b) {
    return (uint32_t)__bfloat16_as_ushort(a) | ((uint32_t)__bfloat16_as_ushort(b) << 16);
}
__device__ __forceinline__ uint32_t pack2f(float a, float b) {
    return pack_bf16(__float2bfloat16(a), __float2bfloat16(b));
}
__device__ __forceinline__ uint32_t smem_u32(const void* p) {
    uint32_t a;
    asm("{ .reg .u64 t; cvta.to.shared.u64 t, %1; cvt.u32.u64 %0, t; }" : "=r"(a) : "l"(p));
    return a;
}
__device__ __forceinline__ uint32_t swz(uint32_t off) { return off ^ ((off >> 3) & 0x70); }

__device__ __forceinline__ void ldm_x4(uint32_t addr, uint32_t* r) {
    asm volatile("ldmatrix.sync.aligned.m8n8.x4.shared.b16 {%0,%1,%2,%3}, [%4];"
                 : "=r"(r[0]), "=r"(r[1]), "=r"(r[2]), "=r"(r[3]) : "r"(addr));
}
__device__ __forceinline__ void mma16816(float* c, const uint32_t* a, const uint32_t* b) {
    asm volatile("mma.sync.aligned.m16n8k16.row.col.f32.bf16.bf16.f32 "
        "{%0,%1,%2,%3}, {%4,%5,%6,%7}, {%8,%9}, {%0,%1,%2,%3};"
        : "+f"(c[0]), "+f"(c[1]), "+f"(c[2]), "+f"(c[3])
        : "r"(a[0]), "r"(a[1]), "r"(a[2]), "r"(a[3]), "r"(b[0]), "r"(b[1]));
}
__device__ __forceinline__ void cpasync16z(uint32_t dst, const void* src, int src_bytes) {
    asm volatile("cp.async.ca.shared.global [%0], [%1], 16, %2;"
                 :: "r"(dst), "l"(__cvta_generic_to_global(src)), "r"(src_bytes) : "memory");
}
#define CP_COMMIT() asm volatile("cp.async.commit_group;" ::: "memory")
#define CP_WAIT0()  asm volatile("cp.async.wait_group 0;" ::: "memory")

// ===================== small kernels =====================
__global__ void split_weights_kernel(const float* __restrict__ Ws1, const float* __restrict__ Wn1,
                                     const float* __restrict__ Ws2, const float* __restrict__ Wn2,
                                     const float* __restrict__ L1) {
    int g = blockIdx.x * blockDim.x + threadIdx.x;
    if (g >= 18 * 16384) return;
    int m = g >> 14, r = g & 16383, n = r >> 7, k = r & 127;
    const float* s;
    if (m < 4)       s = Ws1 + (size_t)m * 16384;
    else if (m < 8)  s = Wn1 + (size_t)(m - 4) * 16384;
    else if (m < 12) s = Ws2 + (size_t)(m - 8) * 16384;
    else if (m < 16) s = Wn2 + (size_t)(m - 12) * 16384;
    else             s = L1  + (size_t)(m - 16) * 16384;
    g_whi[(size_t)m * 16384 + n * 128 + k] = __float2bfloat16(s[k * 128 + n]);
}

__global__ void split_x_kernel(const float* __restrict__ src) {
    int i = blockIdx.x * blockDim.x + threadIdx.x;
    if (i >= NN * FH) return;
    g_x[i] = __float2bfloat16(src[i]);
}

struct EdgeArgs {
    const int* src[4]; const int* dst[4];
    int off[5];
};

// ---------- CSR build ----------
__global__ void degcount_kernel(EdgeArgs a) {
    int w = blockIdx.x * blockDim.x + threadIdx.x;
    if (w >= a.off[4]) return;
    int y = (w >= a.off[1]) + (w >= a.off[2]) + (w >= a.off[3]);
    atomicAdd(&g_degi[y * NN + __ldg(a.dst[y] + (w - a.off[y]))], 1);
}

__global__ void scan1_kernel() {
    __shared__ int sh[1024];
    int t = threadIdx.x;
    int i = blockIdx.x * 1024 + t;
    int v = (i < NTOT) ? g_degi[i] : 0;
    sh[t] = v;
    __syncthreads();
#pragma unroll
    for (int o = 1; o < 1024; o <<= 1) {
        int add = (t >= o) ? sh[t - o] : 0;
        __syncthreads();
        sh[t] += add;
        __syncthreads();
    }
    if (i < NTOT) g_offs[i] = sh[t] - v;
    if (t == 1023) g_part[blockIdx.x] = sh[1023];
}

__global__ void scan2_kernel() {
    __shared__ int sh[256];
    int t = threadIdx.x;
    int v = (t < SCAN_B) ? g_part[t] : 0;
    sh[t] = v;
    __syncthreads();
#pragma unroll
    for (int o = 1; o < 256; o <<= 1) {
        int add = (t >= o) ? sh[t - o] : 0;
        __syncthreads();
        sh[t] += add;
        __syncthreads();
    }
    if (t < SCAN_B) g_part[t] = sh[t] - v;
    if (t == 255) g_offs[NTOT] = sh[255];
}

__global__ void scan3_kernel() {
    int i = blockIdx.x * 1024 + threadIdx.x;
    if (i < NTOT) g_offs[i] += g_part[blockIdx.x];
}

__global__ void fill_kernel(EdgeArgs a) {
    int w = blockIdx.x * blockDim.x + threadIdx.x;
    if (w >= a.off[4]) return;
    int y = (w >= a.off[1]) + (w >= a.off[2]) + (w >= a.off[3]);
    int e = w - a.off[y];
    int s = __ldg(a.src[y] + e), d = __ldg(a.dst[y] + e);
    int node = y * NN + d;
    int pos = g_offs[node] + atomicAdd(&g_cur[node], 1);
    g_csr[pos] = s;
}

// ---------- CSR gather aggregation: one warp per (metapath,node), 2-edge ILP, bf16 rows ----------
__global__ void gather_kernel(const __nv_bfloat16* __restrict__ src, size_t ystride) {
    int g = (blockIdx.x * blockDim.x + threadIdx.x) >> 5;
    if (g >= NTOT) return;
    int lane = threadIdx.x & 31;
    int y = g / NN;
    const __nv_bfloat16* base = src + (size_t)y * ystride;
    int o0 = __ldg(g_offs + g), o1 = __ldg(g_offs + g + 1);
    float4 acc0 = make_float4(0.f, 0.f, 0.f, 0.f);
    float4 acc1 = make_float4(0.f, 0.f, 0.f, 0.f);
    int j = o0;
    for (; j + 1 < o1; j += 2) {
        int s0 = __ldg(g_csr + j), s1 = __ldg(g_csr + j + 1);
        uint2 h0 = __ldg((const uint2*)(base + (size_t)s0 * FH) + lane);
        uint2 h1 = __ldg((const uint2*)(base + (size_t)s1 * FH) + lane);
        float2 a0 = __bfloat1622float2(*(__nv_bfloat162*)&h0.x);
        float2 b0 = __bfloat1622float2(*(__nv_bfloat162*)&h0.y);
        float2 a1 = __bfloat1622float2(*(__nv_bfloat162*)&h1.x);
        float2 b1 = __bfloat1622float2(*(__nv_bfloat162*)&h1.y);
        acc0.x += a0.x; acc0.y += a0.y; acc0.z += b0.x; acc0.w += b0.y;
        acc1.x += a1.x; acc1.y += a1.y; acc1.z += b1.x; acc1.w += b1.y;
    }
    if (j < o1) {
        int s0 = __ldg(g_csr + j);
        uint2 h0 = __ldg((const uint2*)(base + (size_t)s0 * FH) + lane);
        float2 a0 = __bfloat1622float2(*(__nv_bfloat162*)&h0.x);
        float2 b0 = __bfloat1622float2(*(__nv_bfloat162*)&h0.y);
        acc0.x += a0.x; acc0.y += a0.y; acc0.z += b0.x; acc0.w += b0.y;
    }
    float sc = 1.0f / fmaxf((float)(o1 - o0), 1.0f);
    float ax = (acc0.x + acc1.x) * sc, ay = (acc0.y + acc1.y) * sc;
    float az = (acc0.z + acc1.z) * sc, aw = (acc0.w + acc1.w) * sc;
    *(uint2*)(g_agg + (size_t)g * FH + lane * 4) = make_uint2(pack2f(ax, ay), pack2f(az, aw));
}

// attention softmax over 4 metapaths -> emb bf16; one warp per node
__global__ void attention_kernel(const float* __restrict__ attW, const float* __restrict__ attB) {
    int n = (blockIdx.x * blockDim.x + threadIdx.x) >> 5;
    if (n >= NN) return;
    int lane = threadIdx.x & 31;
    float4 hv[4]; float logit[4];
#pragma unroll
    for (int k = 0; k < 4; ++k) {
        uint2 h = __ldg((const uint2*)(g_hs + ((size_t)k * NN + n) * FH) + lane);
        float2 h01 = __bfloat1622float2(*(__nv_bfloat162*)&h.x);
        float2 h23 = __bfloat1622float2(*(__nv_bfloat162*)&h.y);
        float4 h4 = make_float4(h01.x, h01.y, h23.x, h23.y);
        float4 w4 = *(const float4*)(attW + k * FH + lane * 4);
        hv[k] = h4;
        float p = h4.x * w4.x + h4.y * w4.y + h4.z * w4.z + h4.w * w4.w;
#pragma unroll
        for (int o2 = 16; o2; o2 >>= 1) p += __shfl_xor_sync(0xffffffffu, p, o2);
        logit[k] = p + attB[k];
    }
    float m = fmaxf(fmaxf(logit[0], logit[1]), fmaxf(logit[2], logit[3]));
    float e[4], s = 0.0f;
#pragma unroll
    for (int k = 0; k < 4; ++k) { e[k] = expf(logit[k] - m); s += e[k]; }
    float is = 1.0f / s;
    float4 o = make_float4(0.f, 0.f, 0.f, 0.f);
#pragma unroll
    for (int k = 0; k < 4; ++k) {
        float w = e[k] * is;
        o.x += w * hv[k].x; o.y += w * hv[k].y; o.z += w * hv[k].z; o.w += w * hv[k].w;
    }
    *(uint2*)(g_emb + (size_t)n * FH + lane * 4) = make_uint2(pack2f(o.x, o.y), pack2f(o.z, o.w));
}

// edge scorer: score = sigmoid(sum relu(P[s]+Q[d]+b) * w2 + b2); one warp per edge.
__global__ void edge_score_kernel(const int* __restrict__ src, const int* __restrict__ dst,
                                  const float* __restrict__ l1b, const float* __restrict__ l2w,
                                  const float* __restrict__ l2b,
                                  float* __restrict__ out, int ne) {
    int e = (blockIdx.x * blockDim.x + threadIdx.x) >> 5;
    if (e >= ne) return;
    int lane = threadIdx.x & 31;
    int s = __ldg(src + e), d = __ldg(dst + e);
    float4 p = *(const float4*)(g_pq + (size_t)s * FH + lane * 4);
    float4 q = *(const float4*)(g_pq + (size_t)NN * FH + (size_t)d * FH + lane * 4);
    float4 b = *(const float4*)(l1b + lane * 4);
    float4 w = *(const float4*)(l2w + lane * 4);
    float acc = fmaxf(p.x + q.x + b.x, 0.f) * w.x + fmaxf(p.y + q.y + b.y, 0.f) * w.y
              + fmaxf(p.z + q.z + b.z, 0.f) * w.z + fmaxf(p.w + q.w + b.w, 0.f) * w.w;
#pragma unroll
    for (int o = 16; o; o >>= 1) acc += __shfl_xor_sync(0xffffffffu, acc, o);
    if (lane == 0) out[e] = 1.0f / (1.0f + expf(-(acc + __ldg(l2b))));
}

// ===================== mma.sync GEMM: single bf16 pass =====================
// MODE 0: 2 halves, bias+relu -> bf16.  MODE 1: 2 halves, +bias -> bf16.
// MODE 3: single half (K=128), no bias -> f32.
#define SB_BIAS 0
#define SB_TILES 1024
#define TILE_SZ 16384
#define SMEM_TOTAL (SB_TILES + 2 * TILE_SZ)

__device__ __forceinline__ void stage_tile(uint32_t stile, const __nv_bfloat16* gbase,
                                           int row0, int nrows, int kofs, int tid) {
#pragma unroll
    for (int i = tid; i < 1024; i += 256) {
        int r = i >> 3, j = i & 7;
        int grow = row0 + r;
        bool valid = grow < nrows;
        const __nv_bfloat16* src = gbase + (size_t)(valid ? grow : 0) * FH + kofs + j * 8;
        uint32_t off = (uint32_t)(r * 128 + j * 16);
        cpasync16z(stile + swz(off), src, valid ? 16 : 0);
    }
}

__device__ __forceinline__ void load_a_frag(uint32_t tb, int wm, int ks, int lane, uint32_t* ra) {
    int q = lane >> 3, r = lane & 7;
    int rofs = ((q & 1) ? 8 : 0) + r;
    int kl = ks * 16 + ((q & 2) ? 8 : 0);
#pragma unroll
    for (int mf = 0; mf < 4; ++mf) {
        uint32_t off = (uint32_t)((wm * 64 + mf * 16 + rofs) * 128 + kl * 2);
        ldm_x4(tb + swz(off), ra + mf * 4);
    }
}
__device__ __forceinline__ void load_w_frag(uint32_t tb, int wn, int ks, int lane, uint32_t* rw) {
    int q = lane >> 3, r = lane & 7;
    int rofs = ((q & 2) ? 8 : 0) + r;
    int kl = ks * 16 + ((q & 1) ? 8 : 0);
#pragma unroll
    for (int pf = 0; pf < 2; ++pf) {
        uint32_t off = (uint32_t)((wn * 32 + pf * 16 + rofs) * 128 + kl * 2);
        ldm_x4(tb + swz(off), rw + pf * 4);
    }
}

template <int MODE>
__global__ void __launch_bounds__(256) mp_gemm_kernel(
    const __nv_bfloat16* __restrict__ a0, size_t a0stride,
    const __nv_bfloat16* __restrict__ a1, size_t a1stride,
    int w0mat, int w1mat, int wmatstride,
    const float* __restrict__ bias, int bstride,
    float* __restrict__ outf, size_t outfstride,
    __nv_bfloat16* __restrict__ outb, size_t outbstride,
    int nrows)
{
    extern __shared__ char smem[];
    const uint32_t sb = smem_u32(smem);
    const int tid = threadIdx.x, lane = tid & 31, wid = tid >> 5;
    const int wm = wid & 1, wn = wid >> 1;
    const int y = blockIdx.y;
    const int row0 = blockIdx.x * 128;

    float* sbias = (float*)(smem + SB_BIAS);
    if (tid < 128) sbias[tid] = bias[bstride * y + tid];

    const __nv_bfloat16* ab[2] = { a0 + (size_t)y * a0stride, a1 + (size_t)y * a1stride };
    const int wm0 = w0mat + y * wmatstride, wm1 = w1mat + y * wmatstride;

    const uint32_t tA = sb + SB_TILES;
    const uint32_t tW = sb + SB_TILES + TILE_SZ;

    float acc[4][4][4];
#pragma unroll
    for (int i = 0; i < 4; ++i)
#pragma unroll
        for (int j = 0; j < 4; ++j)
#pragma unroll
            for (int q = 0; q < 4; ++q) acc[i][j][q] = 0.0f;

    const int CHUNKS = (MODE == 3) ? 2 : 4;
#pragma unroll 1
    for (int c = 0; c < CHUNKS; ++c) {
        const int half = (MODE == 3) ? 0 : (c >> 1), kc = (c & 1) * 64;
        const __nv_bfloat16* whb = g_whi + (size_t)(half ? wm1 : wm0) * 16384;
        if (c) __syncthreads();
        stage_tile(tA, ab[half], row0, nrows, kc, tid);
        stage_tile(tW, whb, 0, 128, kc, tid);
        CP_COMMIT();
        CP_WAIT0();
        __syncthreads();

#pragma unroll
        for (int ks = 0; ks < 4; ++ks) {
            uint32_t ra[16], rw[8];
            load_a_frag(tA, wm, ks, lane, ra);
            load_w_frag(tW, wn, ks, lane, rw);
#pragma unroll
            for (int mf = 0; mf < 4; ++mf)
#pragma unroll
                for (int nf = 0; nf < 4; ++nf)
                    mma16816(acc[mf][nf], ra + mf * 4, rw + nf * 2);
        }
    }

    // ---------------- epilogue ----------------
    const int rbase = row0 + wm * 64 + (lane >> 2);
    const int cbase = wn * 32 + 2 * (lane & 3);

#pragma unroll
    for (int mf = 0; mf < 4; ++mf) {
        int r0 = rbase + mf * 16, r1 = r0 + 8;
        bool v0 = r0 < nrows, v1 = r1 < nrows;
#pragma unroll
        for (int nf = 0; nf < 4; ++nf) {
            int gc = cbase + nf * 8;
            float b0v = (MODE == 3) ? 0.f : sbias[gc];
            float b1v = (MODE == 3) ? 0.f : sbias[gc + 1];
            float e0 = acc[mf][nf][0] + b0v, e1 = acc[mf][nf][1] + b1v;
            float e2 = acc[mf][nf][2] + b0v, e3 = acc[mf][nf][3] + b1v;
            if (MODE == 3) {
                if (v0) *(float2*)(outf + (size_t)y * outfstride + (size_t)r0 * FH + gc) = make_float2(e0, e1);
                if (v1) *(float2*)(outf + (size_t)y * outfstride + (size_t)r1 * FH + gc) = make_float2(e2, e3);
            } else {
                if (MODE == 0) {
                    e0 = fmaxf(e0, 0.f); e1 = fmaxf(e1, 0.f);
                    e2 = fmaxf(e2, 0.f); e3 = fmaxf(e3, 0.f);
                }
                if (v0) *(uint32_t*)(outb + (size_t)y * outbstride + (size_t)r0 * FH + gc) = pack2f(e0, e1);
                if (v1) *(uint32_t*)(outb + (size_t)y * outbstride + (size_t)r1 * FH + gc) = pack2f(e2, e3);
            }
        }
    }
}

// ===================== host =====================
extern "C" void kernel_launch(void* const* d_in, const int* in_sizes, int n_in,
                              void* d_out, int out_size) {
    const float* x    = (const float*)d_in[0];
    const float* Ws1  = (const float*)d_in[1];
    const float* b1   = (const float*)d_in[2];
    const float* Wn1  = (const float*)d_in[3];
    const float* Ws2  = (const float*)d_in[4];
    const float* b2   = (const float*)d_in[5];
    const float* Wn2  = (const float*)d_in[6];
    const float* attW = (const float*)d_in[7];
    const float* attB = (const float*)d_in[8];
    const float* l1W  = (const float*)d_in[9];
    const float* l1b  = (const float*)d_in[10];
    const float* l2W  = (const float*)d_in[11];
    const float* l2b  = (const float*)d_in[12];
    const int* srcs[4] = {(const int*)d_in[13], (const int*)d_in[15],
                          (const int*)d_in[17], (const int*)d_in[19]};
    const int* dsts[4] = {(const int*)d_in[14], (const int*)d_in[16],
                          (const int*)d_in[18], (const int*)d_in[20]};
    const int* ssim = (const int*)d_in[21];
    const int* dsim = (const int*)d_in[22];
    const int  esim = in_sizes[21];

    void *degiP, *curP, *pqP, *xP, *aggP, *h1P, *hsP, *embP;
    cudaGetSymbolAddress(&degiP, g_degi);
    cudaGetSymbolAddress(&curP, g_cur);
    cudaGetSymbolAddress(&pqP, g_pq);
    cudaGetSymbolAddress(&xP, g_x);
    cudaGetSymbolAddress(&aggP, g_agg);
    cudaGetSymbolAddress(&h1P, g_h1);
    cudaGetSymbolAddress(&hsP, g_hs);
    cudaGetSymbolAddress(&embP, g_emb);

    cudaFuncSetAttribute(mp_gemm_kernel<0>, cudaFuncAttributeMaxDynamicSharedMemorySize, SMEM_TOTAL);
    cudaFuncSetAttribute(mp_gemm_kernel<1>, cudaFuncAttributeMaxDynamicSharedMemorySize, SMEM_TOTAL);
    cudaFuncSetAttribute(mp_gemm_kernel<3>, cudaFuncAttributeMaxDynamicSharedMemorySize, SMEM_TOTAL);

    EdgeArgs ea;
    ea.off[0] = 0;
    for (int k = 0; k < 4; ++k) {
        ea.src[k] = srcs[k]; ea.dst[k] = dsts[k];
        ea.off[k + 1] = ea.off[k] + in_sizes[13 + 2 * k];
    }
    const int total_e = ea.off[4];

    const int NB = (NN + 127) / 128;
    const size_t NF = (size_t)NN * FH;
    const int NG = (int)(((size_t)NTOT * 32 + 255) / 256);

    // 0. weight + x conversion
    split_weights_kernel<<<(18 * 16384 + 255) / 256, 256>>>(Ws1, Wn1, Ws2, Wn2, l1W);
    split_x_kernel<<<(NN * FH + 255) / 256, 256>>>(x);

    // 1. CSR build (shared by both layers)
    cudaMemsetAsync(degiP, 0, NTOT * sizeof(int));
    cudaMemsetAsync(curP, 0, NTOT * sizeof(int));
    degcount_kernel<<<(total_e + 255) / 256, 256>>>(ea);
    scan1_kernel<<<SCAN_B, 1024>>>();
    scan2_kernel<<<1, 256>>>();
    scan3_kernel<<<SCAN_B, 1024>>>();
    fill_kernel<<<(total_e + 255) / 256, 256>>>(ea);

    // 2. layer-1 aggregation: gather mean of x -> agg bf16
    gather_kernel<<<NG, 256>>>((const __nv_bfloat16*)xP, 0);

    // 3. layer-1 GEMM: h1 = relu(x@Ws1 + aggn@Wn1 + b1) -> bf16
    mp_gemm_kernel<0><<<dim3(NB, 4), 256, SMEM_TOTAL>>>(
        (const __nv_bfloat16*)xP, 0, (const __nv_bfloat16*)aggP, NF,
        0, 4, 1, b1, FH,
        nullptr, 0, (__nv_bfloat16*)h1P, NF, NN);

    // 4. layer-2 aggregation: gather mean of h1
    gather_kernel<<<NG, 256>>>((const __nv_bfloat16*)h1P, NF);

    // 5. layer-2 GEMM -> hstack bf16
    mp_gemm_kernel<1><<<dim3(NB, 4), 256, SMEM_TOTAL>>>(
        (const __nv_bfloat16*)h1P, NF, (const __nv_bfloat16*)aggP, NF,
        8, 12, 1, b2, FH,
        nullptr, 0, (__nv_bfloat16*)hsP, NF, NN);

    // 6. attention -> emb bf16
    attention_kernel<<<(NN * 32 + 255) / 256, 256>>>(attW, attB);

    // 7. P/Q GEMM: P = emb@W1a (y=0), Q = emb@W1b (y=1); no bias
    mp_gemm_kernel<3><<<dim3(NB, 2), 256, SMEM_TOTAL>>>(
        (const __nv_bfloat16*)embP, 0, (const __nv_bfloat16*)embP, 0,
        16, 16, 1, l1b, 0,
        (float*)pqP, NF, nullptr, 0, NN);

    // 8. edge scorer: relu(P[s]+Q[d]+b) . w2 -> sigmoid
    edge_score_kernel<<<(int)(((size_t)esim * 32 + 255) / 256), 256>>>(
        ssim, dsim, l1b, l2W, l2b, (float*)d_out, esim);
}

// round 15
// speedup vs baseline: 6.4892x; 1.0230x over previous
#include <cuda_runtime.h>
#include <cuda_bf16.h>
#include <math.h>
#include <stdint.h>

#define NN   50000
#define FH   128
#define NTOT (4 * NN)
#define CSRMAX 2200000
#define SCAN_B ((NTOT + 1023) / 1024)

// ===================== scratch (static device globals) =====================
__device__ int           g_degi[NTOT];
__device__ int           g_offs[NTOT + 1];
__device__ int           g_cur[NTOT];
__device__ int           g_part[SCAN_B];
__device__ int           g_csr[CSRMAX];
__device__ __nv_bfloat16 g_pq[(size_t)2 * NN * FH];   // P = emb@W1a, Q = emb@W1b (bf16)
__device__ __nv_bfloat16 g_x[(size_t)NN * FH];
__device__ __nv_bfloat16 g_agg[(size_t)4 * NN * FH];
__device__ __nv_bfloat16 g_h1[(size_t)4 * NN * FH];
__device__ __nv_bfloat16 g_hs[(size_t)4 * NN * FH];
__device__ __nv_bfloat16 g_emb[(size_t)NN * FH];
__device__ __nv_bfloat16 g_whi[18 * 16384];   // [mat][n][k]

__device__ __forceinline__ uint32_t pack_bf16(__nv_bfloat16 a, __nv_bfloat16 b) {
    return (uint32_t)__bfloat16_as_ushort(a) | ((uint32_t)__bfloat16_as_ushort(b) << 16);
}
__device__ __forceinline__ uint32_t pack2f(float a, float b) {
    return pack_bf16(__float2bfloat16(a), __float2bfloat16(b));
}
__device__ __forceinline__ uint32_t smem_u32(const void* p) {
    uint32_t a;
    asm("{ .reg .u64 t; cvta.to.shared.u64 t, %1; cvt.u32.u64 %0, t; }" : "=r"(a) : "l"(p));
    return a;
}
__device__ __forceinline__ uint32_t swz(uint32_t off) { return off ^ ((off >> 3) & 0x70); }

__device__ __forceinline__ void ldm_x4(uint32_t addr, uint32_t* r) {
    asm volatile("ldmatrix.sync.aligned.m8n8.x4.shared.b16 {%0,%1,%2,%3}, [%4];"
                 : "=r"(r[0]), "=r"(r[1]), "=r"(r[2]), "=r"(r[3]) : "r"(addr));
}
__device__ __forceinline__ void mma16816(float* c, const uint32_t* a, const uint32_t* b) {
    asm volatile("mma.sync.aligned.m16n8k16.row.col.f32.bf16.bf16.f32 "
        "{%0,%1,%2,%3}, {%4,%5,%6,%7}, {%8,%9}, {%0,%1,%2,%3};"
        : "+f"(c[0]), "+f"(c[1]), "+f"(c[2]), "+f"(c[3])
        : "r"(a[0]), "r"(a[1]), "r"(a[2]), "r"(a[3]), "r"(b[0]), "r"(b[1]));
}
__device__ __forceinline__ void cpasync16z(uint32_t dst, const void* src, int src_bytes) {
    asm volatile("cp.async.ca.shared.global [%0], [%1], 16, %2;"
                 :: "r"(dst), "l"(__cvta_generic_to_global(src)), "r"(src_bytes) : "memory");
}
#define CP_COMMIT() asm volatile("cp.async.commit_group;" ::: "memory")
#define CP_WAIT0()  asm volatile("cp.async.wait_group 0;" ::: "memory")
#define CP_WAIT1()  asm volatile("cp.async.wait_group 1;" ::: "memory")

// ===================== small kernels =====================
__global__ void split_weights_kernel(const float* __restrict__ Ws1, const float* __restrict__ Wn1,
                                     const float* __restrict__ Ws2, const float* __restrict__ Wn2,
                                     const float* __restrict__ L1) {
    int g = blockIdx.x * blockDim.x + threadIdx.x;
    if (g >= 18 * 16384) return;
    int m = g >> 14, r = g & 16383, n = r >> 7, k = r & 127;
    const float* s;
    if (m < 4)       s = Ws1 + (size_t)m * 16384;
    else if (m < 8)  s = Wn1 + (size_t)(m - 4) * 16384;
    else if (m < 12) s = Ws2 + (size_t)(m - 8) * 16384;
    else if (m < 16) s = Wn2 + (size_t)(m - 12) * 16384;
    else             s = L1  + (size_t)(m - 16) * 16384;
    g_whi[(size_t)m * 16384 + n * 128 + k] = __float2bfloat16(s[k * 128 + n]);
}

__global__ void split_x_kernel(const float* __restrict__ src) {
    int i = blockIdx.x * blockDim.x + threadIdx.x;
    if (i >= NN * FH) return;
    g_x[i] = __float2bfloat16(src[i]);
}

struct EdgeArgs {
    const int* src[4]; const int* dst[4];
    int off[5];
};

// ---------- CSR build ----------
__global__ void degcount_kernel(EdgeArgs a) {
    int w = blockIdx.x * blockDim.x + threadIdx.x;
    if (w >= a.off[4]) return;
    int y = (w >= a.off[1]) + (w >= a.off[2]) + (w >= a.off[3]);
    atomicAdd(&g_degi[y * NN + __ldg(a.dst[y] + (w - a.off[y]))], 1);
}

__global__ void scan1_kernel() {
    __shared__ int sh[1024];
    int t = threadIdx.x;
    int i = blockIdx.x * 1024 + t;
    int v = (i < NTOT) ? g_degi[i] : 0;
    sh[t] = v;
    __syncthreads();
#pragma unroll
    for (int o = 1; o < 1024; o <<= 1) {
        int add = (t >= o) ? sh[t - o] : 0;
        __syncthreads();
        sh[t] += add;
        __syncthreads();
    }
    if (i < NTOT) g_offs[i] = sh[t] - v;
    if (t == 1023) g_part[blockIdx.x] = sh[1023];
}

__global__ void scan2_kernel() {
    __shared__ int sh[256];
    int t = threadIdx.x;
    int v = (t < SCAN_B) ? g_part[t] : 0;
    sh[t] = v;
    __syncthreads();
#pragma unroll
    for (int o = 1; o < 256; o <<= 1) {
        int add = (t >= o) ? sh[t - o] : 0;
        __syncthreads();
        sh[t] += add;
        __syncthreads();
    }
    if (t < SCAN_B) g_part[t] = sh[t] - v;
    if (t == 255) g_offs[NTOT] = sh[255];
}

__global__ void scan3_kernel() {
    int i = blockIdx.x * 1024 + threadIdx.x;
    if (i < NTOT) g_offs[i] += g_part[blockIdx.x];
}

__global__ void fill_kernel(EdgeArgs a) {
    int w = blockIdx.x * blockDim.x + threadIdx.x;
    if (w >= a.off[4]) return;
    int y = (w >= a.off[1]) + (w >= a.off[2]) + (w >= a.off[3]);
    int e = w - a.off[y];
    int s = __ldg(a.src[y] + e), d = __ldg(a.dst[y] + e);
    int node = y * NN + d;
    int pos = g_offs[node] + atomicAdd(&g_cur[node], 1);
    g_csr[pos] = s;
}

// ---------- CSR gather aggregation: one warp per (metapath,node), 4-edge ILP ----------
__global__ void gather_kernel(const __nv_bfloat16* __restrict__ src, size_t ystride) {
    int g = (blockIdx.x * blockDim.x + threadIdx.x) >> 5;
    if (g >= NTOT) return;
    int lane = threadIdx.x & 31;
    int y = g / NN;
    const __nv_bfloat16* base = src + (size_t)y * ystride;
    int o0 = __ldg(g_offs + g), o1 = __ldg(g_offs + g + 1);
    float4 acc0 = make_float4(0.f, 0.f, 0.f, 0.f);
    float4 acc1 = make_float4(0.f, 0.f, 0.f, 0.f);
    int j = o0;
    for (; j + 3 < o1; j += 4) {
        int s0 = __ldg(g_csr + j),     s1 = __ldg(g_csr + j + 1);
        int s2 = __ldg(g_csr + j + 2), s3 = __ldg(g_csr + j + 3);
        uint2 h0 = __ldg((const uint2*)(base + (size_t)s0 * FH) + lane);
        uint2 h1 = __ldg((const uint2*)(base + (size_t)s1 * FH) + lane);
        uint2 h2 = __ldg((const uint2*)(base + (size_t)s2 * FH) + lane);
        uint2 h3 = __ldg((const uint2*)(base + (size_t)s3 * FH) + lane);
        float2 a0 = __bfloat1622float2(*(__nv_bfloat162*)&h0.x);
        float2 b0 = __bfloat1622float2(*(__nv_bfloat162*)&h0.y);
        float2 a1 = __bfloat1622float2(*(__nv_bfloat162*)&h1.x);
        float2 b1 = __bfloat1622float2(*(__nv_bfloat162*)&h1.y);
        float2 a2 = __bfloat1622float2(*(__nv_bfloat162*)&h2.x);
        float2 b2 = __bfloat1622float2(*(__nv_bfloat162*)&h2.y);
        float2 a3 = __bfloat1622float2(*(__nv_bfloat162*)&h3.x);
        float2 b3 = __bfloat1622float2(*(__nv_bfloat162*)&h3.y);
        acc0.x += a0.x + a2.x; acc0.y += a0.y + a2.y; acc0.z += b0.x + b2.x; acc0.w += b0.y + b2.y;
        acc1.x += a1.x + a3.x; acc1.y += a1.y + a3.y; acc1.z += b1.x + b3.x; acc1.w += b1.y + b3.y;
    }
    for (; j < o1; ++j) {
        int s0 = __ldg(g_csr + j);
        uint2 h0 = __ldg((const uint2*)(base + (size_t)s0 * FH) + lane);
        float2 a0 = __bfloat1622float2(*(__nv_bfloat162*)&h0.x);
        float2 b0 = __bfloat1622float2(*(__nv_bfloat162*)&h0.y);
        acc0.x += a0.x; acc0.y += a0.y; acc0.z += b0.x; acc0.w += b0.y;
    }
    float sc = 1.0f / fmaxf((float)(o1 - o0), 1.0f);
    float ax = (acc0.x + acc1.x) * sc, ay = (acc0.y + acc1.y) * sc;
    float az = (acc0.z + acc1.z) * sc, aw = (acc0.w + acc1.w) * sc;
    *(uint2*)(g_agg + (size_t)g * FH + lane * 4) = make_uint2(pack2f(ax, ay), pack2f(az, aw));
}

// attention softmax over 4 metapaths -> emb bf16; one warp per node
__global__ void attention_kernel(const float* __restrict__ attW, const float* __restrict__ attB) {
    int n = (blockIdx.x * blockDim.x + threadIdx.x) >> 5;
    if (n >= NN) return;
    int lane = threadIdx.x & 31;
    float4 hv[4]; float logit[4];
#pragma unroll
    for (int k = 0; k < 4; ++k) {
        uint2 h = __ldg((const uint2*)(g_hs + ((size_t)k * NN + n) * FH) + lane);
        float2 h01 = __bfloat1622float2(*(__nv_bfloat162*)&h.x);
        float2 h23 = __bfloat1622float2(*(__nv_bfloat162*)&h.y);
        float4 h4 = make_float4(h01.x, h01.y, h23.x, h23.y);
        float4 w4 = *(const float4*)(attW + k * FH + lane * 4);
        hv[k] = h4;
        float p = h4.x * w4.x + h4.y * w4.y + h4.z * w4.z + h4.w * w4.w;
#pragma unroll
        for (int o2 = 16; o2; o2 >>= 1) p += __shfl_xor_sync(0xffffffffu, p, o2);
        logit[k] = p + attB[k];
    }
    float m = fmaxf(fmaxf(logit[0], logit[1]), fmaxf(logit[2], logit[3]));
    float e[4], s = 0.0f;
#pragma unroll
    for (int k = 0; k < 4; ++k) { e[k] = expf(logit[k] - m); s += e[k]; }
    float is = 1.0f / s;
    float4 o = make_float4(0.f, 0.f, 0.f, 0.f);
#pragma unroll
    for (int k = 0; k < 4; ++k) {
        float w = e[k] * is;
        o.x += w * hv[k].x; o.y += w * hv[k].y; o.z += w * hv[k].z; o.w += w * hv[k].w;
    }
    *(uint2*)(g_emb + (size_t)n * FH + lane * 4) = make_uint2(pack2f(o.x, o.y), pack2f(o.z, o.w));
}

// edge scorer: score = sigmoid(sum relu(P[s]+Q[d]+b) * w2 + b2); one warp per edge; bf16 P/Q.
__global__ void edge_score_kernel(const int* __restrict__ src, const int* __restrict__ dst,
                                  const float* __restrict__ l1b, const float* __restrict__ l2w,
                                  const float* __restrict__ l2b,
                                  float* __restrict__ out, int ne) {
    int e = (blockIdx.x * blockDim.x + threadIdx.x) >> 5;
    if (e >= ne) return;
    int lane = threadIdx.x & 31;
    int s = __ldg(src + e), d = __ldg(dst + e);
    uint2 pu = __ldg((const uint2*)(g_pq + (size_t)s * FH) + lane);
    uint2 qu = __ldg((const uint2*)(g_pq + (size_t)NN * FH + (size_t)d * FH) + lane);
    float2 p01 = __bfloat1622float2(*(__nv_bfloat162*)&pu.x);
    float2 p23 = __bfloat1622float2(*(__nv_bfloat162*)&pu.y);
    float2 q01 = __bfloat1622float2(*(__nv_bfloat162*)&qu.x);
    float2 q23 = __bfloat1622float2(*(__nv_bfloat162*)&qu.y);
    float4 b = *(const float4*)(l1b + lane * 4);
    float4 w = *(const float4*)(l2w + lane * 4);
    float acc = fmaxf(p01.x + q01.x + b.x, 0.f) * w.x + fmaxf(p01.y + q01.y + b.y, 0.f) * w.y
              + fmaxf(p23.x + q23.x + b.z, 0.f) * w.z + fmaxf(p23.y + q23.y + b.w, 0.f) * w.w;
#pragma unroll
    for (int o = 16; o; o >>= 1) acc += __shfl_xor_sync(0xffffffffu, acc, o);
    if (lane == 0) out[e] = 1.0f / (1.0f + expf(-(acc + __ldg(l2b))));
}

// ===================== mma.sync GEMM: single bf16 pass, cp.async double-buffer =====================
// MODE 0: 2 halves, bias+relu -> bf16.  MODE 1: 2 halves, +bias -> bf16.
// MODE 3: single half (K=128), no bias -> bf16.
#define SB_BIAS 0
#define SB_TILES 1024
#define TILE_SZ 16384
#define SMEM_TOTAL (SB_TILES + 4 * TILE_SZ)   // 2 stages x (A,W)

__device__ __forceinline__ void stage_tile(uint32_t stile, const __nv_bfloat16* gbase,
                                           int row0, int nrows, int kofs, int tid) {
#pragma unroll
    for (int i = tid; i < 1024; i += 256) {
        int r = i >> 3, j = i & 7;
        int grow = row0 + r;
        bool valid = grow < nrows;
        const __nv_bfloat16* src = gbase + (size_t)(valid ? grow : 0) * FH + kofs + j * 8;
        uint32_t off = (uint32_t)(r * 128 + j * 16);
        cpasync16z(stile + swz(off), src, valid ? 16 : 0);
    }
}

__device__ __forceinline__ void load_a_frag(uint32_t tb, int wm, int ks, int lane, uint32_t* ra) {
    int q = lane >> 3, r = lane & 7;
    int rofs = ((q & 1) ? 8 : 0) + r;
    int kl = ks * 16 + ((q & 2) ? 8 : 0);
#pragma unroll
    for (int mf = 0; mf < 4; ++mf) {
        uint32_t off = (uint32_t)((wm * 64 + mf * 16 + rofs) * 128 + kl * 2);
        ldm_x4(tb + swz(off), ra + mf * 4);
    }
}
__device__ __forceinline__ void load_w_frag(uint32_t tb, int wn, int ks, int lane, uint32_t* rw) {
    int q = lane >> 3, r = lane & 7;
    int rofs = ((q & 2) ? 8 : 0) + r;
    int kl = ks * 16 + ((q & 1) ? 8 : 0);
#pragma unroll
    for (int pf = 0; pf < 2; ++pf) {
        uint32_t off = (uint32_t)((wn * 32 + pf * 16 + rofs) * 128 + kl * 2);
        ldm_x4(tb + swz(off), rw + pf * 4);
    }
}

template <int MODE>
__global__ void __launch_bounds__(256) mp_gemm_kernel(
    const __nv_bfloat16* __restrict__ a0, size_t a0stride,
    const __nv_bfloat16* __restrict__ a1, size_t a1stride,
    int w0mat, int w1mat, int wmatstride,
    const float* __restrict__ bias, int bstride,
    __nv_bfloat16* __restrict__ outb, size_t outbstride,
    int nrows)
{
    extern __shared__ char smem[];
    const uint32_t sb = smem_u32(smem);
    const int tid = threadIdx.x, lane = tid & 31, wid = tid >> 5;
    const int wm = wid & 1, wn = wid >> 1;
    const int y = blockIdx.y;
    const int row0 = blockIdx.x * 128;

    float* sbias = (float*)(smem + SB_BIAS);
    if (tid < 128) sbias[tid] = (MODE == 3) ? 0.f : bias[bstride * y + tid];

    const __nv_bfloat16* ab[2] = { a0 + (size_t)y * a0stride, a1 + (size_t)y * a1stride };
    const int wm0 = w0mat + y * wmatstride, wm1 = w1mat + y * wmatstride;

    float acc[4][4][4];
#pragma unroll
    for (int i = 0; i < 4; ++i)
#pragma unroll
        for (int j = 0; j < 4; ++j)
#pragma unroll
            for (int q = 0; q < 4; ++q) acc[i][j][q] = 0.0f;

    const int CHUNKS = (MODE == 3) ? 2 : 4;
    // prologue: stage chunk 0 into buffer 0
    {
        const int half = 0, kc = 0;
        stage_tile(sb + SB_TILES, ab[half], row0, nrows, kc, tid);
        stage_tile(sb + SB_TILES + TILE_SZ, g_whi + (size_t)wm0 * 16384, 0, 128, kc, tid);
        CP_COMMIT();
    }
#pragma unroll 1
    for (int c = 0; c < CHUNKS; ++c) {
        if (c + 1 < CHUNKS) {
            const int nh = (MODE == 3) ? 0 : ((c + 1) >> 1), nkc = ((c + 1) & 1) * 64;
            const uint32_t nbuf = sb + SB_TILES + ((c + 1) & 1) * 2 * TILE_SZ;
            stage_tile(nbuf, ab[nh], row0, nrows, nkc, tid);
            stage_tile(nbuf + TILE_SZ, g_whi + (size_t)(nh ? wm1 : wm0) * 16384, 0, 128, nkc, tid);
            CP_COMMIT();
            CP_WAIT1();
        } else {
            CP_WAIT0();
        }
        __syncthreads();
        const uint32_t buf = sb + SB_TILES + (c & 1) * 2 * TILE_SZ;
        const uint32_t tA = buf, tW = buf + TILE_SZ;
#pragma unroll
        for (int ks = 0; ks < 4; ++ks) {
            uint32_t ra[16], rw[8];
            load_a_frag(tA, wm, ks, lane, ra);
            load_w_frag(tW, wn, ks, lane, rw);
#pragma unroll
            for (int mf = 0; mf < 4; ++mf)
#pragma unroll
                for (int nf = 0; nf < 4; ++nf)
                    mma16816(acc[mf][nf], ra + mf * 4, rw + nf * 2);
        }
        if (c + 1 < CHUNKS) __syncthreads();   // done reading buf before it is re-staged
    }

    // ---------------- epilogue ----------------
    const int rbase = row0 + wm * 64 + (lane >> 2);
    const int cbase = wn * 32 + 2 * (lane & 3);

#pragma unroll
    for (int mf = 0; mf < 4; ++mf) {
        int r0 = rbase + mf * 16, r1 = r0 + 8;
        bool v0 = r0 < nrows, v1 = r1 < nrows;
#pragma unroll
        for (int nf = 0; nf < 4; ++nf) {
            int gc = cbase + nf * 8;
            float b0v = sbias[gc], b1v = sbias[gc + 1];
            float e0 = acc[mf][nf][0] + b0v, e1 = acc[mf][nf][1] + b1v;
            float e2 = acc[mf][nf][2] + b0v, e3 = acc[mf][nf][3] + b1v;
            if (MODE == 0) {
                e0 = fmaxf(e0, 0.f); e1 = fmaxf(e1, 0.f);
                e2 = fmaxf(e2, 0.f); e3 = fmaxf(e3, 0.f);
            }
            if (v0) *(uint32_t*)(outb + (size_t)y * outbstride + (size_t)r0 * FH + gc) = pack2f(e0, e1);
            if (v1) *(uint32_t*)(outb + (size_t)y * outbstride + (size_t)r1 * FH + gc) = pack2f(e2, e3);
        }
    }
}

// ===================== host =====================
extern "C" void kernel_launch(void* const* d_in, const int* in_sizes, int n_in,
                              void* d_out, int out_size) {
    const float* x    = (const float*)d_in[0];
    const float* Ws1  = (const float*)d_in[1];
    const float* b1   = (const float*)d_in[2];
    const float* Wn1  = (const float*)d_in[3];
    const float* Ws2  = (const float*)d_in[4];
    const float* b2   = (const float*)d_in[5];
    const float* Wn2  = (const float*)d_in[6];
    const float* attW = (const float*)d_in[7];
    const float* attB = (const float*)d_in[8];
    const float* l1W  = (const float*)d_in[9];
    const float* l1b  = (const float*)d_in[10];
    const float* l2W  = (const float*)d_in[11];
    const float* l2b  = (const float*)d_in[12];
    const int* srcs[4] = {(const int*)d_in[13], (const int*)d_in[15],
                          (const int*)d_in[17], (const int*)d_in[19]};
    const int* dsts[4] = {(const int*)d_in[14], (const int*)d_in[16],
                          (const int*)d_in[18], (const int*)d_in[20]};
    const int* ssim = (const int*)d_in[21];
    const int* dsim = (const int*)d_in[22];
    const int  esim = in_sizes[21];

    void *degiP, *curP, *pqP, *xP, *aggP, *h1P, *hsP, *embP;
    cudaGetSymbolAddress(&degiP, g_degi);
    cudaGetSymbolAddress(&curP, g_cur);
    cudaGetSymbolAddress(&pqP, g_pq);
    cudaGetSymbolAddress(&xP, g_x);
    cudaGetSymbolAddress(&aggP, g_agg);
    cudaGetSymbolAddress(&h1P, g_h1);
    cudaGetSymbolAddress(&hsP, g_hs);
    cudaGetSymbolAddress(&embP, g_emb);

    cudaFuncSetAttribute(mp_gemm_kernel<0>, cudaFuncAttributeMaxDynamicSharedMemorySize, SMEM_TOTAL);
    cudaFuncSetAttribute(mp_gemm_kernel<1>, cudaFuncAttributeMaxDynamicSharedMemorySize, SMEM_TOTAL);
    cudaFuncSetAttribute(mp_gemm_kernel<3>, cudaFuncAttributeMaxDynamicSharedMemorySize, SMEM_TOTAL);

    EdgeArgs ea;
    ea.off[0] = 0;
    for (int k = 0; k < 4; ++k) {
        ea.src[k] = srcs[k]; ea.dst[k] = dsts[k];
        ea.off[k + 1] = ea.off[k] + in_sizes[13 + 2 * k];
    }
    const int total_e = ea.off[4];

    const int NB = (NN + 127) / 128;
    const size_t NF = (size_t)NN * FH;
    const int NG = (int)(((size_t)NTOT * 32 + 255) / 256);

    // 0. weight + x conversion
    split_weights_kernel<<<(18 * 16384 + 255) / 256, 256>>>(Ws1, Wn1, Ws2, Wn2, l1W);
    split_x_kernel<<<(NN * FH + 255) / 256, 256>>>(x);

    // 1. CSR build (shared by both layers)
    cudaMemsetAsync(degiP, 0, NTOT * sizeof(int));
    cudaMemsetAsync(curP, 0, NTOT * sizeof(int));
    degcount_kernel<<<(total_e + 255) / 256, 256>>>(ea);
    scan1_kernel<<<SCAN_B, 1024>>>();
    scan2_kernel<<<1, 256>>>();
    scan3_kernel<<<SCAN_B, 1024>>>();
    fill_kernel<<<(total_e + 255) / 256, 256>>>(ea);

    // 2. layer-1 aggregation: gather mean of x -> agg bf16
    gather_kernel<<<NG, 256>>>((const __nv_bfloat16*)xP, 0);

    // 3. layer-1 GEMM: h1 = relu(x@Ws1 + aggn@Wn1 + b1) -> bf16
    mp_gemm_kernel<0><<<dim3(NB, 4), 256, SMEM_TOTAL>>>(
        (const __nv_bfloat16*)xP, 0, (const __nv_bfloat16*)aggP, NF,
        0, 4, 1, b1, FH,
        (__nv_bfloat16*)h1P, NF, NN);

    // 4. layer-2 aggregation: gather mean of h1
    gather_kernel<<<NG, 256>>>((const __nv_bfloat16*)h1P, NF);

    // 5. layer-2 GEMM -> hstack bf16
    mp_gemm_kernel<1><<<dim3(NB, 4), 256, SMEM_TOTAL>>>(
        (const __nv_bfloat16*)h1P, NF, (const __nv_bfloat16*)aggP, NF,
        8, 12, 1, b2, FH,
        (__nv_bfloat16*)hsP, NF, NN);

    // 6. attention -> emb bf16
    attention_kernel<<<(NN * 32 + 255) / 256, 256>>>(attW, attB);

    // 7. P/Q GEMM: P = emb@W1a (y=0), Q = emb@W1b (y=1); no bias -> bf16
    mp_gemm_kernel<3><<<dim3(NB, 2), 256, SMEM_TOTAL>>>(
        (const __nv_bfloat16*)embP, 0, (const __nv_bfloat16*)embP, 0,
        16, 16, 1, l1b, 0,
        (__nv_bfloat16*)pqP, NF, NN);

    // 8. edge scorer: relu(P[s]+Q[d]+b) . w2 -> sigmoid
    edge_score_kernel<<<(int)(((size_t)esim * 32 + 255) / 256), 256>>>(
        ssim, dsim, l1b, l2W, l2b, (float*)d_out, esim);
}

// round 16
// speedup vs baseline: 6.6737x; 1.0284x over previous
#include <cuda_runtime.h>
#include <cuda_bf16.h>
#include <math.h>
#include <stdint.h>

#define NN   50000
#define FH   128
#define NTOT (4 * NN)
#define CSRMAX 2200000
#define SCAN_B ((NTOT + 1023) / 1024)
#define NWELEM (18 * 16384)

// ===================== scratch (static device globals) =====================
__device__ int           g_degi[NTOT];          // zero-init; re-zeroed by gather each launch
__device__ int           g_offs[NTOT + 1];
__device__ int           g_cur[NTOT];           // zero-init; re-zeroed by gather each launch
__device__ int           g_part[SCAN_B];
__device__ int           g_csr[CSRMAX];
__device__ __nv_bfloat16 g_pq[(size_t)2 * NN * FH];   // P = emb@W1a, Q = emb@W1b (bf16)
__device__ __nv_bfloat16 g_x[(size_t)NN * FH];
__device__ __nv_bfloat16 g_agg[(size_t)4 * NN * FH];
__device__ __nv_bfloat16 g_h1[(size_t)4 * NN * FH];
__device__ __nv_bfloat16 g_hs[(size_t)4 * NN * FH];
__device__ __nv_bfloat16 g_emb[(size_t)NN * FH];
__device__ __nv_bfloat16 g_whi[NWELEM];   // [mat][n][k]

__device__ __forceinline__ uint32_t pack_bf16(__nv_bfloat16 a, __nv_bfloat16 b) {
    return (uint32_t)__bfloat16_as_ushort(a) | ((uint32_t)__bfloat16_as_ushort(b) << 16);
}
__device__ __forceinline__ uint32_t pack2f(float a, float b) {
    return pack_bf16(__float2bfloat16(a), __float2bfloat16(b));
}
__device__ __forceinline__ uint32_t smem_u32(const void* p) {
    uint32_t a;
    asm("{ .reg .u64 t; cvta.to.shared.u64 t, %1; cvt.u32.u64 %0, t; }" : "=r"(a) : "l"(p));
    return a;
}
__device__ __forceinline__ uint32_t swz(uint32_t off) { return off ^ ((off >> 3) & 0x70); }

__device__ __forceinline__ void ldm_x4(uint32_t addr, uint32_t* r) {
    asm volatile("ldmatrix.sync.aligned.m8n8.x4.shared.b16 {%0,%1,%2,%3}, [%4];"
                 : "=r"(r[0]), "=r"(r[1]), "=r"(r[2]), "=r"(r[3]) : "r"(addr));
}
__device__ __forceinline__ void mma16816(float* c, const uint32_t* a, const uint32_t* b) {
    asm volatile("mma.sync.aligned.m16n8k16.row.col.f32.bf16.bf16.f32 "
        "{%0,%1,%2,%3}, {%4,%5,%6,%7}, {%8,%9}, {%0,%1,%2,%3};"
        : "+f"(c[0]), "+f"(c[1]), "+f"(c[2]), "+f"(c[3])
        : "r"(a[0]), "r"(a[1]), "r"(a[2]), "r"(a[3]), "r"(b[0]), "r"(b[1]));
}
__device__ __forceinline__ void cpasync16z(uint32_t dst, const void* src, int src_bytes) {
    asm volatile("cp.async.ca.shared.global [%0], [%1], 16, %2;"
                 :: "r"(dst), "l"(__cvta_generic_to_global(src)), "r"(src_bytes) : "memory");
}
#define CP_COMMIT() asm volatile("cp.async.commit_group;" ::: "memory")
#define CP_WAIT0()  asm volatile("cp.async.wait_group 0;" ::: "memory")
#define CP_WAIT1()  asm volatile("cp.async.wait_group 1;" ::: "memory")

// ===================== prologue: weight transpose+convert AND x convert, one launch =====================
__global__ void prologue_kernel(const float* __restrict__ Ws1, const float* __restrict__ Wn1,
                                const float* __restrict__ Ws2, const float* __restrict__ Wn2,
                                const float* __restrict__ L1, const float* __restrict__ x) {
    int g = blockIdx.x * blockDim.x + threadIdx.x;
    if (g < NWELEM) {
        int m = g >> 14, r = g & 16383, n = r >> 7, k = r & 127;
        const float* s;
        if (m < 4)       s = Ws1 + (size_t)m * 16384;
        else if (m < 8)  s = Wn1 + (size_t)(m - 4) * 16384;
        else if (m < 12) s = Ws2 + (size_t)(m - 8) * 16384;
        else if (m < 16) s = Wn2 + (size_t)(m - 12) * 16384;
        else             s = L1  + (size_t)(m - 16) * 16384;
        g_whi[(size_t)m * 16384 + n * 128 + k] = __float2bfloat16(s[k * 128 + n]);
    } else {
        int i = g - NWELEM;
        if (i < NN * FH) g_x[i] = __float2bfloat16(x[i]);
    }
}

struct EdgeArgs {
    const int* src[4]; const int* dst[4];
    int off[5];
};

// ---------- CSR build ----------
__global__ void degcount_kernel(EdgeArgs a) {
    int w = blockIdx.x * blockDim.x + threadIdx.x;
    if (w >= a.off[4]) return;
    int y = (w >= a.off[1]) + (w >= a.off[2]) + (w >= a.off[3]);
    atomicAdd(&g_degi[y * NN + __ldg(a.dst[y] + (w - a.off[y]))], 1);
}

__global__ void scan1_kernel() {
    __shared__ int sh[1024];
    int t = threadIdx.x;
    int i = blockIdx.x * 1024 + t;
    int v = (i < NTOT) ? g_degi[i] : 0;
    sh[t] = v;
    __syncthreads();
#pragma unroll
    for (int o = 1; o < 1024; o <<= 1) {
        int add = (t >= o) ? sh[t - o] : 0;
        __syncthreads();
        sh[t] += add;
        __syncthreads();
    }
    if (i < NTOT) g_offs[i] = sh[t] - v;
    if (t == 1023) g_part[blockIdx.x] = sh[1023];
}

__global__ void scan2_kernel() {
    __shared__ int sh[256];
    int t = threadIdx.x;
    int v = (t < SCAN_B) ? g_part[t] : 0;
    sh[t] = v;
    __syncthreads();
#pragma unroll
    for (int o = 1; o < 256; o <<= 1) {
        int add = (t >= o) ? sh[t - o] : 0;
        __syncthreads();
        sh[t] += add;
        __syncthreads();
    }
    if (t < SCAN_B) g_part[t] = sh[t] - v;
    if (t == 255) g_offs[NTOT] = sh[255];
}

__global__ void scan3_kernel() {
    int i = blockIdx.x * 1024 + threadIdx.x;
    if (i < NTOT) g_offs[i] += g_part[blockIdx.x];
}

__global__ void fill_kernel(EdgeArgs a) {
    int w = blockIdx.x * blockDim.x + threadIdx.x;
    if (w >= a.off[4]) return;
    int y = (w >= a.off[1]) + (w >= a.off[2]) + (w >= a.off[3]);
    int e = w - a.off[y];
    int s = __ldg(a.src[y] + e), d = __ldg(a.dst[y] + e);
    int node = y * NN + d;
    int pos = g_offs[node] + atomicAdd(&g_cur[node], 1);
    g_csr[pos] = s;
}

// ---------- CSR gather aggregation: one warp per (metapath,node), 4-edge ILP ----------
// Also re-zeroes g_degi/g_cur for the next graph replay (replaces two memsets).
__global__ void gather_kernel(const __nv_bfloat16* __restrict__ src, size_t ystride) {
    int g = (blockIdx.x * blockDim.x + threadIdx.x) >> 5;
    if (g >= NTOT) return;
    int lane = threadIdx.x & 31;
    int y = g / NN;
    const __nv_bfloat16* base = src + (size_t)y * ystride;
    int o0 = __ldg(g_offs + g), o1 = __ldg(g_offs + g + 1);
    if (lane == 0) { g_degi[g] = 0; g_cur[g] = 0; }
    float4 acc0 = make_float4(0.f, 0.f, 0.f, 0.f);
    float4 acc1 = make_float4(0.f, 0.f, 0.f, 0.f);
    int j = o0;
    for (; j + 3 < o1; j += 4) {
        int s0 = __ldg(g_csr + j),     s1 = __ldg(g_csr + j + 1);
        int s2 = __ldg(g_csr + j + 2), s3 = __ldg(g_csr + j + 3);
        uint2 h0 = __ldg((const uint2*)(base + (size_t)s0 * FH) + lane);
        uint2 h1 = __ldg((const uint2*)(base + (size_t)s1 * FH) + lane);
        uint2 h2 = __ldg((const uint2*)(base + (size_t)s2 * FH) + lane);
        uint2 h3 = __ldg((const uint2*)(base + (size_t)s3 * FH) + lane);
        float2 a0 = __bfloat1622float2(*(__nv_bfloat162*)&h0.x);
        float2 b0 = __bfloat1622float2(*(__nv_bfloat162*)&h0.y);
        float2 a1 = __bfloat1622float2(*(__nv_bfloat162*)&h1.x);
        float2 b1 = __bfloat1622float2(*(__nv_bfloat162*)&h1.y);
        float2 a2 = __bfloat1622float2(*(__nv_bfloat162*)&h2.x);
        float2 b2 = __bfloat1622float2(*(__nv_bfloat162*)&h2.y);
        float2 a3 = __bfloat1622float2(*(__nv_bfloat162*)&h3.x);
        float2 b3 = __bfloat1622float2(*(__nv_bfloat162*)&h3.y);
        acc0.x += a0.x + a2.x; acc0.y += a0.y + a2.y; acc0.z += b0.x + b2.x; acc0.w += b0.y + b2.y;
        acc1.x += a1.x + a3.x; acc1.y += a1.y + a3.y; acc1.z += b1.x + b3.x; acc1.w += b1.y + b3.y;
    }
    for (; j < o1; ++j) {
        int s0 = __ldg(g_csr + j);
        uint2 h0 = __ldg((const uint2*)(base + (size_t)s0 * FH) + lane);
        float2 a0 = __bfloat1622float2(*(__nv_bfloat162*)&h0.x);
        float2 b0 = __bfloat1622float2(*(__nv_bfloat162*)&h0.y);
        acc0.x += a0.x; acc0.y += a0.y; acc0.z += b0.x; acc0.w += b0.y;
    }
    float sc = 1.0f / fmaxf((float)(o1 - o0), 1.0f);
    float ax = (acc0.x + acc1.x) * sc, ay = (acc0.y + acc1.y) * sc;
    float az = (acc0.z + acc1.z) * sc, aw = (acc0.w + acc1.w) * sc;
    *(uint2*)(g_agg + (size_t)g * FH + lane * 4) = make_uint2(pack2f(ax, ay), pack2f(az, aw));
}

// attention softmax over 4 metapaths -> emb bf16; one warp per node
__global__ void attention_kernel(const float* __restrict__ attW, const float* __restrict__ attB) {
    int n = (blockIdx.x * blockDim.x + threadIdx.x) >> 5;
    if (n >= NN) return;
    int lane = threadIdx.x & 31;
    float4 hv[4]; float logit[4];
#pragma unroll
    for (int k = 0; k < 4; ++k) {
        uint2 h = __ldg((const uint2*)(g_hs + ((size_t)k * NN + n) * FH) + lane);
        float2 h01 = __bfloat1622float2(*(__nv_bfloat162*)&h.x);
        float2 h23 = __bfloat1622float2(*(__nv_bfloat162*)&h.y);
        float4 h4 = make_float4(h01.x, h01.y, h23.x, h23.y);
        float4 w4 = *(const float4*)(attW + k * FH + lane * 4);
        hv[k] = h4;
        float p = h4.x * w4.x + h4.y * w4.y + h4.z * w4.z + h4.w * w4.w;
#pragma unroll
        for (int o2 = 16; o2; o2 >>= 1) p += __shfl_xor_sync(0xffffffffu, p, o2);
        logit[k] = p + attB[k];
    }
    float m = fmaxf(fmaxf(logit[0], logit[1]), fmaxf(logit[2], logit[3]));
    float e[4], s = 0.0f;
#pragma unroll
    for (int k = 0; k < 4; ++k) { e[k] = expf(logit[k] - m); s += e[k]; }
    float is = 1.0f / s;
    float4 o = make_float4(0.f, 0.f, 0.f, 0.f);
#pragma unroll
    for (int k = 0; k < 4; ++k) {
        float w = e[k] * is;
        o.x += w * hv[k].x; o.y += w * hv[k].y; o.z += w * hv[k].z; o.w += w * hv[k].w;
    }
    *(uint2*)(g_emb + (size_t)n * FH + lane * 4) = make_uint2(pack2f(o.x, o.y), pack2f(o.z, o.w));
}

// edge scorer: score = sigmoid(sum relu(P[s]+Q[d]+b) * w2 + b2); one warp per edge; bf16 P/Q.
__global__ void edge_score_kernel(const int* __restrict__ src, const int* __restrict__ dst,
                                  const float* __restrict__ l1b, const float* __restrict__ l2w,
                                  const float* __restrict__ l2b,
                                  float* __restrict__ out, int ne) {
    int e = (blockIdx.x * blockDim.x + threadIdx.x) >> 5;
    if (e >= ne) return;
    int lane = threadIdx.x & 31;
    int s = __ldg(src + e), d = __ldg(dst + e);
    uint2 pu = __ldg((const uint2*)(g_pq + (size_t)s * FH) + lane);
    uint2 qu = __ldg((const uint2*)(g_pq + (size_t)NN * FH + (size_t)d * FH) + lane);
    float2 p01 = __bfloat1622float2(*(__nv_bfloat162*)&pu.x);
    float2 p23 = __bfloat1622float2(*(__nv_bfloat162*)&pu.y);
    float2 q01 = __bfloat1622float2(*(__nv_bfloat162*)&qu.x);
    float2 q23 = __bfloat1622float2(*(__nv_bfloat162*)&qu.y);
    float4 b = *(const float4*)(l1b + lane * 4);
    float4 w = *(const float4*)(l2w + lane * 4);
    float acc = fmaxf(p01.x + q01.x + b.x, 0.f) * w.x + fmaxf(p01.y + q01.y + b.y, 0.f) * w.y
              + fmaxf(p23.x + q23.x + b.z, 0.f) * w.z + fmaxf(p23.y + q23.y + b.w, 0.f) * w.w;
#pragma unroll
    for (int o = 16; o; o >>= 1) acc += __shfl_xor_sync(0xffffffffu, acc, o);
    if (lane == 0) out[e] = 1.0f / (1.0f + expf(-(acc + __ldg(l2b))));
}

// ===================== mma.sync GEMM: single bf16 pass, cp.async double-buffer =====================
// MODE 0: 2 halves, bias+relu -> bf16.  MODE 1: 2 halves, +bias -> bf16.
// MODE 3: single half (K=128), no bias -> bf16.
#define SB_BIAS 0
#define SB_TILES 1024
#define TILE_SZ 16384
#define SMEM_TOTAL (SB_TILES + 4 * TILE_SZ)   // 2 stages x (A,W)

__device__ __forceinline__ void stage_tile(uint32_t stile, const __nv_bfloat16* gbase,
                                           int row0, int nrows, int kofs, int tid) {
#pragma unroll
    for (int i = tid; i < 1024; i += 256) {
        int r = i >> 3, j = i & 7;
        int grow = row0 + r;
        bool valid = grow < nrows;
        const __nv_bfloat16* src = gbase + (size_t)(valid ? grow : 0) * FH + kofs + j * 8;
        uint32_t off = (uint32_t)(r * 128 + j * 16);
        cpasync16z(stile + swz(off), src, valid ? 16 : 0);
    }
}

__device__ __forceinline__ void load_a_frag(uint32_t tb, int wm, int ks, int lane, uint32_t* ra) {
    int q = lane >> 3, r = lane & 7;
    int rofs = ((q & 1) ? 8 : 0) + r;
    int kl = ks * 16 + ((q & 2) ? 8 : 0);
#pragma unroll
    for (int mf = 0; mf < 4; ++mf) {
        uint32_t off = (uint32_t)((wm * 64 + mf * 16 + rofs) * 128 + kl * 2);
        ldm_x4(tb + swz(off), ra + mf * 4);
    }
}
__device__ __forceinline__ void load_w_frag(uint32_t tb, int wn, int ks, int lane, uint32_t* rw) {
    int q = lane >> 3, r = lane & 7;
    int rofs = ((q & 2) ? 8 : 0) + r;
    int kl = ks * 16 + ((q & 1) ? 8 : 0);
#pragma unroll
    for (int pf = 0; pf < 2; ++pf) {
        uint32_t off = (uint32_t)((wn * 32 + pf * 16 + rofs) * 128 + kl * 2);
        ldm_x4(tb + swz(off), rw + pf * 4);
    }
}

template <int MODE>
__global__ void __launch_bounds__(256) mp_gemm_kernel(
    const __nv_bfloat16* __restrict__ a0, size_t a0stride,
    const __nv_bfloat16* __restrict__ a1, size_t a1stride,
    int w0mat, int w1mat, int wmatstride,
    const float* __restrict__ bias, int bstride,
    __nv_bfloat16* __restrict__ outb, size_t outbstride,
    int nrows)
{
    extern __shared__ char smem[];
    const uint32_t sb = smem_u32(smem);
    const int tid = threadIdx.x, lane = tid & 31, wid = tid >> 5;
    const int wm = wid & 1, wn = wid >> 1;
    const int y = blockIdx.y;
    const int row0 = blockIdx.x * 128;

    float* sbias = (float*)(smem + SB_BIAS);
    if (tid < 128) sbias[tid] = (MODE == 3) ? 0.f : bias[bstride * y + tid];

    const __nv_bfloat16* ab[2] = { a0 + (size_t)y * a0stride, a1 + (size_t)y * a1stride };
    const int wm0 = w0mat + y * wmatstride, wm1 = w1mat + y * wmatstride;

    float acc[4][4][4];
#pragma unroll
    for (int i = 0; i < 4; ++i)
#pragma unroll
        for (int j = 0; j < 4; ++j)
#pragma unroll
            for (int q = 0; q < 4; ++q) acc[i][j][q] = 0.0f;

    const int CHUNKS = (MODE == 3) ? 2 : 4;
    // prologue: stage chunk 0 into buffer 0
    stage_tile(sb + SB_TILES, ab[0], row0, nrows, 0, tid);
    stage_tile(sb + SB_TILES + TILE_SZ, g_whi + (size_t)wm0 * 16384, 0, 128, 0, tid);
    CP_COMMIT();

#pragma unroll 1
    for (int c = 0; c < CHUNKS; ++c) {
        if (c + 1 < CHUNKS) {
            const int nh = (MODE == 3) ? 0 : ((c + 1) >> 1), nkc = ((c + 1) & 1) * 64;
            const uint32_t nbuf = sb + SB_TILES + ((c + 1) & 1) * 2 * TILE_SZ;
            stage_tile(nbuf, ab[nh], row0, nrows, nkc, tid);
            stage_tile(nbuf + TILE_SZ, g_whi + (size_t)(nh ? wm1 : wm0) * 16384, 0, 128, nkc, tid);
            CP_COMMIT();
            CP_WAIT1();
        } else {
            CP_WAIT0();
        }
        __syncthreads();
        const uint32_t buf = sb + SB_TILES + (c & 1) * 2 * TILE_SZ;
        const uint32_t tA = buf, tW = buf + TILE_SZ;
#pragma unroll
        for (int ks = 0; ks < 4; ++ks) {
            uint32_t ra[16], rw[8];
            load_a_frag(tA, wm, ks, lane, ra);
            load_w_frag(tW, wn, ks, lane, rw);
#pragma unroll
            for (int mf = 0; mf < 4; ++mf)
#pragma unroll
                for (int nf = 0; nf < 4; ++nf)
                    mma16816(acc[mf][nf], ra + mf * 4, rw + nf * 2);
        }
        if (c + 1 < CHUNKS) __syncthreads();   // done reading buf before it is re-staged
    }

    // ---------------- epilogue ----------------
    const int rbase = row0 + wm * 64 + (lane >> 2);
    const int cbase = wn * 32 + 2 * (lane & 3);

#pragma unroll
    for (int mf = 0; mf < 4; ++mf) {
        int r0 = rbase + mf * 16, r1 = r0 + 8;
        bool v0 = r0 < nrows, v1 = r1 < nrows;
#pragma unroll
        for (int nf = 0; nf < 4; ++nf) {
            int gc = cbase + nf * 8;
            float b0v = sbias[gc], b1v = sbias[gc + 1];
            float e0 = acc[mf][nf][0] + b0v, e1 = acc[mf][nf][1] + b1v;
            float e2 = acc[mf][nf][2] + b0v, e3 = acc[mf][nf][3] + b1v;
            if (MODE == 0) {
                e0 = fmaxf(e0, 0.f); e1 = fmaxf(e1, 0.f);
                e2 = fmaxf(e2, 0.f); e3 = fmaxf(e3, 0.f);
            }
            if (v0) *(uint32_t*)(outb + (size_t)y * outbstride + (size_t)r0 * FH + gc) = pack2f(e0, e1);
            if (v1) *(uint32_t*)(outb + (size_t)y * outbstride + (size_t)r1 * FH + gc) = pack2f(e2, e3);
        }
    }
}

// ===================== host =====================
extern "C" void kernel_launch(void* const* d_in, const int* in_sizes, int n_in,
                              void* d_out, int out_size) {
    const float* x    = (const float*)d_in[0];
    const float* Ws1  = (const float*)d_in[1];
    const float* b1   = (const float*)d_in[2];
    const float* Wn1  = (const float*)d_in[3];
    const float* Ws2  = (const float*)d_in[4];
    const float* b2   = (const float*)d_in[5];
    const float* Wn2  = (const float*)d_in[6];
    const float* attW = (const float*)d_in[7];
    const float* attB = (const float*)d_in[8];
    const float* l1W  = (const float*)d_in[9];
    const float* l1b  = (const float*)d_in[10];
    const float* l2W  = (const float*)d_in[11];
    const float* l2b  = (const float*)d_in[12];
    const int* srcs[4] = {(const int*)d_in[13], (const int*)d_in[15],
                          (const int*)d_in[17], (const int*)d_in[19]};
    const int* dsts[4] = {(const int*)d_in[14], (const int*)d_in[16],
                          (const int*)d_in[18], (const int*)d_in[20]};
    const int* ssim = (const int*)d_in[21];
    const int* dsim = (const int*)d_in[22];
    const int  esim = in_sizes[21];

    void *pqP, *xP, *aggP, *h1P, *hsP, *embP;
    cudaGetSymbolAddress(&pqP, g_pq);
    cudaGetSymbolAddress(&xP, g_x);
    cudaGetSymbolAddress(&aggP, g_agg);
    cudaGetSymbolAddress(&h1P, g_h1);
    cudaGetSymbolAddress(&hsP, g_hs);
    cudaGetSymbolAddress(&embP, g_emb);

    cudaFuncSetAttribute(mp_gemm_kernel<0>, cudaFuncAttributeMaxDynamicSharedMemorySize, SMEM_TOTAL);
    cudaFuncSetAttribute(mp_gemm_kernel<1>, cudaFuncAttributeMaxDynamicSharedMemorySize, SMEM_TOTAL);
    cudaFuncSetAttribute(mp_gemm_kernel<3>, cudaFuncAttributeMaxDynamicSharedMemorySize, SMEM_TOTAL);

    EdgeArgs ea;
    ea.off[0] = 0;
    for (int k = 0; k < 4; ++k) {
        ea.src[k] = srcs[k]; ea.dst[k] = dsts[k];
        ea.off[k + 1] = ea.off[k] + in_sizes[13 + 2 * k];
    }
    const int total_e = ea.off[4];

    const int NB = (NN + 127) / 128;
    const size_t NF = (size_t)NN * FH;
    const int NG = (int)(((size_t)NTOT * 32 + 255) / 256);

    // 0. fused prologue: weight transpose+bf16 convert AND x bf16 convert
    prologue_kernel<<<(NWELEM + NN * FH + 255) / 256, 256>>>(Ws1, Wn1, Ws2, Wn2, l1W, x);

    // 1. CSR build (g_degi/g_cur are zero: static init on first run, re-zeroed by gather on replays)
    degcount_kernel<<<(total_e + 255) / 256, 256>>>(ea);
    scan1_kernel<<<SCAN_B, 1024>>>();
    scan2_kernel<<<1, 256>>>();
    scan3_kernel<<<SCAN_B, 1024>>>();
    fill_kernel<<<(total_e + 255) / 256, 256>>>(ea);

    // 2. layer-1 aggregation: gather mean of x -> agg bf16 (also zeroes degi/cur)
    gather_kernel<<<NG, 256>>>((const __nv_bfloat16*)xP, 0);

    // 3. layer-1 GEMM: h1 = relu(x@Ws1 + aggn@Wn1 + b1) -> bf16
    mp_gemm_kernel<0><<<dim3(NB, 4), 256, SMEM_TOTAL>>>(
        (const __nv_bfloat16*)xP, 0, (const __nv_bfloat16*)aggP, NF,
        0, 4, 1, b1, FH,
        (__nv_bfloat16*)h1P, NF, NN);

    // 4. layer-2 aggregation: gather mean of h1
    gather_kernel<<<NG, 256>>>((const __nv_bfloat16*)h1P, NF);

    // 5. layer-2 GEMM -> hstack bf16
    mp_gemm_kernel<1><<<dim3(NB, 4), 256, SMEM_TOTAL>>>(
        (const __nv_bfloat16*)h1P, NF, (const __nv_bfloat16*)aggP, NF,
        8, 12, 1, b2, FH,
        (__nv_bfloat16*)hsP, NF, NN);

    // 6. attention -> emb bf16
    attention_kernel<<<(NN * 32 + 255) / 256, 256>>>(attW, attB);

    // 7. P/Q GEMM: P = emb@W1a (y=0), Q = emb@W1b (y=1); no bias -> bf16
    mp_gemm_kernel<3><<<dim3(NB, 2), 256, SMEM_TOTAL>>>(
        (const __nv_bfloat16*)embP, 0, (const __nv_bfloat16*)embP, 0,
        16, 16, 1, l1b, 0,
        (__nv_bfloat16*)pqP, NF, NN);

    // 8. edge scorer: relu(P[s]+Q[d]+b) . w2 -> sigmoid
    edge_score_kernel<<<(int)(((size_t)esim * 32 + 255) / 256), 256>>>(
        ssim, dsim, l1b, l2W, l2b, (float*)d_out, esim);
}